// round 1
// baseline (speedup 1.0000x reference)
#include <cuda_runtime.h>
#include <math.h>

#define D_MODEL 1024
#define N_HEADS 16
#define HDIM    64
#define SEQ     2048
#define BATCH   2
#define ROWS    (BATCH * SEQ)   // 4096

// ---------------------------------------------------------------------------
// Scratch (static device globals — no allocation allowed)
// ---------------------------------------------------------------------------
__device__ float g_q[ROWS * D_MODEL];
__device__ float g_k[ROWS * D_MODEL];
__device__ float g_v[ROWS * D_MODEL];
__device__ float g_att[ROWS * D_MODEL];

// ---------------------------------------------------------------------------
// SGEMM: C[M,N] = A[M,K] @ W[N,K]^T + bias[N]
// 128x128 block tile, BK=8, 256 threads, 8x8 register tile per thread.
// M,N multiples of 128; K multiple of 8. (Here M=4096, N=K=1024.)
// ---------------------------------------------------------------------------
__device__ __forceinline__ void gemm_body(
    const float* __restrict__ A, const float* __restrict__ W,
    const float* __restrict__ bias, float* __restrict__ C,
    int M, int N, int K)
{
    __shared__ float As[8][128];
    __shared__ float Bs[8][128];

    const int tid  = threadIdx.x;
    const int brow = blockIdx.y * 128;
    const int bcol = blockIdx.x * 128;
    const int lrow = tid >> 1;          // 0..127
    const int lcol = (tid & 1) * 4;     // 0 or 4
    const int tr   = tid >> 4;          // 0..15
    const int tc   = tid & 15;          // 0..15

    float acc[8][8];
#pragma unroll
    for (int i = 0; i < 8; i++)
#pragma unroll
        for (int j = 0; j < 8; j++) acc[i][j] = 0.0f;

    const float* Ap = A + (brow + lrow) * K + lcol;
    const float* Wp = W + (bcol + lrow) * K + lcol;

    for (int k0 = 0; k0 < K; k0 += 8) {
        float4 av = *(const float4*)(Ap + k0);
        float4 bv = *(const float4*)(Wp + k0);
        As[lcol + 0][lrow] = av.x; As[lcol + 1][lrow] = av.y;
        As[lcol + 2][lrow] = av.z; As[lcol + 3][lrow] = av.w;
        Bs[lcol + 0][lrow] = bv.x; Bs[lcol + 1][lrow] = bv.y;
        Bs[lcol + 2][lrow] = bv.z; Bs[lcol + 3][lrow] = bv.w;
        __syncthreads();

#pragma unroll
        for (int kk = 0; kk < 8; kk++) {
            float ar[8], br[8];
            *(float4*)(ar)     = *(const float4*)(&As[kk][tr * 8]);
            *(float4*)(ar + 4) = *(const float4*)(&As[kk][tr * 8 + 4]);
            *(float4*)(br)     = *(const float4*)(&Bs[kk][tc * 8]);
            *(float4*)(br + 4) = *(const float4*)(&Bs[kk][tc * 8 + 4]);
#pragma unroll
            for (int i = 0; i < 8; i++)
#pragma unroll
                for (int j = 0; j < 8; j++)
                    acc[i][j] += ar[i] * br[j];
        }
        __syncthreads();
    }

#pragma unroll
    for (int i = 0; i < 8; i++) {
        int row = brow + tr * 8 + i;
#pragma unroll
        for (int j = 0; j < 8; j += 4) {
            int col = bcol + tc * 8 + j;
            float4 o;
            o.x = acc[i][j + 0] + bias[col + 0];
            o.y = acc[i][j + 1] + bias[col + 1];
            o.z = acc[i][j + 2] + bias[col + 2];
            o.w = acc[i][j + 3] + bias[col + 3];
            *(float4*)(C + row * N + col) = o;
        }
    }
}

__global__ __launch_bounds__(256)
void gemm_qkv_kernel(const float* __restrict__ X,
                     const float* __restrict__ Wq, const float* __restrict__ Bq, float* __restrict__ Oq,
                     const float* __restrict__ Wk, const float* __restrict__ Bk, float* __restrict__ Ok,
                     const float* __restrict__ Wv, const float* __restrict__ Bv, float* __restrict__ Ov)
{
    const float* W; const float* bb; float* C;
    if (blockIdx.z == 0)      { W = Wq; bb = Bq; C = Oq; }
    else if (blockIdx.z == 1) { W = Wk; bb = Bk; C = Ok; }
    else                      { W = Wv; bb = Bv; C = Ov; }
    gemm_body(X, W, bb, C, ROWS, D_MODEL, D_MODEL);
}

__global__ __launch_bounds__(256)
void gemm_out_kernel(const float* __restrict__ A, const float* __restrict__ W,
                     const float* __restrict__ bb, float* __restrict__ C)
{
    gemm_body(A, W, bb, C, ROWS, D_MODEL, D_MODEL);
}

// ---------------------------------------------------------------------------
// RoPE (in-place on q and k). Layout: [row = b*S+s][h*64 + d], pairs (i, i+32).
// ---------------------------------------------------------------------------
__global__ void rope_kernel(float* __restrict__ q, float* __restrict__ k)
{
    int idx = blockIdx.x * blockDim.x + threadIdx.x;
    if (idx >= ROWS * N_HEADS * 32) return;
    int i   = idx & 31;             // freq index 0..31
    int h   = (idx >> 5) & (N_HEADS - 1);
    int row = idx >> 9;             // b*S + s
    int t   = row & (SEQ - 1);      // position s

    float inv = 1.0f / powf(10000.0f, (float)(2 * i) * (1.0f / 64.0f));
    float ang = (float)t * inv;
    float sn, cs;
    sincosf(ang, &sn, &cs);

    int base = row * D_MODEL + h * HDIM + i;
    float q1 = q[base], q2 = q[base + 32];
    q[base]      = q1 * cs - q2 * sn;
    q[base + 32] = q2 * cs + q1 * sn;
    float k1 = k[base], k2 = k[base + 32];
    k[base]      = k1 * cs - k2 * sn;
    k[base + 32] = k2 * cs + k1 * sn;
}

// ---------------------------------------------------------------------------
// Flash attention: block = (64-query tile, b*H+h). 32 key tiles of 64.
// 256 threads, 4x4 register tiles for both QK^T and PV.
// Smem: Qs[d][r], Ks[d][c], Vs[k][j], Ss raw scores [r][k], Ps = P^T [k][r].
// ---------------------------------------------------------------------------
#define FA_SMEM (5 * 64 * 64 * 4 + 3 * 64 * 4)

__global__ __launch_bounds__(256)
void flash_kernel(const float* __restrict__ Q, const float* __restrict__ Kg_,
                  const float* __restrict__ V, const float* __restrict__ mask,
                  float* __restrict__ O)
{
    extern __shared__ float sm[];
    float* Qs  = sm;                // 64x64, [d][r]
    float* Ks  = Qs + 4096;         // 64x64, [d][c]
    float* Vs  = Ks + 4096;         // 64x64, [k][j]
    float* Ss  = Vs + 4096;         // 64x64, raw scores [r][k]
    float* Ps  = Ss + 4096;         // 64x64, P transposed [k][r]
    float* m_s = Ps + 4096;         // [64]
    float* l_s = m_s + 64;          // [64]
    float* c_s = l_s + 64;          // [64]

    const int tid = threadIdx.x;
    const int tr  = tid >> 4;       // 0..15
    const int tc  = tid & 15;       // 0..15
    const int qt  = blockIdx.x;
    const int bh  = blockIdx.y;
    const int b   = bh >> 4;
    const int h   = bh & 15;

    // Load Q tile, transposed into Qs[d][r]
    const float* Qg = Q + (b * SEQ + qt * 64) * D_MODEL + h * HDIM;
#pragma unroll
    for (int l = 0; l < 4; l++) {
        int idx = tid + l * 256;
        int r   = idx >> 4;
        int c4  = (idx & 15) << 2;
        float4 v = *(const float4*)(Qg + r * D_MODEL + c4);
        Qs[(c4 + 0) * 64 + r] = v.x; Qs[(c4 + 1) * 64 + r] = v.y;
        Qs[(c4 + 2) * 64 + r] = v.z; Qs[(c4 + 3) * 64 + r] = v.w;
    }
    if (tid < 64) { m_s[tid] = -1e30f; l_s[tid] = 0.0f; }

    float acc[4][4];
#pragma unroll
    for (int i = 0; i < 4; i++)
#pragma unroll
        for (int j = 0; j < 4; j++) acc[i][j] = 0.0f;

    const float* maskb = mask + b * SEQ;

    for (int kt = 0; kt < SEQ / 64; kt++) {
        __syncthreads();   // previous PV done (and Q load visible on iter 0)
        const float* Kp = Kg_ + (b * SEQ + kt * 64) * D_MODEL + h * HDIM;
        const float* Vp = V   + (b * SEQ + kt * 64) * D_MODEL + h * HDIM;
#pragma unroll
        for (int l = 0; l < 4; l++) {
            int idx = tid + l * 256;
            int r   = idx >> 4;
            int c4  = (idx & 15) << 2;
            float4 kv = *(const float4*)(Kp + r * D_MODEL + c4);
            Ks[(c4 + 0) * 64 + r] = kv.x; Ks[(c4 + 1) * 64 + r] = kv.y;
            Ks[(c4 + 2) * 64 + r] = kv.z; Ks[(c4 + 3) * 64 + r] = kv.w;
            float4 vv = *(const float4*)(Vp + r * D_MODEL + c4);
            *(float4*)(Vs + r * 64 + c4) = vv;
        }
        __syncthreads();

        // S = Q K^T (4x4 per thread)
        float s[4][4];
#pragma unroll
        for (int i = 0; i < 4; i++)
#pragma unroll
            for (int j = 0; j < 4; j++) s[i][j] = 0.0f;
#pragma unroll 16
        for (int d = 0; d < 64; d++) {
            float ar[4], br[4];
            *(float4*)ar = *(const float4*)(Qs + d * 64 + tr * 4);
            *(float4*)br = *(const float4*)(Ks + d * 64 + tc * 4);
#pragma unroll
            for (int i = 0; i < 4; i++)
#pragma unroll
                for (int j = 0; j < 4; j++)
                    s[i][j] += ar[i] * br[j];
        }

        float4 mk = *(const float4*)(maskb + kt * 64 + tc * 4);
        float mka[4] = { mk.x, mk.y, mk.z, mk.w };
#pragma unroll
        for (int i = 0; i < 4; i++) {
            float4 w;
            w.x = s[i][0] * 0.125f + mka[0];
            w.y = s[i][1] * 0.125f + mka[1];
            w.z = s[i][2] * 0.125f + mka[2];
            w.w = s[i][3] * 0.125f + mka[3];
            *(float4*)(Ss + (tr * 4 + i) * 64 + tc * 4) = w;
        }
        __syncthreads();

        // Online softmax per row (threads 0..63, staggered conflict-free scans)
        if (tid < 64) {
            int r = tid;
            float m_old = m_s[r];
            float tmax  = m_old;
#pragma unroll 8
            for (int jj = 0; jj < 64; jj++) {
                int j = (r + jj) & 63;
                tmax = fmaxf(tmax, Ss[r * 64 + j]);
            }
            float corr = __expf(m_old - tmax);
            float sum  = 0.0f;
#pragma unroll 8
            for (int jj = 0; jj < 64; jj++) {
                int j = (r + jj) & 63;
                float p = __expf(Ss[r * 64 + j] - tmax);
                Ps[j * 64 + r] = p;   // transposed store, bank = r%32
                sum += p;
            }
            l_s[r] = l_s[r] * corr + sum;
            m_s[r] = tmax;
            c_s[r] = corr;
        }
        __syncthreads();

        // Rescale accumulators, then O += P V
        float cr[4];
#pragma unroll
        for (int i = 0; i < 4; i++) cr[i] = c_s[tr * 4 + i];
#pragma unroll
        for (int i = 0; i < 4; i++)
#pragma unroll
            for (int j = 0; j < 4; j++) acc[i][j] *= cr[i];

#pragma unroll 8
        for (int kk = 0; kk < 64; kk++) {
            float pr[4], vr[4];
            *(float4*)pr = *(const float4*)(Ps + kk * 64 + tr * 4);
            *(float4*)vr = *(const float4*)(Vs + kk * 64 + tc * 4);
#pragma unroll
            for (int i = 0; i < 4; i++)
#pragma unroll
                for (int j = 0; j < 4; j++)
                    acc[i][j] += pr[i] * vr[j];
        }
    }

    float* Og = O + (b * SEQ + qt * 64) * D_MODEL + h * HDIM;
#pragma unroll
    for (int i = 0; i < 4; i++) {
        int r = tr * 4 + i;
        float inv = 1.0f / l_s[r];
        float4 o;
        o.x = acc[i][0] * inv;
        o.y = acc[i][1] * inv;
        o.z = acc[i][2] * inv;
        o.w = acc[i][3] * inv;
        *(float4*)(Og + r * D_MODEL + tc * 4) = o;
    }
}

// ---------------------------------------------------------------------------
// Launch
// ---------------------------------------------------------------------------
extern "C" void kernel_launch(void* const* d_in, const int* in_sizes, int n_in,
                              void* d_out, int out_size)
{
    const float* x    = (const float*)d_in[0];
    const float* wq   = (const float*)d_in[1];
    const float* bq   = (const float*)d_in[2];
    const float* wk   = (const float*)d_in[3];
    const float* bk   = (const float*)d_in[4];
    const float* wv   = (const float*)d_in[5];
    const float* bv   = (const float*)d_in[6];
    const float* wo   = (const float*)d_in[7];
    const float* bo   = (const float*)d_in[8];
    const float* mask = (const float*)d_in[9];
    float* out = (float*)d_out;

    float *q, *k, *v, *att;
    cudaGetSymbolAddress((void**)&q,   g_q);
    cudaGetSymbolAddress((void**)&k,   g_k);
    cudaGetSymbolAddress((void**)&v,   g_v);
    cudaGetSymbolAddress((void**)&att, g_att);

    cudaFuncSetAttribute(flash_kernel,
                         cudaFuncAttributeMaxDynamicSharedMemorySize, FA_SMEM);

    // QKV projections (fused over gridDim.z)
    dim3 g1(D_MODEL / 128, ROWS / 128, 3);
    gemm_qkv_kernel<<<g1, 256>>>(x, wq, bq, q, wk, bk, k, wv, bv, v);

    // RoPE in-place on q, k
    int rope_threads = ROWS * N_HEADS * 32;
    rope_kernel<<<rope_threads / 256, 256>>>(q, k);

    // Attention
    dim3 g2(SEQ / 64, BATCH * N_HEADS);
    flash_kernel<<<g2, 256, FA_SMEM>>>(q, k, v, mask, att);

    // Output projection -> d_out
    dim3 g3(D_MODEL / 128, ROWS / 128);
    gemm_out_kernel<<<g3, 256>>>(att, wo, bo, out);
}

// round 5
// speedup vs baseline: 1.1698x; 1.1698x over previous
#include <cuda_runtime.h>
#include <cstdint>
#include <math.h>

#define D_MODEL 1024
#define N_HEADS 16
#define HDIM    64
#define SEQ     2048
#define BATCH   2
#define ROWS    (BATCH * SEQ)   // 4096

// ---------------------------------------------------------------------------
// Scratch (static device globals — no allocation allowed)
// ---------------------------------------------------------------------------
__device__ float g_q[ROWS * D_MODEL];
__device__ float g_k[ROWS * D_MODEL];
__device__ float g_v[ROWS * D_MODEL];
__device__ float g_att[ROWS * D_MODEL];

// ---------------------------------------------------------------------------
// Helpers
// ---------------------------------------------------------------------------
__device__ __forceinline__ uint32_t smem_u32(const void* p) {
    uint32_t a;
    asm("{ .reg .u64 t; cvta.to.shared.u64 t, %1; cvt.u32.u64 %0, t; }"
        : "=r"(a) : "l"(p));
    return a;
}

__device__ __forceinline__ void cp_async16(uint32_t saddr, const void* gptr) {
    asm volatile("cp.async.cg.shared.global [%0], [%1], 16;"
                 :: "r"(saddr), "l"(gptr) : "memory");
}
__device__ __forceinline__ void cp_commit() {
    asm volatile("cp.async.commit_group;" ::: "memory");
}
template <int N>
__device__ __forceinline__ void cp_wait() {
    asm volatile("cp.async.wait_group %0;" :: "n"(N) : "memory");
}

// Round to tf32 (rna). PTX cvt.rna.tf32.f32 requires a .b32 destination.
__device__ __forceinline__ uint32_t tf32_rna_bits(float x) {
    uint32_t y;
    asm("cvt.rna.tf32.f32 %0, %1;" : "=r"(y) : "f"(x));
    return y;
}

// mma.sync m16n8k8 tf32: D = A*B + C (row.col)
__device__ __forceinline__ void mma_tf32(float* d, const uint32_t* a,
                                         const uint32_t* b) {
    asm volatile(
        "mma.sync.aligned.m16n8k8.row.col.f32.tf32.tf32.f32 "
        "{%0,%1,%2,%3}, {%4,%5,%6,%7}, {%8,%9}, {%0,%1,%2,%3};"
        : "+f"(d[0]), "+f"(d[1]), "+f"(d[2]), "+f"(d[3])
        : "r"(a[0]), "r"(a[1]), "r"(a[2]), "r"(a[3]), "r"(b[0]), "r"(b[1]));
}

// FFMA-only exp (no MUFU). Accurate to ~1e-7 rel on [-87, 0].
__device__ __forceinline__ float fast_exp(float x) {
    x = fmaxf(x, -87.0f);
    float y = x * 1.4426950408889634f;          // x * log2(e)
    float r = y + 12582912.0f;                  // round-to-nearest-int trick
    float n = r - 12582912.0f;
    float f = y - n;                            // f in [-0.5, 0.5]
    float t = f * 0.6931471805599453f;          // back to natural units
    float p = 1.3888889e-3f;                    // 1/720
    p = fmaf(p, t, 8.3333333e-3f);              // 1/120
    p = fmaf(p, t, 4.1666667e-2f);              // 1/24
    p = fmaf(p, t, 1.6666667e-1f);              // 1/6
    p = fmaf(p, t, 0.5f);
    p = fmaf(p, t, 1.0f);
    p = fmaf(p, t, 1.0f);
    int ni = __float_as_int(r) - 0x4B400000;    // integer n from magic bits
    float scale = __int_as_float((ni << 23) + 0x3F800000);
    return p * scale;
}

// ---------------------------------------------------------------------------
// 3xTF32 tensor-core GEMM: C[M,N] = A[M,K] @ W[N,K]^T + bias[N]
// 128x128x32 CTA tile, 256 threads (8 warps as 2x4), warp tile 64x32,
// m16n8k8 fragments with hi/lo error compensation (hi*hi + hi*lo + lo*hi).
// ---------------------------------------------------------------------------
#define BK        32
#define NCH       (D_MODEL / BK)       // 32 chunks
#define LDS_STRIDE 36                  // floats per smem row (32 + 4 pad)
#define TILE_FLOATS (128 * LDS_STRIDE) // 4608
#define STAGE_FLOATS (2 * TILE_FLOATS) // A + B
#define GEMM_SMEM (2 * STAGE_FLOATS * 4)  // 73728 bytes

__device__ __forceinline__ void stage_chunk(
    const float* __restrict__ Arow, const float* __restrict__ Wrow,
    float* __restrict__ smemf, int stage, int k0, int tid)
{
    uint32_t sa = smem_u32(smemf + stage * STAGE_FLOATS);
    uint32_t sb = sa + TILE_FLOATS * 4;
#pragma unroll
    for (int i = 0; i < 4; i++) {
        int idx = tid + i * 256;          // 0..1023
        int r   = idx >> 3;               // row 0..127
        int f4  = (idx & 7) << 2;         // col 0,4,...,28
        cp_async16(sa + (r * LDS_STRIDE + f4) * 4, Arow + r * D_MODEL + k0 + f4);
        cp_async16(sb + (r * LDS_STRIDE + f4) * 4, Wrow + r * D_MODEL + k0 + f4);
    }
    cp_commit();
}

__device__ __forceinline__ void gemm_tc_body(
    const float* __restrict__ A, const float* __restrict__ W,
    const float* __restrict__ bias, float* __restrict__ C)
{
    extern __shared__ float smemf[];

    const int tid  = threadIdx.x;
    const int wid  = tid >> 5;
    const int lane = tid & 31;
    const int wm   = (wid & 1) * 64;      // warp m offset within tile
    const int wn   = (wid >> 1) * 32;     // warp n offset within tile
    const int brow = blockIdx.y * 128;
    const int bcol = blockIdx.x * 128;

    const int qrow = lane >> 2;           // 0..7
    const int qcol = lane & 3;            // 0..3

    float acc[4][4][4];
#pragma unroll
    for (int mf = 0; mf < 4; mf++)
#pragma unroll
        for (int nf = 0; nf < 4; nf++)
#pragma unroll
            for (int r = 0; r < 4; r++) acc[mf][nf][r] = 0.0f;

    const float* Arow = A + brow * D_MODEL;
    const float* Wrow = W + bcol * D_MODEL;

    stage_chunk(Arow, Wrow, smemf, 0, 0, tid);
    stage_chunk(Arow, Wrow, smemf, 1, BK, tid);

    for (int c = 0; c < NCH; c++) {
        if (c == NCH - 1) cp_wait<0>(); else cp_wait<1>();
        __syncthreads();

        const float* As = smemf + (c & 1) * STAGE_FLOATS;
        const float* Bs = As + TILE_FLOATS;

#pragma unroll
        for (int ks = 0; ks < 4; ks++) {
            const int kc = ks * 8 + qcol;
            uint32_t a_hi[4][4], a_lo[4][4];
#pragma unroll
            for (int mf = 0; mf < 4; mf++) {
                const float* ap = As + (wm + mf * 16 + qrow) * LDS_STRIDE + kc;
                float v0 = ap[0];
                float v1 = ap[8 * LDS_STRIDE];
                float v2 = ap[4];
                float v3 = ap[8 * LDS_STRIDE + 4];
                uint32_t h0 = tf32_rna_bits(v0), h1 = tf32_rna_bits(v1);
                uint32_t h2 = tf32_rna_bits(v2), h3 = tf32_rna_bits(v3);
                a_hi[mf][0] = h0;
                a_hi[mf][1] = h1;
                a_hi[mf][2] = h2;
                a_hi[mf][3] = h3;
                a_lo[mf][0] = __float_as_uint(v0 - __uint_as_float(h0));
                a_lo[mf][1] = __float_as_uint(v1 - __uint_as_float(h1));
                a_lo[mf][2] = __float_as_uint(v2 - __uint_as_float(h2));
                a_lo[mf][3] = __float_as_uint(v3 - __uint_as_float(h3));
            }
            uint32_t b_hi[4][2], b_lo[4][2];
#pragma unroll
            for (int nf = 0; nf < 4; nf++) {
                const float* bp = Bs + (wn + nf * 8 + qrow) * LDS_STRIDE + kc;
                float v0 = bp[0];
                float v1 = bp[4];
                uint32_t h0 = tf32_rna_bits(v0), h1 = tf32_rna_bits(v1);
                b_hi[nf][0] = h0;
                b_hi[nf][1] = h1;
                b_lo[nf][0] = __float_as_uint(v0 - __uint_as_float(h0));
                b_lo[nf][1] = __float_as_uint(v1 - __uint_as_float(h1));
            }
#pragma unroll
            for (int mf = 0; mf < 4; mf++)
#pragma unroll
                for (int nf = 0; nf < 4; nf++) {
                    mma_tf32(acc[mf][nf], a_lo[mf], b_hi[nf]);
                    mma_tf32(acc[mf][nf], a_hi[mf], b_lo[nf]);
                    mma_tf32(acc[mf][nf], a_hi[mf], b_hi[nf]);
                }
        }

        __syncthreads();
        if (c + 2 < NCH)
            stage_chunk(Arow, Wrow, smemf, c & 1, (c + 2) * BK, tid);
    }

    // Epilogue: c0,c1 -> (row, col..col+1); c2,c3 -> (row+8, col..col+1)
#pragma unroll
    for (int mf = 0; mf < 4; mf++) {
        int row0 = brow + wm + mf * 16 + qrow;
#pragma unroll
        for (int nf = 0; nf < 4; nf++) {
            int col = bcol + wn + nf * 8 + 2 * qcol;
            float b0 = bias[col], b1 = bias[col + 1];
            float2 v0 = make_float2(acc[mf][nf][0] + b0, acc[mf][nf][1] + b1);
            float2 v1 = make_float2(acc[mf][nf][2] + b0, acc[mf][nf][3] + b1);
            *(float2*)(C + row0 * D_MODEL + col)       = v0;
            *(float2*)(C + (row0 + 8) * D_MODEL + col) = v1;
        }
    }
}

__global__ __launch_bounds__(256)
void gemm_qkv_tc(const float* __restrict__ X,
                 const float* __restrict__ Wq, const float* __restrict__ Bq, float* __restrict__ Oq,
                 const float* __restrict__ Wk, const float* __restrict__ Bk, float* __restrict__ Ok,
                 const float* __restrict__ Wv, const float* __restrict__ Bv, float* __restrict__ Ov)
{
    const float* W; const float* bb; float* C;
    if (blockIdx.z == 0)      { W = Wq; bb = Bq; C = Oq; }
    else if (blockIdx.z == 1) { W = Wk; bb = Bk; C = Ok; }
    else                      { W = Wv; bb = Bv; C = Ov; }
    gemm_tc_body(X, W, bb, C);
}

__global__ __launch_bounds__(256)
void gemm_out_tc(const float* __restrict__ A, const float* __restrict__ W,
                 const float* __restrict__ bb, float* __restrict__ C)
{
    gemm_tc_body(A, W, bb, C);
}

// ---------------------------------------------------------------------------
// RoPE (in-place on q and k). Layout: [row = b*S+s][h*64 + d], pairs (i, i+32).
// ---------------------------------------------------------------------------
__global__ void rope_kernel(float* __restrict__ q, float* __restrict__ k)
{
    int idx = blockIdx.x * blockDim.x + threadIdx.x;
    if (idx >= ROWS * N_HEADS * 32) return;
    int i   = idx & 31;
    int h   = (idx >> 5) & (N_HEADS - 1);
    int row = idx >> 9;
    int t   = row & (SEQ - 1);

    float inv = 1.0f / powf(10000.0f, (float)(2 * i) * (1.0f / 64.0f));
    float ang = (float)t * inv;
    float sn, cs;
    sincosf(ang, &sn, &cs);

    int base = row * D_MODEL + h * HDIM + i;
    float q1 = q[base], q2 = q[base + 32];
    q[base]      = q1 * cs - q2 * sn;
    q[base + 32] = q2 * cs + q1 * sn;
    float k1 = k[base], k2 = k[base + 32];
    k[base]      = k1 * cs - k2 * sn;
    k[base + 32] = k2 * cs + k1 * sn;
}

// ---------------------------------------------------------------------------
// Flash attention: block = (64-query tile, b*H+h). 32 key tiles of 64.
// 256 threads, 4x4 register tiles. Softmax exp via FFMA poly (no MUFU).
// ---------------------------------------------------------------------------
#define FA_SMEM (5 * 64 * 64 * 4 + 3 * 64 * 4)

__global__ __launch_bounds__(256)
void flash_kernel(const float* __restrict__ Q, const float* __restrict__ Kg_,
                  const float* __restrict__ V, const float* __restrict__ mask,
                  float* __restrict__ O)
{
    extern __shared__ float sm[];
    float* Qs  = sm;
    float* Ks  = Qs + 4096;
    float* Vs  = Ks + 4096;
    float* Ss  = Vs + 4096;
    float* Ps  = Ss + 4096;
    float* m_s = Ps + 4096;
    float* l_s = m_s + 64;
    float* c_s = l_s + 64;

    const int tid = threadIdx.x;
    const int tr  = tid >> 4;
    const int tc  = tid & 15;
    const int qt  = blockIdx.x;
    const int bh  = blockIdx.y;
    const int b   = bh >> 4;
    const int h   = bh & 15;

    const float* Qg = Q + (b * SEQ + qt * 64) * D_MODEL + h * HDIM;
#pragma unroll
    for (int l = 0; l < 4; l++) {
        int idx = tid + l * 256;
        int r   = idx >> 4;
        int c4  = (idx & 15) << 2;
        float4 v = *(const float4*)(Qg + r * D_MODEL + c4);
        Qs[(c4 + 0) * 64 + r] = v.x; Qs[(c4 + 1) * 64 + r] = v.y;
        Qs[(c4 + 2) * 64 + r] = v.z; Qs[(c4 + 3) * 64 + r] = v.w;
    }
    if (tid < 64) { m_s[tid] = -1e30f; l_s[tid] = 0.0f; }

    float acc[4][4];
#pragma unroll
    for (int i = 0; i < 4; i++)
#pragma unroll
        for (int j = 0; j < 4; j++) acc[i][j] = 0.0f;

    const float* maskb = mask + b * SEQ;

    for (int kt = 0; kt < SEQ / 64; kt++) {
        __syncthreads();
        const float* Kp = Kg_ + (b * SEQ + kt * 64) * D_MODEL + h * HDIM;
        const float* Vp = V   + (b * SEQ + kt * 64) * D_MODEL + h * HDIM;
#pragma unroll
        for (int l = 0; l < 4; l++) {
            int idx = tid + l * 256;
            int r   = idx >> 4;
            int c4  = (idx & 15) << 2;
            float4 kv = *(const float4*)(Kp + r * D_MODEL + c4);
            Ks[(c4 + 0) * 64 + r] = kv.x; Ks[(c4 + 1) * 64 + r] = kv.y;
            Ks[(c4 + 2) * 64 + r] = kv.z; Ks[(c4 + 3) * 64 + r] = kv.w;
            float4 vv = *(const float4*)(Vp + r * D_MODEL + c4);
            *(float4*)(Vs + r * 64 + c4) = vv;
        }
        __syncthreads();

        float s[4][4];
#pragma unroll
        for (int i = 0; i < 4; i++)
#pragma unroll
            for (int j = 0; j < 4; j++) s[i][j] = 0.0f;
#pragma unroll 16
        for (int d = 0; d < 64; d++) {
            float ar[4], br[4];
            *(float4*)ar = *(const float4*)(Qs + d * 64 + tr * 4);
            *(float4*)br = *(const float4*)(Ks + d * 64 + tc * 4);
#pragma unroll
            for (int i = 0; i < 4; i++)
#pragma unroll
                for (int j = 0; j < 4; j++)
                    s[i][j] += ar[i] * br[j];
        }

        float4 mk = *(const float4*)(maskb + kt * 64 + tc * 4);
        float mka[4] = { mk.x, mk.y, mk.z, mk.w };
#pragma unroll
        for (int i = 0; i < 4; i++) {
            float4 w;
            w.x = s[i][0] * 0.125f + mka[0];
            w.y = s[i][1] * 0.125f + mka[1];
            w.z = s[i][2] * 0.125f + mka[2];
            w.w = s[i][3] * 0.125f + mka[3];
            *(float4*)(Ss + (tr * 4 + i) * 64 + tc * 4) = w;
        }
        __syncthreads();

        if (tid < 64) {
            int r = tid;
            float m_old = m_s[r];
            float tmax  = m_old;
#pragma unroll 8
            for (int jj = 0; jj < 64; jj++) {
                int j = (r + jj) & 63;
                tmax = fmaxf(tmax, Ss[r * 64 + j]);
            }
            float corr = fast_exp(m_old - tmax);
            float sum  = 0.0f;
#pragma unroll 8
            for (int jj = 0; jj < 64; jj++) {
                int j = (r + jj) & 63;
                float p = fast_exp(Ss[r * 64 + j] - tmax);
                Ps[j * 64 + r] = p;
                sum += p;
            }
            l_s[r] = l_s[r] * corr + sum;
            m_s[r] = tmax;
            c_s[r] = corr;
        }
        __syncthreads();

        float cr[4];
#pragma unroll
        for (int i = 0; i < 4; i++) cr[i] = c_s[tr * 4 + i];
#pragma unroll
        for (int i = 0; i < 4; i++)
#pragma unroll
            for (int j = 0; j < 4; j++) acc[i][j] *= cr[i];

#pragma unroll 8
        for (int kk = 0; kk < 64; kk++) {
            float pr[4], vr[4];
            *(float4*)pr = *(const float4*)(Ps + kk * 64 + tr * 4);
            *(float4*)vr = *(const float4*)(Vs + kk * 64 + tc * 4);
#pragma unroll
            for (int i = 0; i < 4; i++)
#pragma unroll
                for (int j = 0; j < 4; j++)
                    acc[i][j] += pr[i] * vr[j];
        }
    }

    float* Og = O + (b * SEQ + qt * 64) * D_MODEL + h * HDIM;
#pragma unroll
    for (int i = 0; i < 4; i++) {
        int r = tr * 4 + i;
        float inv = 1.0f / l_s[r];
        float4 o;
        o.x = acc[i][0] * inv;
        o.y = acc[i][1] * inv;
        o.z = acc[i][2] * inv;
        o.w = acc[i][3] * inv;
        *(float4*)(Og + r * D_MODEL + tc * 4) = o;
    }
}

// ---------------------------------------------------------------------------
// Launch
// ---------------------------------------------------------------------------
extern "C" void kernel_launch(void* const* d_in, const int* in_sizes, int n_in,
                              void* d_out, int out_size)
{
    const float* x    = (const float*)d_in[0];
    const float* wq   = (const float*)d_in[1];
    const float* bq   = (const float*)d_in[2];
    const float* wk   = (const float*)d_in[3];
    const float* bk   = (const float*)d_in[4];
    const float* wv   = (const float*)d_in[5];
    const float* bv   = (const float*)d_in[6];
    const float* wo   = (const float*)d_in[7];
    const float* bo   = (const float*)d_in[8];
    const float* mask = (const float*)d_in[9];
    float* out = (float*)d_out;

    float *q, *k, *v, *att;
    cudaGetSymbolAddress((void**)&q,   g_q);
    cudaGetSymbolAddress((void**)&k,   g_k);
    cudaGetSymbolAddress((void**)&v,   g_v);
    cudaGetSymbolAddress((void**)&att, g_att);

    cudaFuncSetAttribute(flash_kernel,
                         cudaFuncAttributeMaxDynamicSharedMemorySize, FA_SMEM);
    cudaFuncSetAttribute(gemm_qkv_tc,
                         cudaFuncAttributeMaxDynamicSharedMemorySize, GEMM_SMEM);
    cudaFuncSetAttribute(gemm_out_tc,
                         cudaFuncAttributeMaxDynamicSharedMemorySize, GEMM_SMEM);

    // QKV projections (3xTF32 mma.sync)
    dim3 g1(D_MODEL / 128, ROWS / 128, 3);
    gemm_qkv_tc<<<g1, 256, GEMM_SMEM>>>(x, wq, bq, q, wk, bk, k, wv, bv, v);

    // RoPE in-place on q, k
    int rope_threads = ROWS * N_HEADS * 32;
    rope_kernel<<<rope_threads / 256, 256>>>(q, k);

    // Attention (fp32 SIMT flash, FFMA exp)
    dim3 g2(SEQ / 64, BATCH * N_HEADS);
    flash_kernel<<<g2, 256, FA_SMEM>>>(q, k, v, mask, att);

    // Output projection (3xTF32 mma.sync) -> d_out
    dim3 g3(D_MODEL / 128, ROWS / 128);
    gemm_out_tc<<<g3, 256, GEMM_SMEM>>>(att, wo, bo, out);
}

// round 6
// speedup vs baseline: 2.5360x; 2.1678x over previous
#include <cuda_runtime.h>
#include <cuda_bf16.h>
#include <cstdint>
#include <math.h>

#define D_MODEL 1024
#define N_HEADS 16
#define HDIM    64
#define SEQ     2048
#define BATCH   2
#define ROWS    (BATCH * SEQ)   // 4096

// ---------------------------------------------------------------------------
// Scratch (static device globals — no allocation allowed)
// ---------------------------------------------------------------------------
__device__ float g_q[ROWS * D_MODEL];
__device__ float g_k[ROWS * D_MODEL];
__device__ float g_v[ROWS * D_MODEL];
__device__ float g_att[ROWS * D_MODEL];
__device__ __nv_bfloat16 g_qh[ROWS * D_MODEL];
__device__ __nv_bfloat16 g_qm[ROWS * D_MODEL];
__device__ __nv_bfloat16 g_kh[ROWS * D_MODEL];
__device__ __nv_bfloat16 g_km[ROWS * D_MODEL];
__device__ __nv_bfloat16 g_vth[BATCH * N_HEADS * HDIM * SEQ];  // [bh*64+d][s]
__device__ __nv_bfloat16 g_vtm[BATCH * N_HEADS * HDIM * SEQ];

// ---------------------------------------------------------------------------
// Helpers
// ---------------------------------------------------------------------------
__device__ __forceinline__ uint32_t smem_u32(const void* p) {
    uint32_t a;
    asm("{ .reg .u64 t; cvta.to.shared.u64 t, %1; cvt.u32.u64 %0, t; }"
        : "=r"(a) : "l"(p));
    return a;
}
__device__ __forceinline__ void cp_async16(uint32_t saddr, const void* gptr) {
    asm volatile("cp.async.cg.shared.global [%0], [%1], 16;"
                 :: "r"(saddr), "l"(gptr) : "memory");
}
__device__ __forceinline__ void cp_commit() {
    asm volatile("cp.async.commit_group;" ::: "memory");
}
template <int N>
__device__ __forceinline__ void cp_wait() {
    asm volatile("cp.async.wait_group %0;" :: "n"(N) : "memory");
}
__device__ __forceinline__ uint32_t tf32_rna_bits(float x) {
    uint32_t y;
    asm("cvt.rna.tf32.f32 %0, %1;" : "=r"(y) : "f"(x));
    return y;
}
__device__ __forceinline__ void mma_tf32(float* d, const uint32_t* a,
                                         const uint32_t* b) {
    asm volatile(
        "mma.sync.aligned.m16n8k8.row.col.f32.tf32.tf32.f32 "
        "{%0,%1,%2,%3}, {%4,%5,%6,%7}, {%8,%9}, {%0,%1,%2,%3};"
        : "+f"(d[0]), "+f"(d[1]), "+f"(d[2]), "+f"(d[3])
        : "r"(a[0]), "r"(a[1]), "r"(a[2]), "r"(a[3]), "r"(b[0]), "r"(b[1]));
}
__device__ __forceinline__ void mma_bf16(float* d, const uint32_t* a,
                                         const uint32_t* b) {
    asm volatile(
        "mma.sync.aligned.m16n8k16.row.col.f32.bf16.bf16.f32 "
        "{%0,%1,%2,%3}, {%4,%5,%6,%7}, {%8,%9}, {%0,%1,%2,%3};"
        : "+f"(d[0]), "+f"(d[1]), "+f"(d[2]), "+f"(d[3])
        : "r"(a[0]), "r"(a[1]), "r"(a[2]), "r"(a[3]), "r"(b[0]), "r"(b[1]));
}
// pack {lo, hi} floats into bf16x2 word (lo in low half)
__device__ __forceinline__ uint32_t pack_bf16(float lo, float hi) {
    uint32_t r;
    asm("cvt.rn.bf16x2.f32 %0, %1, %2;" : "=r"(r) : "f"(hi), "f"(lo));
    return r;
}
__device__ __forceinline__ float bf16lo_f(uint32_t w) { return __uint_as_float(w << 16); }
__device__ __forceinline__ float bf16hi_f(uint32_t w) { return __uint_as_float(w & 0xffff0000u); }

// FFMA-only exp, accurate ~1e-7 on [-87, 0]
__device__ __forceinline__ float fast_exp(float x) {
    x = fmaxf(x, -87.0f);
    float y = x * 1.4426950408889634f;
    float r = y + 12582912.0f;
    float n = r - 12582912.0f;
    float f = y - n;
    float t = f * 0.6931471805599453f;
    float p = 1.3888889e-3f;
    p = fmaf(p, t, 8.3333333e-3f);
    p = fmaf(p, t, 4.1666667e-2f);
    p = fmaf(p, t, 1.6666667e-1f);
    p = fmaf(p, t, 0.5f);
    p = fmaf(p, t, 1.0f);
    p = fmaf(p, t, 1.0f);
    int ni = __float_as_int(r) - 0x4B400000;
    float scale = __int_as_float((ni << 23) + 0x3F800000);
    return p * scale;
}

// ---------------------------------------------------------------------------
// 3xTF32 GEMM (unchanged, validated): C = A @ W^T + bias
// ---------------------------------------------------------------------------
#define BK        32
#define NCH       (D_MODEL / BK)
#define LDS_STRIDE 36
#define TILE_FLOATS (128 * LDS_STRIDE)
#define STAGE_FLOATS (2 * TILE_FLOATS)
#define GEMM_SMEM (2 * STAGE_FLOATS * 4)

__device__ __forceinline__ void stage_chunk(
    const float* __restrict__ Arow, const float* __restrict__ Wrow,
    float* __restrict__ smemf, int stage, int k0, int tid)
{
    uint32_t sa = smem_u32(smemf + stage * STAGE_FLOATS);
    uint32_t sb = sa + TILE_FLOATS * 4;
#pragma unroll
    for (int i = 0; i < 4; i++) {
        int idx = tid + i * 256;
        int r   = idx >> 3;
        int f4  = (idx & 7) << 2;
        cp_async16(sa + (r * LDS_STRIDE + f4) * 4, Arow + r * D_MODEL + k0 + f4);
        cp_async16(sb + (r * LDS_STRIDE + f4) * 4, Wrow + r * D_MODEL + k0 + f4);
    }
    cp_commit();
}

__device__ __forceinline__ void gemm_tc_body(
    const float* __restrict__ A, const float* __restrict__ W,
    const float* __restrict__ bias, float* __restrict__ C)
{
    extern __shared__ float smemf[];
    const int tid  = threadIdx.x;
    const int wid  = tid >> 5;
    const int lane = tid & 31;
    const int wm   = (wid & 1) * 64;
    const int wn   = (wid >> 1) * 32;
    const int brow = blockIdx.y * 128;
    const int bcol = blockIdx.x * 128;
    const int qrow = lane >> 2;
    const int qcol = lane & 3;

    float acc[4][4][4];
#pragma unroll
    for (int mf = 0; mf < 4; mf++)
#pragma unroll
        for (int nf = 0; nf < 4; nf++)
#pragma unroll
            for (int r = 0; r < 4; r++) acc[mf][nf][r] = 0.0f;

    const float* Arow = A + brow * D_MODEL;
    const float* Wrow = W + bcol * D_MODEL;

    stage_chunk(Arow, Wrow, smemf, 0, 0, tid);
    stage_chunk(Arow, Wrow, smemf, 1, BK, tid);

    for (int c = 0; c < NCH; c++) {
        if (c == NCH - 1) cp_wait<0>(); else cp_wait<1>();
        __syncthreads();
        const float* As = smemf + (c & 1) * STAGE_FLOATS;
        const float* Bs = As + TILE_FLOATS;

#pragma unroll
        for (int ks = 0; ks < 4; ks++) {
            const int kc = ks * 8 + qcol;
            uint32_t a_hi[4][4], a_lo[4][4];
#pragma unroll
            for (int mf = 0; mf < 4; mf++) {
                const float* ap = As + (wm + mf * 16 + qrow) * LDS_STRIDE + kc;
                float v0 = ap[0], v1 = ap[8 * LDS_STRIDE];
                float v2 = ap[4], v3 = ap[8 * LDS_STRIDE + 4];
                uint32_t h0 = tf32_rna_bits(v0), h1 = tf32_rna_bits(v1);
                uint32_t h2 = tf32_rna_bits(v2), h3 = tf32_rna_bits(v3);
                a_hi[mf][0] = h0; a_hi[mf][1] = h1; a_hi[mf][2] = h2; a_hi[mf][3] = h3;
                a_lo[mf][0] = __float_as_uint(v0 - __uint_as_float(h0));
                a_lo[mf][1] = __float_as_uint(v1 - __uint_as_float(h1));
                a_lo[mf][2] = __float_as_uint(v2 - __uint_as_float(h2));
                a_lo[mf][3] = __float_as_uint(v3 - __uint_as_float(h3));
            }
            uint32_t b_hi[4][2], b_lo[4][2];
#pragma unroll
            for (int nf = 0; nf < 4; nf++) {
                const float* bp = Bs + (wn + nf * 8 + qrow) * LDS_STRIDE + kc;
                float v0 = bp[0], v1 = bp[4];
                uint32_t h0 = tf32_rna_bits(v0), h1 = tf32_rna_bits(v1);
                b_hi[nf][0] = h0; b_hi[nf][1] = h1;
                b_lo[nf][0] = __float_as_uint(v0 - __uint_as_float(h0));
                b_lo[nf][1] = __float_as_uint(v1 - __uint_as_float(h1));
            }
#pragma unroll
            for (int mf = 0; mf < 4; mf++)
#pragma unroll
                for (int nf = 0; nf < 4; nf++) {
                    mma_tf32(acc[mf][nf], a_lo[mf], b_hi[nf]);
                    mma_tf32(acc[mf][nf], a_hi[mf], b_lo[nf]);
                    mma_tf32(acc[mf][nf], a_hi[mf], b_hi[nf]);
                }
        }
        __syncthreads();
        if (c + 2 < NCH)
            stage_chunk(Arow, Wrow, smemf, c & 1, (c + 2) * BK, tid);
    }

#pragma unroll
    for (int mf = 0; mf < 4; mf++) {
        int row0 = brow + wm + mf * 16 + qrow;
#pragma unroll
        for (int nf = 0; nf < 4; nf++) {
            int col = bcol + wn + nf * 8 + 2 * qcol;
            float b0 = bias[col], b1 = bias[col + 1];
            float2 v0 = make_float2(acc[mf][nf][0] + b0, acc[mf][nf][1] + b1);
            float2 v1 = make_float2(acc[mf][nf][2] + b0, acc[mf][nf][3] + b1);
            *(float2*)(C + row0 * D_MODEL + col)       = v0;
            *(float2*)(C + (row0 + 8) * D_MODEL + col) = v1;
        }
    }
}

__global__ __launch_bounds__(256)
void gemm_qkv_tc(const float* __restrict__ X,
                 const float* __restrict__ Wq, const float* __restrict__ Bq, float* __restrict__ Oq,
                 const float* __restrict__ Wk, const float* __restrict__ Bk, float* __restrict__ Ok,
                 const float* __restrict__ Wv, const float* __restrict__ Bv, float* __restrict__ Ov)
{
    const float* W; const float* bb; float* C;
    if (blockIdx.z == 0)      { W = Wq; bb = Bq; C = Oq; }
    else if (blockIdx.z == 1) { W = Wk; bb = Bk; C = Ok; }
    else                      { W = Wv; bb = Bv; C = Ov; }
    gemm_tc_body(X, W, bb, C);
}

__global__ __launch_bounds__(256)
void gemm_out_tc(const float* __restrict__ A, const float* __restrict__ W,
                 const float* __restrict__ bb, float* __restrict__ C)
{
    gemm_tc_body(A, W, bb, C);
}

// ---------------------------------------------------------------------------
// RoPE + split: read fp32 q,k; write rotated values as bf16 hi/mid pairs.
// Layout preserved: [row = b*S+s][h*64 + d], rotation pairs (i, i+32).
// ---------------------------------------------------------------------------
__global__ void rope_split_kernel(const float* __restrict__ q, const float* __restrict__ k,
                                  __nv_bfloat16* __restrict__ qh, __nv_bfloat16* __restrict__ qm,
                                  __nv_bfloat16* __restrict__ kh, __nv_bfloat16* __restrict__ km)
{
    int idx = blockIdx.x * blockDim.x + threadIdx.x;
    if (idx >= ROWS * N_HEADS * 32) return;
    int i   = idx & 31;
    int h   = (idx >> 5) & (N_HEADS - 1);
    int row = idx >> 9;
    int t   = row & (SEQ - 1);

    float inv = 1.0f / powf(10000.0f, (float)(2 * i) * (1.0f / 64.0f));
    float ang = (float)t * inv;
    float sn, cs;
    sincosf(ang, &sn, &cs);

    int base = row * D_MODEL + h * HDIM + i;
    float q1 = q[base], q2 = q[base + 32];
    float k1 = k[base], k2 = k[base + 32];
    float qa = q1 * cs - q2 * sn;
    float qb = q2 * cs + q1 * sn;
    float ka = k1 * cs - k2 * sn;
    float kb = k2 * cs + k1 * sn;

    __nv_bfloat16 hv;
    hv = __float2bfloat16_rn(qa); qh[base]      = hv; qm[base]      = __float2bfloat16_rn(qa - __bfloat162float(hv));
    hv = __float2bfloat16_rn(qb); qh[base + 32] = hv; qm[base + 32] = __float2bfloat16_rn(qb - __bfloat162float(hv));
    hv = __float2bfloat16_rn(ka); kh[base]      = hv; km[base]      = __float2bfloat16_rn(ka - __bfloat162float(hv));
    hv = __float2bfloat16_rn(kb); kh[base + 32] = hv; km[base + 32] = __float2bfloat16_rn(kb - __bfloat162float(hv));
}

// ---------------------------------------------------------------------------
// V split + transpose: v fp32 [b*S+s][h*64+d] -> vT hi/mid bf16 [(bh*64)+d][s]
// Block: 64 s x 64 d tile per (s-tile, bh).
// ---------------------------------------------------------------------------
__global__ __launch_bounds__(256)
void v_split_t_kernel(const float* __restrict__ v,
                      __nv_bfloat16* __restrict__ vth, __nv_bfloat16* __restrict__ vtm)
{
    __shared__ __nv_bfloat16 th[64][66];
    __shared__ __nv_bfloat16 tm[64][66];
    const int tid = threadIdx.x;
    const int st  = blockIdx.x;          // s tile
    const int bh  = blockIdx.y;
    const int b   = bh >> 4;
    const int h   = bh & 15;
    const int s0  = st * 64;

#pragma unroll
    for (int l = 0; l < 16; l++) {
        int e = l * 256 + tid;
        int r = e >> 6, d = e & 63;
        float x = v[(b * SEQ + s0 + r) * D_MODEL + h * HDIM + d];
        __nv_bfloat16 hv = __float2bfloat16_rn(x);
        th[d][r] = hv;
        tm[d][r] = __float2bfloat16_rn(x - __bfloat162float(hv));
    }
    __syncthreads();
#pragma unroll
    for (int l = 0; l < 16; l++) {
        int e = l * 256 + tid;
        int d = e >> 6, sc = e & 63;
        int o = (bh * HDIM + d) * SEQ + s0 + sc;
        vth[o] = th[d][sc];
        vtm[o] = tm[d][sc];
    }
}

// ---------------------------------------------------------------------------
// Flash attention, bf16x3 mma.sync.
// Block: 128 q rows x (b,h). 8 warps, each 16 q rows x full 64-key tile.
// Smem rows padded to 72 bf16 (144B) -> conflict-free 32-bit fragment loads.
// ---------------------------------------------------------------------------
#define NT       (SEQ / 64)     // 32 key tiles
#define FL_QH    0
#define FL_QM    18432
#define FL_KH(s) (36864  + (s) * 9216)
#define FL_KM(s) (55296  + (s) * 9216)
#define FL_VH(s) (73728  + (s) * 9216)
#define FL_VM(s) (92160  + (s) * 9216)
#define FL_MS(s) (110592 + (s) * 256)
#define FA2_SMEM 111104

__global__ __launch_bounds__(256)
void flash2_kernel(const __nv_bfloat16* __restrict__ Qh, const __nv_bfloat16* __restrict__ Qm,
                   const __nv_bfloat16* __restrict__ Kh, const __nv_bfloat16* __restrict__ Km,
                   const __nv_bfloat16* __restrict__ Vth, const __nv_bfloat16* __restrict__ Vtm,
                   const float* __restrict__ mask, float* __restrict__ O)
{
    extern __shared__ char sm2[];
    const int tid  = threadIdx.x;
    const int w    = tid >> 5;
    const int lane = tid & 31;
    const int g    = lane >> 2;
    const int t    = lane & 3;
    const int qt   = blockIdx.x;
    const int bh   = blockIdx.y;
    const int b    = bh >> 4;
    const int h    = bh & 15;
    const uint32_t sbase = smem_u32(sm2);

    const __nv_bfloat16* qh_g = Qh + (b * SEQ + qt * 128) * D_MODEL + h * HDIM;
    const __nv_bfloat16* qm_g = Qm + (b * SEQ + qt * 128) * D_MODEL + h * HDIM;
    const __nv_bfloat16* kh_g = Kh + b * SEQ * D_MODEL + h * HDIM;
    const __nv_bfloat16* km_g = Km + b * SEQ * D_MODEL + h * HDIM;
    const __nv_bfloat16* vh_g = Vth + bh * HDIM * SEQ;
    const __nv_bfloat16* vm_g = Vtm + bh * HDIM * SEQ;
    const float* mask_g = mask + b * SEQ;

    // Stage a key tile kt into stage buffer s
    auto stage = [&](int kt, int s) {
#pragma unroll
        for (int i = 0; i < 2; i++) {
            int idx = tid + i * 256;           // 0..511
            int r   = idx >> 3;                // 0..63
            int ch  = idx & 7;                 // 16B chunk
            cp_async16(sbase + FL_KH(s) + r * 144 + ch * 16,
                       kh_g + (kt * 64 + r) * D_MODEL + ch * 8);
            cp_async16(sbase + FL_KM(s) + r * 144 + ch * 16,
                       km_g + (kt * 64 + r) * D_MODEL + ch * 8);
            cp_async16(sbase + FL_VH(s) + r * 144 + ch * 16,
                       vh_g + r * SEQ + kt * 64 + ch * 8);
            cp_async16(sbase + FL_VM(s) + r * 144 + ch * 16,
                       vm_g + r * SEQ + kt * 64 + ch * 8);
        }
        if (tid < 16)
            cp_async16(sbase + FL_MS(s) + tid * 16, mask_g + kt * 64 + tid * 4);
    };

    // Load Q tile (once) + tile 0, one commit group
#pragma unroll
    for (int i = 0; i < 4; i++) {
        int idx = tid + i * 256;               // 0..1023
        int r   = idx >> 3;
        int ch  = idx & 7;
        cp_async16(sbase + FL_QH + r * 144 + ch * 16, qh_g + r * D_MODEL + ch * 8);
        cp_async16(sbase + FL_QM + r * 144 + ch * 16, qm_g + r * D_MODEL + ch * 8);
    }
    stage(0, 0);
    cp_commit();

    float o[8][4];
#pragma unroll
    for (int nf = 0; nf < 8; nf++)
#pragma unroll
        for (int j = 0; j < 4; j++) o[nf][j] = 0.0f;
    float m0 = -1e30f, m1 = -1e30f, l0 = 0.0f, l1 = 0.0f;

    const uint32_t qh_s = sbase + FL_QH + (w * 16 + g) * 144;
    const uint32_t qm_s = sbase + FL_QM + (w * 16 + g) * 144;

    for (int kt = 0; kt < NT; kt++) {
        const int s = kt & 1;
        if (kt + 1 < NT) { stage(kt + 1, s ^ 1); cp_commit(); cp_wait<1>(); }
        else             { cp_wait<0>(); }
        __syncthreads();

        // ---- S = Q K^T (bf16x3) ----
        float sc[8][4];
#pragma unroll
        for (int nf = 0; nf < 8; nf++)
#pragma unroll
            for (int j = 0; j < 4; j++) sc[nf][j] = 0.0f;

        const uint32_t kh_s = sbase + FL_KH(s) + g * 144;
        const uint32_t km_s = sbase + FL_KM(s) + g * 144;
#pragma unroll
        for (int ks = 0; ks < 4; ks++) {
            uint32_t ah[4], am[4];
            ah[0] = *(const uint32_t*)(sm2 + (qh_s - sbase) + (ks * 8 + t) * 4);
            ah[1] = *(const uint32_t*)(sm2 + (qh_s - sbase) + 8 * 144 + (ks * 8 + t) * 4);
            ah[2] = *(const uint32_t*)(sm2 + (qh_s - sbase) + (ks * 8 + t + 4) * 4);
            ah[3] = *(const uint32_t*)(sm2 + (qh_s - sbase) + 8 * 144 + (ks * 8 + t + 4) * 4);
            am[0] = *(const uint32_t*)(sm2 + (qm_s - sbase) + (ks * 8 + t) * 4);
            am[1] = *(const uint32_t*)(sm2 + (qm_s - sbase) + 8 * 144 + (ks * 8 + t) * 4);
            am[2] = *(const uint32_t*)(sm2 + (qm_s - sbase) + (ks * 8 + t + 4) * 4);
            am[3] = *(const uint32_t*)(sm2 + (qm_s - sbase) + 8 * 144 + (ks * 8 + t + 4) * 4);
#pragma unroll
            for (int nf = 0; nf < 8; nf++) {
                uint32_t bh2[2], bm2[2];
                bh2[0] = *(const uint32_t*)(sm2 + (kh_s - sbase) + nf * 8 * 144 + (ks * 8 + t) * 4);
                bh2[1] = *(const uint32_t*)(sm2 + (kh_s - sbase) + nf * 8 * 144 + (ks * 8 + t + 4) * 4);
                bm2[0] = *(const uint32_t*)(sm2 + (km_s - sbase) + nf * 8 * 144 + (ks * 8 + t) * 4);
                bm2[1] = *(const uint32_t*)(sm2 + (km_s - sbase) + nf * 8 * 144 + (ks * 8 + t + 4) * 4);
                mma_bf16(sc[nf], am, bh2);
                mma_bf16(sc[nf], ah, bm2);
                mma_bf16(sc[nf], ah, bh2);
            }
        }

        // ---- scale + mask + online softmax (warp-local) ----
        float rmax0 = -1e30f, rmax1 = -1e30f;
#pragma unroll
        for (int nf = 0; nf < 8; nf++) {
            float2 mk = *(const float2*)(sm2 + FL_MS(s) + (nf * 8 + 2 * t) * 4);
            sc[nf][0] = fmaf(sc[nf][0], 0.125f, mk.x);
            sc[nf][1] = fmaf(sc[nf][1], 0.125f, mk.y);
            sc[nf][2] = fmaf(sc[nf][2], 0.125f, mk.x);
            sc[nf][3] = fmaf(sc[nf][3], 0.125f, mk.y);
            rmax0 = fmaxf(rmax0, fmaxf(sc[nf][0], sc[nf][1]));
            rmax1 = fmaxf(rmax1, fmaxf(sc[nf][2], sc[nf][3]));
        }
        rmax0 = fmaxf(rmax0, __shfl_xor_sync(0xffffffffu, rmax0, 1));
        rmax0 = fmaxf(rmax0, __shfl_xor_sync(0xffffffffu, rmax0, 2));
        rmax1 = fmaxf(rmax1, __shfl_xor_sync(0xffffffffu, rmax1, 1));
        rmax1 = fmaxf(rmax1, __shfl_xor_sync(0xffffffffu, rmax1, 2));
        float mn0 = fmaxf(m0, rmax0), mn1 = fmaxf(m1, rmax1);
        float c0 = fast_exp(m0 - mn0), c1 = fast_exp(m1 - mn1);
        float sum0 = 0.0f, sum1 = 0.0f;
#pragma unroll
        for (int nf = 0; nf < 8; nf++) {
            sc[nf][0] = fast_exp(sc[nf][0] - mn0);
            sc[nf][1] = fast_exp(sc[nf][1] - mn0);
            sc[nf][2] = fast_exp(sc[nf][2] - mn1);
            sc[nf][3] = fast_exp(sc[nf][3] - mn1);
            sum0 += sc[nf][0] + sc[nf][1];
            sum1 += sc[nf][2] + sc[nf][3];
        }
        sum0 += __shfl_xor_sync(0xffffffffu, sum0, 1);
        sum0 += __shfl_xor_sync(0xffffffffu, sum0, 2);
        sum1 += __shfl_xor_sync(0xffffffffu, sum1, 1);
        sum1 += __shfl_xor_sync(0xffffffffu, sum1, 2);
        l0 = l0 * c0 + sum0;
        l1 = l1 * c1 + sum1;
        m0 = mn0; m1 = mn1;
#pragma unroll
        for (int nf = 0; nf < 8; nf++) {
            o[nf][0] *= c0; o[nf][1] *= c0;
            o[nf][2] *= c1; o[nf][3] *= c1;
        }

        // ---- O += P V (bf16x3; P split in registers) ----
        const uint32_t vh_s = sbase + FL_VH(s) + g * 144;
        const uint32_t vm_s = sbase + FL_VM(s) + g * 144;
#pragma unroll
        for (int ks = 0; ks < 4; ks++) {
            uint32_t ph[4], pm[4];
            ph[0] = pack_bf16(sc[2 * ks][0],     sc[2 * ks][1]);
            ph[1] = pack_bf16(sc[2 * ks][2],     sc[2 * ks][3]);
            ph[2] = pack_bf16(sc[2 * ks + 1][0], sc[2 * ks + 1][1]);
            ph[3] = pack_bf16(sc[2 * ks + 1][2], sc[2 * ks + 1][3]);
            pm[0] = pack_bf16(sc[2 * ks][0]     - bf16lo_f(ph[0]), sc[2 * ks][1]     - bf16hi_f(ph[0]));
            pm[1] = pack_bf16(sc[2 * ks][2]     - bf16lo_f(ph[1]), sc[2 * ks][3]     - bf16hi_f(ph[1]));
            pm[2] = pack_bf16(sc[2 * ks + 1][0] - bf16lo_f(ph[2]), sc[2 * ks + 1][1] - bf16hi_f(ph[2]));
            pm[3] = pack_bf16(sc[2 * ks + 1][2] - bf16lo_f(ph[3]), sc[2 * ks + 1][3] - bf16hi_f(ph[3]));
#pragma unroll
            for (int nf = 0; nf < 8; nf++) {
                uint32_t bh2[2], bm2[2];
                bh2[0] = *(const uint32_t*)(sm2 + (vh_s - sbase) + nf * 8 * 144 + (ks * 8 + t) * 4);
                bh2[1] = *(const uint32_t*)(sm2 + (vh_s - sbase) + nf * 8 * 144 + (ks * 8 + t + 4) * 4);
                bm2[0] = *(const uint32_t*)(sm2 + (vm_s - sbase) + nf * 8 * 144 + (ks * 8 + t) * 4);
                bm2[1] = *(const uint32_t*)(sm2 + (vm_s - sbase) + nf * 8 * 144 + (ks * 8 + t + 4) * 4);
                mma_bf16(o[nf], pm, bh2);
                mma_bf16(o[nf], ph, bm2);
                mma_bf16(o[nf], ph, bh2);
            }
        }
        __syncthreads();
    }

    // ---- epilogue ----
    float i0 = 1.0f / l0, i1 = 1.0f / l1;
    float* Og = O + (b * SEQ + qt * 128 + w * 16 + g) * D_MODEL + h * HDIM;
#pragma unroll
    for (int nf = 0; nf < 8; nf++) {
        *(float2*)(Og + nf * 8 + 2 * t) =
            make_float2(o[nf][0] * i0, o[nf][1] * i0);
        *(float2*)(Og + 8 * D_MODEL + nf * 8 + 2 * t) =
            make_float2(o[nf][2] * i1, o[nf][3] * i1);
    }
}

// ---------------------------------------------------------------------------
// Launch
// ---------------------------------------------------------------------------
extern "C" void kernel_launch(void* const* d_in, const int* in_sizes, int n_in,
                              void* d_out, int out_size)
{
    const float* x    = (const float*)d_in[0];
    const float* wq   = (const float*)d_in[1];
    const float* bq   = (const float*)d_in[2];
    const float* wk   = (const float*)d_in[3];
    const float* bk   = (const float*)d_in[4];
    const float* wv   = (const float*)d_in[5];
    const float* bv   = (const float*)d_in[6];
    const float* wo   = (const float*)d_in[7];
    const float* bo   = (const float*)d_in[8];
    const float* mask = (const float*)d_in[9];
    float* out = (float*)d_out;

    float *q, *k, *v, *att;
    __nv_bfloat16 *qh, *qm, *kh, *km, *vth, *vtm;
    cudaGetSymbolAddress((void**)&q,   g_q);
    cudaGetSymbolAddress((void**)&k,   g_k);
    cudaGetSymbolAddress((void**)&v,   g_v);
    cudaGetSymbolAddress((void**)&att, g_att);
    cudaGetSymbolAddress((void**)&qh,  g_qh);
    cudaGetSymbolAddress((void**)&qm,  g_qm);
    cudaGetSymbolAddress((void**)&kh,  g_kh);
    cudaGetSymbolAddress((void**)&km,  g_km);
    cudaGetSymbolAddress((void**)&vth, g_vth);
    cudaGetSymbolAddress((void**)&vtm, g_vtm);

    cudaFuncSetAttribute(gemm_qkv_tc,
                         cudaFuncAttributeMaxDynamicSharedMemorySize, GEMM_SMEM);
    cudaFuncSetAttribute(gemm_out_tc,
                         cudaFuncAttributeMaxDynamicSharedMemorySize, GEMM_SMEM);
    cudaFuncSetAttribute(flash2_kernel,
                         cudaFuncAttributeMaxDynamicSharedMemorySize, FA2_SMEM);

    // QKV projections (3xTF32 mma.sync)
    dim3 g1(D_MODEL / 128, ROWS / 128, 3);
    gemm_qkv_tc<<<g1, 256, GEMM_SMEM>>>(x, wq, bq, q, wk, bk, k, wv, bv, v);

    // RoPE + bf16 hi/mid split of q, k
    int rope_threads = ROWS * N_HEADS * 32;
    rope_split_kernel<<<rope_threads / 256, 256>>>(q, k, qh, qm, kh, km);

    // V split + transpose
    v_split_t_kernel<<<dim3(SEQ / 64, BATCH * N_HEADS), 256>>>(v, vth, vtm);

    // Flash attention (bf16x3 mma.sync)
    flash2_kernel<<<dim3(SEQ / 128, BATCH * N_HEADS), 256, FA2_SMEM>>>(
        qh, qm, kh, km, vth, vtm, mask, att);

    // Output projection (3xTF32 mma.sync) -> d_out
    dim3 g3(D_MODEL / 128, ROWS / 128);
    gemm_out_tc<<<g3, 256, GEMM_SMEM>>>(att, wo, bo, out);
}

// round 7
// speedup vs baseline: 3.1390x; 1.2378x over previous
#include <cuda_runtime.h>
#include <cuda_bf16.h>
#include <cstdint>
#include <math.h>

#define D_MODEL 1024
#define N_HEADS 16
#define HDIM    64
#define SEQ     2048
#define BATCH   2
#define ROWS    (BATCH * SEQ)   // 4096

// ---------------------------------------------------------------------------
// Scratch (static device globals — no allocation allowed)
// ---------------------------------------------------------------------------
__device__ float g_q[ROWS * D_MODEL];
__device__ float g_k[ROWS * D_MODEL];
__device__ float g_v[ROWS * D_MODEL];
__device__ float g_att[ROWS * D_MODEL];
__device__ __nv_bfloat16 g_qh[ROWS * D_MODEL];
__device__ __nv_bfloat16 g_qm[ROWS * D_MODEL];
__device__ __nv_bfloat16 g_kh[ROWS * D_MODEL];
__device__ __nv_bfloat16 g_km[ROWS * D_MODEL];
__device__ __nv_bfloat16 g_vth[BATCH * N_HEADS * HDIM * SEQ];  // [bh*64+d][s]
__device__ __nv_bfloat16 g_vtm[BATCH * N_HEADS * HDIM * SEQ];
// bf16 hi/mid splits for GEMM operands
__device__ __nv_bfloat16 g_xh[ROWS * D_MODEL];
__device__ __nv_bfloat16 g_xm[ROWS * D_MODEL];
__device__ __nv_bfloat16 g_ath[ROWS * D_MODEL];
__device__ __nv_bfloat16 g_atm[ROWS * D_MODEL];
__device__ __nv_bfloat16 g_wqh[D_MODEL * D_MODEL];
__device__ __nv_bfloat16 g_wqm[D_MODEL * D_MODEL];
__device__ __nv_bfloat16 g_wkh[D_MODEL * D_MODEL];
__device__ __nv_bfloat16 g_wkm[D_MODEL * D_MODEL];
__device__ __nv_bfloat16 g_wvh[D_MODEL * D_MODEL];
__device__ __nv_bfloat16 g_wvm[D_MODEL * D_MODEL];
__device__ __nv_bfloat16 g_woh[D_MODEL * D_MODEL];
__device__ __nv_bfloat16 g_wom[D_MODEL * D_MODEL];

// ---------------------------------------------------------------------------
// Helpers
// ---------------------------------------------------------------------------
__device__ __forceinline__ uint32_t smem_u32(const void* p) {
    uint32_t a;
    asm("{ .reg .u64 t; cvta.to.shared.u64 t, %1; cvt.u32.u64 %0, t; }"
        : "=r"(a) : "l"(p));
    return a;
}
__device__ __forceinline__ void cp_async16(uint32_t saddr, const void* gptr) {
    asm volatile("cp.async.cg.shared.global [%0], [%1], 16;"
                 :: "r"(saddr), "l"(gptr) : "memory");
}
__device__ __forceinline__ void cp_commit() {
    asm volatile("cp.async.commit_group;" ::: "memory");
}
template <int N>
__device__ __forceinline__ void cp_wait() {
    asm volatile("cp.async.wait_group %0;" :: "n"(N) : "memory");
}
__device__ __forceinline__ void mma_bf16(float* d, const uint32_t* a,
                                         const uint32_t* b) {
    asm volatile(
        "mma.sync.aligned.m16n8k16.row.col.f32.bf16.bf16.f32 "
        "{%0,%1,%2,%3}, {%4,%5,%6,%7}, {%8,%9}, {%0,%1,%2,%3};"
        : "+f"(d[0]), "+f"(d[1]), "+f"(d[2]), "+f"(d[3])
        : "r"(a[0]), "r"(a[1]), "r"(a[2]), "r"(a[3]), "r"(b[0]), "r"(b[1]));
}
__device__ __forceinline__ uint32_t pack_bf16(float lo, float hi) {
    uint32_t r;
    asm("cvt.rn.bf16x2.f32 %0, %1, %2;" : "=r"(r) : "f"(hi), "f"(lo));
    return r;
}
__device__ __forceinline__ float bf16lo_f(uint32_t w) { return __uint_as_float(w << 16); }
__device__ __forceinline__ float bf16hi_f(uint32_t w) { return __uint_as_float(w & 0xffff0000u); }

// FFMA-only exp, accurate ~1e-7 on [-87, 0]
__device__ __forceinline__ float fast_exp(float x) {
    x = fmaxf(x, -87.0f);
    float y = x * 1.4426950408889634f;
    float r = y + 12582912.0f;
    float n = r - 12582912.0f;
    float f = y - n;
    float t = f * 0.6931471805599453f;
    float p = 1.3888889e-3f;
    p = fmaf(p, t, 8.3333333e-3f);
    p = fmaf(p, t, 4.1666667e-2f);
    p = fmaf(p, t, 1.6666667e-1f);
    p = fmaf(p, t, 0.5f);
    p = fmaf(p, t, 1.0f);
    p = fmaf(p, t, 1.0f);
    int ni = __float_as_int(r) - 0x4B400000;
    float scale = __int_as_float((ni << 23) + 0x3F800000);
    return p * scale;
}

// ---------------------------------------------------------------------------
// Split prepass: fp32 -> bf16 hi + mid (residual). Vectorized by 4.
// ---------------------------------------------------------------------------
__global__ __launch_bounds__(256)
void split_kernel(const float* __restrict__ src,
                  __nv_bfloat16* __restrict__ h, __nv_bfloat16* __restrict__ m,
                  int n4)
{
    int i = blockIdx.x * blockDim.x + threadIdx.x;
    if (i >= n4) return;
    float4 x = *(const float4*)(src + i * 4);
    __nv_bfloat16 h0 = __float2bfloat16_rn(x.x);
    __nv_bfloat16 h1 = __float2bfloat16_rn(x.y);
    __nv_bfloat16 h2 = __float2bfloat16_rn(x.z);
    __nv_bfloat16 h3 = __float2bfloat16_rn(x.w);
    __nv_bfloat162* hp = (__nv_bfloat162*)(h + i * 4);
    hp[0] = __nv_bfloat162(h0, h1);
    hp[1] = __nv_bfloat162(h2, h3);
    __nv_bfloat162* mp = (__nv_bfloat162*)(m + i * 4);
    mp[0] = __nv_bfloat162(__float2bfloat16_rn(x.x - __bfloat162float(h0)),
                           __float2bfloat16_rn(x.y - __bfloat162float(h1)));
    mp[1] = __nv_bfloat162(__float2bfloat16_rn(x.z - __bfloat162float(h2)),
                           __float2bfloat16_rn(x.w - __bfloat162float(h3)));
}

// ---------------------------------------------------------------------------
// bf16x3 tensor-core GEMM: C[M,N] = A[M,K] @ W[N,K]^T + bias[N]
// A, W pre-split into bf16 hi/mid. 128x128x32 CTA tile, 256 threads (8 warps
// as 2x4), warp tile 64x32, m16n8k16 fragments, cp.async double buffering.
// Smem rows padded to 20 words (40 bf16) -> conflict-free fragment loads.
// ---------------------------------------------------------------------------
#define BK2      32
#define NCH2     (D_MODEL / BK2)       // 32 chunks
#define BW       20                    // u32 words per smem row
#define TILE_W   (128 * BW)            // 2560 words per tile
#define STAGE_W  (4 * TILE_W)          // Ah, Am, Bh, Bm
#define GEMM_SMEM2 (2 * STAGE_W * 4)   // 81920 bytes

__device__ __forceinline__ void stage_chunk2(
    const __nv_bfloat16* __restrict__ Ah, const __nv_bfloat16* __restrict__ Am,
    const __nv_bfloat16* __restrict__ Wh, const __nv_bfloat16* __restrict__ Wm,
    uint32_t sbase, int stage, int k0, int tid)
{
    const __nv_bfloat16* src[4] = { Ah, Am, Wh, Wm };
    uint32_t s0 = sbase + stage * STAGE_W * 4;
#pragma unroll
    for (int i = 0; i < 8; i++) {
        int idx  = tid + i * 256;         // 0..2047
        int tile = idx >> 9;              // 0..3
        int wi   = idx & 511;
        int r    = wi >> 2;               // row 0..127
        int ch   = wi & 3;                // 16B chunk (8 bf16)
        cp_async16(s0 + (tile * TILE_W + r * BW + ch * 4) * 4,
                   src[tile] + r * D_MODEL + k0 + ch * 8);
    }
    cp_commit();
}

__device__ __forceinline__ void gemm_bf_body(
    const __nv_bfloat16* __restrict__ Ah, const __nv_bfloat16* __restrict__ Am,
    const __nv_bfloat16* __restrict__ Wh, const __nv_bfloat16* __restrict__ Wm,
    const float* __restrict__ bias, float* __restrict__ C)
{
    extern __shared__ uint32_t smw[];
    const uint32_t sbase = smem_u32(smw);
    const int tid  = threadIdx.x;
    const int wid  = tid >> 5;
    const int lane = tid & 31;
    const int wm   = (wid & 1) * 64;
    const int wn   = (wid >> 1) * 32;
    const int brow = blockIdx.y * 128;
    const int bcol = blockIdx.x * 128;
    const int g    = lane >> 2;
    const int t    = lane & 3;

    float acc[4][4][4];
#pragma unroll
    for (int mf = 0; mf < 4; mf++)
#pragma unroll
        for (int nf = 0; nf < 4; nf++)
#pragma unroll
            for (int r = 0; r < 4; r++) acc[mf][nf][r] = 0.0f;

    const __nv_bfloat16* Ah_r = Ah + brow * D_MODEL;
    const __nv_bfloat16* Am_r = Am + brow * D_MODEL;
    const __nv_bfloat16* Wh_r = Wh + bcol * D_MODEL;
    const __nv_bfloat16* Wm_r = Wm + bcol * D_MODEL;

    stage_chunk2(Ah_r, Am_r, Wh_r, Wm_r, sbase, 0, 0, tid);
    stage_chunk2(Ah_r, Am_r, Wh_r, Wm_r, sbase, 1, BK2, tid);

    for (int c = 0; c < NCH2; c++) {
        if (c == NCH2 - 1) cp_wait<0>(); else cp_wait<1>();
        __syncthreads();

        const uint32_t* S  = smw + (c & 1) * STAGE_W;
        const uint32_t* sAh = S;
        const uint32_t* sAm = S + TILE_W;
        const uint32_t* sBh = S + 2 * TILE_W;
        const uint32_t* sBm = S + 3 * TILE_W;

#pragma unroll
        for (int ks = 0; ks < 2; ks++) {
            const int kw = ks * 8 + t;
            uint32_t ah[4][4], am[4][4];
#pragma unroll
            for (int mf = 0; mf < 4; mf++) {
                int r0 = wm + mf * 16 + g;
                ah[mf][0] = sAh[r0 * BW + kw];
                ah[mf][1] = sAh[(r0 + 8) * BW + kw];
                ah[mf][2] = sAh[r0 * BW + kw + 4];
                ah[mf][3] = sAh[(r0 + 8) * BW + kw + 4];
                am[mf][0] = sAm[r0 * BW + kw];
                am[mf][1] = sAm[(r0 + 8) * BW + kw];
                am[mf][2] = sAm[r0 * BW + kw + 4];
                am[mf][3] = sAm[(r0 + 8) * BW + kw + 4];
            }
            uint32_t bh[4][2], bm[4][2];
#pragma unroll
            for (int nf = 0; nf < 4; nf++) {
                int rb = wn + nf * 8 + g;
                bh[nf][0] = sBh[rb * BW + kw];
                bh[nf][1] = sBh[rb * BW + kw + 4];
                bm[nf][0] = sBm[rb * BW + kw];
                bm[nf][1] = sBm[rb * BW + kw + 4];
            }
#pragma unroll
            for (int mf = 0; mf < 4; mf++)
#pragma unroll
                for (int nf = 0; nf < 4; nf++) {
                    mma_bf16(acc[mf][nf], am[mf], bh[nf]);
                    mma_bf16(acc[mf][nf], ah[mf], bm[nf]);
                    mma_bf16(acc[mf][nf], ah[mf], bh[nf]);
                }
        }

        __syncthreads();
        if (c + 2 < NCH2)
            stage_chunk2(Ah_r, Am_r, Wh_r, Wm_r, sbase, c & 1, (c + 2) * BK2, tid);
    }

#pragma unroll
    for (int mf = 0; mf < 4; mf++) {
        int row0 = brow + wm + mf * 16 + g;
#pragma unroll
        for (int nf = 0; nf < 4; nf++) {
            int col = bcol + wn + nf * 8 + 2 * t;
            float b0 = bias[col], b1 = bias[col + 1];
            float2 v0 = make_float2(acc[mf][nf][0] + b0, acc[mf][nf][1] + b1);
            float2 v1 = make_float2(acc[mf][nf][2] + b0, acc[mf][nf][3] + b1);
            *(float2*)(C + row0 * D_MODEL + col)       = v0;
            *(float2*)(C + (row0 + 8) * D_MODEL + col) = v1;
        }
    }
}

__global__ __launch_bounds__(256)
void gemm_qkv_bf(const __nv_bfloat16* __restrict__ Xh, const __nv_bfloat16* __restrict__ Xm,
                 const __nv_bfloat16* __restrict__ Wqh, const __nv_bfloat16* __restrict__ Wqm,
                 const float* __restrict__ Bq, float* __restrict__ Oq,
                 const __nv_bfloat16* __restrict__ Wkh, const __nv_bfloat16* __restrict__ Wkm,
                 const float* __restrict__ Bk, float* __restrict__ Ok,
                 const __nv_bfloat16* __restrict__ Wvh, const __nv_bfloat16* __restrict__ Wvm,
                 const float* __restrict__ Bv, float* __restrict__ Ov)
{
    const __nv_bfloat16 *Wh, *Wm; const float* bb; float* C;
    if (blockIdx.z == 0)      { Wh = Wqh; Wm = Wqm; bb = Bq; C = Oq; }
    else if (blockIdx.z == 1) { Wh = Wkh; Wm = Wkm; bb = Bk; C = Ok; }
    else                      { Wh = Wvh; Wm = Wvm; bb = Bv; C = Ov; }
    gemm_bf_body(Xh, Xm, Wh, Wm, bb, C);
}

__global__ __launch_bounds__(256)
void gemm_out_bf(const __nv_bfloat16* __restrict__ Ah, const __nv_bfloat16* __restrict__ Am,
                 const __nv_bfloat16* __restrict__ Wh, const __nv_bfloat16* __restrict__ Wm,
                 const float* __restrict__ bb, float* __restrict__ C)
{
    gemm_bf_body(Ah, Am, Wh, Wm, bb, C);
}

// ---------------------------------------------------------------------------
// RoPE + split: read fp32 q,k; write rotated values as bf16 hi/mid pairs.
// ---------------------------------------------------------------------------
__global__ void rope_split_kernel(const float* __restrict__ q, const float* __restrict__ k,
                                  __nv_bfloat16* __restrict__ qh, __nv_bfloat16* __restrict__ qm,
                                  __nv_bfloat16* __restrict__ kh, __nv_bfloat16* __restrict__ km)
{
    int idx = blockIdx.x * blockDim.x + threadIdx.x;
    if (idx >= ROWS * N_HEADS * 32) return;
    int i   = idx & 31;
    int h   = (idx >> 5) & (N_HEADS - 1);
    int row = idx >> 9;
    int t   = row & (SEQ - 1);

    float inv = 1.0f / powf(10000.0f, (float)(2 * i) * (1.0f / 64.0f));
    float ang = (float)t * inv;
    float sn, cs;
    sincosf(ang, &sn, &cs);

    int base = row * D_MODEL + h * HDIM + i;
    float q1 = q[base], q2 = q[base + 32];
    float k1 = k[base], k2 = k[base + 32];
    float qa = q1 * cs - q2 * sn;
    float qb = q2 * cs + q1 * sn;
    float ka = k1 * cs - k2 * sn;
    float kb = k2 * cs + k1 * sn;

    __nv_bfloat16 hv;
    hv = __float2bfloat16_rn(qa); qh[base]      = hv; qm[base]      = __float2bfloat16_rn(qa - __bfloat162float(hv));
    hv = __float2bfloat16_rn(qb); qh[base + 32] = hv; qm[base + 32] = __float2bfloat16_rn(qb - __bfloat162float(hv));
    hv = __float2bfloat16_rn(ka); kh[base]      = hv; km[base]      = __float2bfloat16_rn(ka - __bfloat162float(hv));
    hv = __float2bfloat16_rn(kb); kh[base + 32] = hv; km[base + 32] = __float2bfloat16_rn(kb - __bfloat162float(hv));
}

// ---------------------------------------------------------------------------
// V split + transpose: v fp32 [b*S+s][h*64+d] -> vT hi/mid bf16 [(bh*64)+d][s]
// ---------------------------------------------------------------------------
__global__ __launch_bounds__(256)
void v_split_t_kernel(const float* __restrict__ v,
                      __nv_bfloat16* __restrict__ vth, __nv_bfloat16* __restrict__ vtm)
{
    __shared__ __nv_bfloat16 th[64][66];
    __shared__ __nv_bfloat16 tm[64][66];
    const int tid = threadIdx.x;
    const int st  = blockIdx.x;
    const int bh  = blockIdx.y;
    const int b   = bh >> 4;
    const int h   = bh & 15;
    const int s0  = st * 64;

#pragma unroll
    for (int l = 0; l < 16; l++) {
        int e = l * 256 + tid;
        int r = e >> 6, d = e & 63;
        float x = v[(b * SEQ + s0 + r) * D_MODEL + h * HDIM + d];
        __nv_bfloat16 hv = __float2bfloat16_rn(x);
        th[d][r] = hv;
        tm[d][r] = __float2bfloat16_rn(x - __bfloat162float(hv));
    }
    __syncthreads();
#pragma unroll
    for (int l = 0; l < 16; l++) {
        int e = l * 256 + tid;
        int d = e >> 6, sc = e & 63;
        int o = (bh * HDIM + d) * SEQ + s0 + sc;
        vth[o] = th[d][sc];
        vtm[o] = tm[d][sc];
    }
}

// ---------------------------------------------------------------------------
// Flash attention, bf16x3 mma.sync (validated round 6).
// ---------------------------------------------------------------------------
#define NT       (SEQ / 64)
#define FL_QH    0
#define FL_QM    18432
#define FL_KH(s) (36864  + (s) * 9216)
#define FL_KM(s) (55296  + (s) * 9216)
#define FL_VH(s) (73728  + (s) * 9216)
#define FL_VM(s) (92160  + (s) * 9216)
#define FL_MS(s) (110592 + (s) * 256)
#define FA2_SMEM 111104

__global__ __launch_bounds__(256)
void flash2_kernel(const __nv_bfloat16* __restrict__ Qh, const __nv_bfloat16* __restrict__ Qm,
                   const __nv_bfloat16* __restrict__ Kh, const __nv_bfloat16* __restrict__ Km,
                   const __nv_bfloat16* __restrict__ Vth, const __nv_bfloat16* __restrict__ Vtm,
                   const float* __restrict__ mask, float* __restrict__ O)
{
    extern __shared__ char sm2[];
    const int tid  = threadIdx.x;
    const int w    = tid >> 5;
    const int lane = tid & 31;
    const int g    = lane >> 2;
    const int t    = lane & 3;
    const int qt   = blockIdx.x;
    const int bh   = blockIdx.y;
    const int b    = bh >> 4;
    const int h    = bh & 15;
    const uint32_t sbase = smem_u32(sm2);

    const __nv_bfloat16* qh_g = Qh + (b * SEQ + qt * 128) * D_MODEL + h * HDIM;
    const __nv_bfloat16* qm_g = Qm + (b * SEQ + qt * 128) * D_MODEL + h * HDIM;
    const __nv_bfloat16* kh_g = Kh + b * SEQ * D_MODEL + h * HDIM;
    const __nv_bfloat16* km_g = Km + b * SEQ * D_MODEL + h * HDIM;
    const __nv_bfloat16* vh_g = Vth + bh * HDIM * SEQ;
    const __nv_bfloat16* vm_g = Vtm + bh * HDIM * SEQ;
    const float* mask_g = mask + b * SEQ;

    auto stage = [&](int kt, int s) {
#pragma unroll
        for (int i = 0; i < 2; i++) {
            int idx = tid + i * 256;
            int r   = idx >> 3;
            int ch  = idx & 7;
            cp_async16(sbase + FL_KH(s) + r * 144 + ch * 16,
                       kh_g + (kt * 64 + r) * D_MODEL + ch * 8);
            cp_async16(sbase + FL_KM(s) + r * 144 + ch * 16,
                       km_g + (kt * 64 + r) * D_MODEL + ch * 8);
            cp_async16(sbase + FL_VH(s) + r * 144 + ch * 16,
                       vh_g + r * SEQ + kt * 64 + ch * 8);
            cp_async16(sbase + FL_VM(s) + r * 144 + ch * 16,
                       vm_g + r * SEQ + kt * 64 + ch * 8);
        }
        if (tid < 16)
            cp_async16(sbase + FL_MS(s) + tid * 16, mask_g + kt * 64 + tid * 4);
    };

#pragma unroll
    for (int i = 0; i < 4; i++) {
        int idx = tid + i * 256;
        int r   = idx >> 3;
        int ch  = idx & 7;
        cp_async16(sbase + FL_QH + r * 144 + ch * 16, qh_g + r * D_MODEL + ch * 8);
        cp_async16(sbase + FL_QM + r * 144 + ch * 16, qm_g + r * D_MODEL + ch * 8);
    }
    stage(0, 0);
    cp_commit();

    float o[8][4];
#pragma unroll
    for (int nf = 0; nf < 8; nf++)
#pragma unroll
        for (int j = 0; j < 4; j++) o[nf][j] = 0.0f;
    float m0 = -1e30f, m1 = -1e30f, l0 = 0.0f, l1 = 0.0f;

    const uint32_t qh_s = sbase + FL_QH + (w * 16 + g) * 144;
    const uint32_t qm_s = sbase + FL_QM + (w * 16 + g) * 144;

    for (int kt = 0; kt < NT; kt++) {
        const int s = kt & 1;
        if (kt + 1 < NT) { stage(kt + 1, s ^ 1); cp_commit(); cp_wait<1>(); }
        else             { cp_wait<0>(); }
        __syncthreads();

        float sc[8][4];
#pragma unroll
        for (int nf = 0; nf < 8; nf++)
#pragma unroll
            for (int j = 0; j < 4; j++) sc[nf][j] = 0.0f;

        const uint32_t kh_s = sbase + FL_KH(s) + g * 144;
        const uint32_t km_s = sbase + FL_KM(s) + g * 144;
#pragma unroll
        for (int ks = 0; ks < 4; ks++) {
            uint32_t ah[4], am[4];
            ah[0] = *(const uint32_t*)(sm2 + (qh_s - sbase) + (ks * 8 + t) * 4);
            ah[1] = *(const uint32_t*)(sm2 + (qh_s - sbase) + 8 * 144 + (ks * 8 + t) * 4);
            ah[2] = *(const uint32_t*)(sm2 + (qh_s - sbase) + (ks * 8 + t + 4) * 4);
            ah[3] = *(const uint32_t*)(sm2 + (qh_s - sbase) + 8 * 144 + (ks * 8 + t + 4) * 4);
            am[0] = *(const uint32_t*)(sm2 + (qm_s - sbase) + (ks * 8 + t) * 4);
            am[1] = *(const uint32_t*)(sm2 + (qm_s - sbase) + 8 * 144 + (ks * 8 + t) * 4);
            am[2] = *(const uint32_t*)(sm2 + (qm_s - sbase) + (ks * 8 + t + 4) * 4);
            am[3] = *(const uint32_t*)(sm2 + (qm_s - sbase) + 8 * 144 + (ks * 8 + t + 4) * 4);
#pragma unroll
            for (int nf = 0; nf < 8; nf++) {
                uint32_t bh2[2], bm2[2];
                bh2[0] = *(const uint32_t*)(sm2 + (kh_s - sbase) + nf * 8 * 144 + (ks * 8 + t) * 4);
                bh2[1] = *(const uint32_t*)(sm2 + (kh_s - sbase) + nf * 8 * 144 + (ks * 8 + t + 4) * 4);
                bm2[0] = *(const uint32_t*)(sm2 + (km_s - sbase) + nf * 8 * 144 + (ks * 8 + t) * 4);
                bm2[1] = *(const uint32_t*)(sm2 + (km_s - sbase) + nf * 8 * 144 + (ks * 8 + t + 4) * 4);
                mma_bf16(sc[nf], am, bh2);
                mma_bf16(sc[nf], ah, bm2);
                mma_bf16(sc[nf], ah, bh2);
            }
        }

        float rmax0 = -1e30f, rmax1 = -1e30f;
#pragma unroll
        for (int nf = 0; nf < 8; nf++) {
            float2 mk = *(const float2*)(sm2 + FL_MS(s) + (nf * 8 + 2 * t) * 4);
            sc[nf][0] = fmaf(sc[nf][0], 0.125f, mk.x);
            sc[nf][1] = fmaf(sc[nf][1], 0.125f, mk.y);
            sc[nf][2] = fmaf(sc[nf][2], 0.125f, mk.x);
            sc[nf][3] = fmaf(sc[nf][3], 0.125f, mk.y);
            rmax0 = fmaxf(rmax0, fmaxf(sc[nf][0], sc[nf][1]));
            rmax1 = fmaxf(rmax1, fmaxf(sc[nf][2], sc[nf][3]));
        }
        rmax0 = fmaxf(rmax0, __shfl_xor_sync(0xffffffffu, rmax0, 1));
        rmax0 = fmaxf(rmax0, __shfl_xor_sync(0xffffffffu, rmax0, 2));
        rmax1 = fmaxf(rmax1, __shfl_xor_sync(0xffffffffu, rmax1, 1));
        rmax1 = fmaxf(rmax1, __shfl_xor_sync(0xffffffffu, rmax1, 2));
        float mn0 = fmaxf(m0, rmax0), mn1 = fmaxf(m1, rmax1);
        float c0 = fast_exp(m0 - mn0), c1 = fast_exp(m1 - mn1);
        float sum0 = 0.0f, sum1 = 0.0f;
#pragma unroll
        for (int nf = 0; nf < 8; nf++) {
            sc[nf][0] = fast_exp(sc[nf][0] - mn0);
            sc[nf][1] = fast_exp(sc[nf][1] - mn0);
            sc[nf][2] = fast_exp(sc[nf][2] - mn1);
            sc[nf][3] = fast_exp(sc[nf][3] - mn1);
            sum0 += sc[nf][0] + sc[nf][1];
            sum1 += sc[nf][2] + sc[nf][3];
        }
        sum0 += __shfl_xor_sync(0xffffffffu, sum0, 1);
        sum0 += __shfl_xor_sync(0xffffffffu, sum0, 2);
        sum1 += __shfl_xor_sync(0xffffffffu, sum1, 1);
        sum1 += __shfl_xor_sync(0xffffffffu, sum1, 2);
        l0 = l0 * c0 + sum0;
        l1 = l1 * c1 + sum1;
        m0 = mn0; m1 = mn1;
#pragma unroll
        for (int nf = 0; nf < 8; nf++) {
            o[nf][0] *= c0; o[nf][1] *= c0;
            o[nf][2] *= c1; o[nf][3] *= c1;
        }

        const uint32_t vh_s = sbase + FL_VH(s) + g * 144;
        const uint32_t vm_s = sbase + FL_VM(s) + g * 144;
#pragma unroll
        for (int ks = 0; ks < 4; ks++) {
            uint32_t ph[4], pm[4];
            ph[0] = pack_bf16(sc[2 * ks][0],     sc[2 * ks][1]);
            ph[1] = pack_bf16(sc[2 * ks][2],     sc[2 * ks][3]);
            ph[2] = pack_bf16(sc[2 * ks + 1][0], sc[2 * ks + 1][1]);
            ph[3] = pack_bf16(sc[2 * ks + 1][2], sc[2 * ks + 1][3]);
            pm[0] = pack_bf16(sc[2 * ks][0]     - bf16lo_f(ph[0]), sc[2 * ks][1]     - bf16hi_f(ph[0]));
            pm[1] = pack_bf16(sc[2 * ks][2]     - bf16lo_f(ph[1]), sc[2 * ks][3]     - bf16hi_f(ph[1]));
            pm[2] = pack_bf16(sc[2 * ks + 1][0] - bf16lo_f(ph[2]), sc[2 * ks + 1][1] - bf16hi_f(ph[2]));
            pm[3] = pack_bf16(sc[2 * ks + 1][2] - bf16lo_f(ph[3]), sc[2 * ks + 1][3] - bf16hi_f(ph[3]));
#pragma unroll
            for (int nf = 0; nf < 8; nf++) {
                uint32_t bh2[2], bm2[2];
                bh2[0] = *(const uint32_t*)(sm2 + (vh_s - sbase) + nf * 8 * 144 + (ks * 8 + t) * 4);
                bh2[1] = *(const uint32_t*)(sm2 + (vh_s - sbase) + nf * 8 * 144 + (ks * 8 + t + 4) * 4);
                bm2[0] = *(const uint32_t*)(sm2 + (vm_s - sbase) + nf * 8 * 144 + (ks * 8 + t) * 4);
                bm2[1] = *(const uint32_t*)(sm2 + (vm_s - sbase) + nf * 8 * 144 + (ks * 8 + t + 4) * 4);
                mma_bf16(o[nf], pm, bh2);
                mma_bf16(o[nf], ph, bm2);
                mma_bf16(o[nf], ph, bh2);
            }
        }
        __syncthreads();
    }

    float i0 = 1.0f / l0, i1 = 1.0f / l1;
    float* Og = O + (b * SEQ + qt * 128 + w * 16 + g) * D_MODEL + h * HDIM;
#pragma unroll
    for (int nf = 0; nf < 8; nf++) {
        *(float2*)(Og + nf * 8 + 2 * t) =
            make_float2(o[nf][0] * i0, o[nf][1] * i0);
        *(float2*)(Og + 8 * D_MODEL + nf * 8 + 2 * t) =
            make_float2(o[nf][2] * i1, o[nf][3] * i1);
    }
}

// ---------------------------------------------------------------------------
// Launch
// ---------------------------------------------------------------------------
extern "C" void kernel_launch(void* const* d_in, const int* in_sizes, int n_in,
                              void* d_out, int out_size)
{
    const float* x    = (const float*)d_in[0];
    const float* wq   = (const float*)d_in[1];
    const float* bq   = (const float*)d_in[2];
    const float* wk   = (const float*)d_in[3];
    const float* bk   = (const float*)d_in[4];
    const float* wv   = (const float*)d_in[5];
    const float* bv   = (const float*)d_in[6];
    const float* wo   = (const float*)d_in[7];
    const float* bo   = (const float*)d_in[8];
    const float* mask = (const float*)d_in[9];
    float* out = (float*)d_out;

    float *q, *k, *v, *att;
    __nv_bfloat16 *qh, *qm, *kh, *km, *vth, *vtm;
    __nv_bfloat16 *xh, *xm, *ath, *atm;
    __nv_bfloat16 *wqh, *wqm, *wkh, *wkm, *wvh, *wvm, *woh, *wom;
    cudaGetSymbolAddress((void**)&q,   g_q);
    cudaGetSymbolAddress((void**)&k,   g_k);
    cudaGetSymbolAddress((void**)&v,   g_v);
    cudaGetSymbolAddress((void**)&att, g_att);
    cudaGetSymbolAddress((void**)&qh,  g_qh);
    cudaGetSymbolAddress((void**)&qm,  g_qm);
    cudaGetSymbolAddress((void**)&kh,  g_kh);
    cudaGetSymbolAddress((void**)&km,  g_km);
    cudaGetSymbolAddress((void**)&vth, g_vth);
    cudaGetSymbolAddress((void**)&vtm, g_vtm);
    cudaGetSymbolAddress((void**)&xh,  g_xh);
    cudaGetSymbolAddress((void**)&xm,  g_xm);
    cudaGetSymbolAddress((void**)&ath, g_ath);
    cudaGetSymbolAddress((void**)&atm, g_atm);
    cudaGetSymbolAddress((void**)&wqh, g_wqh);
    cudaGetSymbolAddress((void**)&wqm, g_wqm);
    cudaGetSymbolAddress((void**)&wkh, g_wkh);
    cudaGetSymbolAddress((void**)&wkm, g_wkm);
    cudaGetSymbolAddress((void**)&wvh, g_wvh);
    cudaGetSymbolAddress((void**)&wvm, g_wvm);
    cudaGetSymbolAddress((void**)&woh, g_woh);
    cudaGetSymbolAddress((void**)&wom, g_wom);

    cudaFuncSetAttribute(gemm_qkv_bf,
                         cudaFuncAttributeMaxDynamicSharedMemorySize, GEMM_SMEM2);
    cudaFuncSetAttribute(gemm_out_bf,
                         cudaFuncAttributeMaxDynamicSharedMemorySize, GEMM_SMEM2);
    cudaFuncSetAttribute(flash2_kernel,
                         cudaFuncAttributeMaxDynamicSharedMemorySize, FA2_SMEM);

    // Split prepasses (bf16 hi/mid)
    const int NX4 = ROWS * D_MODEL / 4;       // 1M
    const int NW4 = D_MODEL * D_MODEL / 4;    // 256K
    split_kernel<<<NX4 / 256, 256>>>(x,  xh,  xm,  NX4);
    split_kernel<<<NW4 / 256, 256>>>(wq, wqh, wqm, NW4);
    split_kernel<<<NW4 / 256, 256>>>(wk, wkh, wkm, NW4);
    split_kernel<<<NW4 / 256, 256>>>(wv, wvh, wvm, NW4);
    split_kernel<<<NW4 / 256, 256>>>(wo, woh, wom, NW4);

    // QKV projections (bf16x3 mma.sync)
    dim3 g1(D_MODEL / 128, ROWS / 128, 3);
    gemm_qkv_bf<<<g1, 256, GEMM_SMEM2>>>(xh, xm, wqh, wqm, bq, q,
                                         wkh, wkm, bk, k, wvh, wvm, bv, v);

    // RoPE + bf16 hi/mid split of q, k
    int rope_threads = ROWS * N_HEADS * 32;
    rope_split_kernel<<<rope_threads / 256, 256>>>(q, k, qh, qm, kh, km);

    // V split + transpose
    v_split_t_kernel<<<dim3(SEQ / 64, BATCH * N_HEADS), 256>>>(v, vth, vtm);

    // Flash attention (bf16x3 mma.sync)
    flash2_kernel<<<dim3(SEQ / 128, BATCH * N_HEADS), 256, FA2_SMEM>>>(
        qh, qm, kh, km, vth, vtm, mask, att);

    // att split + output projection (bf16x3) -> d_out
    split_kernel<<<NX4 / 256, 256>>>(att, ath, atm, NX4);
    dim3 g3(D_MODEL / 128, ROWS / 128);
    gemm_out_bf<<<g3, 256, GEMM_SMEM2>>>(ath, atm, woh, wom, bo, out);
}

// round 8
// speedup vs baseline: 3.1887x; 1.0158x over previous
#include <cuda_runtime.h>
#include <cuda_bf16.h>
#include <cstdint>
#include <math.h>

#define D_MODEL 1024
#define N_HEADS 16
#define HDIM    64
#define SEQ     2048
#define BATCH   2
#define ROWS    (BATCH * SEQ)   // 4096

// ---------------------------------------------------------------------------
// Scratch (static device globals — no allocation allowed)
// ---------------------------------------------------------------------------
__device__ float g_q[ROWS * D_MODEL];
__device__ float g_k[ROWS * D_MODEL];
__device__ float g_v[ROWS * D_MODEL];
__device__ __nv_bfloat16 g_qh[ROWS * D_MODEL];
__device__ __nv_bfloat16 g_qm[ROWS * D_MODEL];
__device__ __nv_bfloat16 g_kh[ROWS * D_MODEL];
__device__ __nv_bfloat16 g_km[ROWS * D_MODEL];
__device__ __nv_bfloat16 g_vth[BATCH * N_HEADS * HDIM * SEQ];  // [bh*64+d][s]
__device__ __nv_bfloat16 g_vtm[BATCH * N_HEADS * HDIM * SEQ];
__device__ __nv_bfloat16 g_xh[ROWS * D_MODEL];
__device__ __nv_bfloat16 g_xm[ROWS * D_MODEL];
__device__ __nv_bfloat16 g_ath[ROWS * D_MODEL];
__device__ __nv_bfloat16 g_atm[ROWS * D_MODEL];
__device__ __nv_bfloat16 g_wqh[D_MODEL * D_MODEL];
__device__ __nv_bfloat16 g_wqm[D_MODEL * D_MODEL];
__device__ __nv_bfloat16 g_wkh[D_MODEL * D_MODEL];
__device__ __nv_bfloat16 g_wkm[D_MODEL * D_MODEL];
__device__ __nv_bfloat16 g_wvh[D_MODEL * D_MODEL];
__device__ __nv_bfloat16 g_wvm[D_MODEL * D_MODEL];
__device__ __nv_bfloat16 g_woh[D_MODEL * D_MODEL];
__device__ __nv_bfloat16 g_wom[D_MODEL * D_MODEL];

// ---------------------------------------------------------------------------
// Helpers
// ---------------------------------------------------------------------------
__device__ __forceinline__ uint32_t smem_u32(const void* p) {
    uint32_t a;
    asm("{ .reg .u64 t; cvta.to.shared.u64 t, %1; cvt.u32.u64 %0, t; }"
        : "=r"(a) : "l"(p));
    return a;
}
__device__ __forceinline__ void cp_async16(uint32_t saddr, const void* gptr) {
    asm volatile("cp.async.cg.shared.global [%0], [%1], 16;"
                 :: "r"(saddr), "l"(gptr) : "memory");
}
__device__ __forceinline__ void cp_commit() {
    asm volatile("cp.async.commit_group;" ::: "memory");
}
template <int N>
__device__ __forceinline__ void cp_wait() {
    asm volatile("cp.async.wait_group %0;" :: "n"(N) : "memory");
}
__device__ __forceinline__ void mma_bf16(float* d, const uint32_t* a,
                                         const uint32_t* b) {
    asm volatile(
        "mma.sync.aligned.m16n8k16.row.col.f32.bf16.bf16.f32 "
        "{%0,%1,%2,%3}, {%4,%5,%6,%7}, {%8,%9}, {%0,%1,%2,%3};"
        : "+f"(d[0]), "+f"(d[1]), "+f"(d[2]), "+f"(d[3])
        : "r"(a[0]), "r"(a[1]), "r"(a[2]), "r"(a[3]), "r"(b[0]), "r"(b[1]));
}
__device__ __forceinline__ uint32_t pack_bf16(float lo, float hi) {
    uint32_t r;
    asm("cvt.rn.bf16x2.f32 %0, %1, %2;" : "=r"(r) : "f"(hi), "f"(lo));
    return r;
}
__device__ __forceinline__ float bf16lo_f(uint32_t w) { return __uint_as_float(w << 16); }
__device__ __forceinline__ float bf16hi_f(uint32_t w) { return __uint_as_float(w & 0xffff0000u); }

// FFMA-only exp, accurate ~1e-7 on [-87, 0]
__device__ __forceinline__ float fast_exp(float x) {
    x = fmaxf(x, -87.0f);
    float y = x * 1.4426950408889634f;
    float r = y + 12582912.0f;
    float n = r - 12582912.0f;
    float f = y - n;
    float t = f * 0.6931471805599453f;
    float p = 1.3888889e-3f;
    p = fmaf(p, t, 8.3333333e-3f);
    p = fmaf(p, t, 4.1666667e-2f);
    p = fmaf(p, t, 1.6666667e-1f);
    p = fmaf(p, t, 0.5f);
    p = fmaf(p, t, 1.0f);
    p = fmaf(p, t, 1.0f);
    int ni = __float_as_int(r) - 0x4B400000;
    float scale = __int_as_float((ni << 23) + 0x3F800000);
    return p * scale;
}

// ---------------------------------------------------------------------------
// Split prepass: fp32 -> bf16 hi + mid (residual). Vectorized by 4.
// ---------------------------------------------------------------------------
__global__ __launch_bounds__(256)
void split_kernel(const float* __restrict__ src,
                  __nv_bfloat16* __restrict__ h, __nv_bfloat16* __restrict__ m,
                  int n4)
{
    int i = blockIdx.x * blockDim.x + threadIdx.x;
    if (i >= n4) return;
    float4 x = *(const float4*)(src + i * 4);
    __nv_bfloat16 h0 = __float2bfloat16_rn(x.x);
    __nv_bfloat16 h1 = __float2bfloat16_rn(x.y);
    __nv_bfloat16 h2 = __float2bfloat16_rn(x.z);
    __nv_bfloat16 h3 = __float2bfloat16_rn(x.w);
    __nv_bfloat162* hp = (__nv_bfloat162*)(h + i * 4);
    hp[0] = __nv_bfloat162(h0, h1);
    hp[1] = __nv_bfloat162(h2, h3);
    __nv_bfloat162* mp = (__nv_bfloat162*)(m + i * 4);
    mp[0] = __nv_bfloat162(__float2bfloat16_rn(x.x - __bfloat162float(h0)),
                           __float2bfloat16_rn(x.y - __bfloat162float(h1)));
    mp[1] = __nv_bfloat162(__float2bfloat16_rn(x.z - __bfloat162float(h2)),
                           __float2bfloat16_rn(x.w - __bfloat162float(h3)));
}

// ---------------------------------------------------------------------------
// bf16x3 GEMM: C[M,N] = A[M,K] @ W[N,K]^T + bias[N]
// 128x128x32 CTA tile, 256 threads (8 warps as 2x4), warp tile 64x32.
// 3-stage cp.async ring, ONE __syncthreads per chunk.
// Smem: 16-word rows with XOR swizzle w ^= ((r>>1)&3)<<2 — conflict-free for
// 16B stores and 32-bit column fragment loads; no padding. Stage 32KB,
// 3 stages = 96KB -> 2 CTAs/SM.
// ---------------------------------------------------------------------------
#define BK2      32
#define NCH2     (D_MODEL / BK2)       // 32 chunks
#define TILE_W2  (128 * 16)            // 2048 words per tile
#define STAGE_W2 (4 * TILE_W2)         // Ah, Am, Bh, Bm = 8192 words (32KB)
#define GEMM_SMEM2 (3 * STAGE_W2 * 4)  // 98304 bytes

__device__ __forceinline__ int swz(int r, int w) {
    return r * 16 + (w ^ (((r >> 1) & 3) << 2));
}

__device__ __forceinline__ void stage_chunk2(
    const __nv_bfloat16* __restrict__ Ah, const __nv_bfloat16* __restrict__ Am,
    const __nv_bfloat16* __restrict__ Wh, const __nv_bfloat16* __restrict__ Wm,
    uint32_t sbase, int buf, int k0, int tid)
{
    const __nv_bfloat16* src[4] = { Ah, Am, Wh, Wm };
    uint32_t s0 = sbase + buf * STAGE_W2 * 4;
#pragma unroll
    for (int i = 0; i < 8; i++) {
        int idx  = tid + i * 256;         // 0..2047
        int tile = idx >> 9;              // 0..3
        int wi   = idx & 511;
        int r    = wi >> 2;               // row 0..127
        int ch   = wi & 3;                // 16B chunk (4 words)
        cp_async16(s0 + (tile * TILE_W2 + swz(r, ch * 4)) * 4,
                   src[tile] + r * D_MODEL + k0 + ch * 8);
    }
    cp_commit();
}

__device__ __forceinline__ void gemm_bf_body(
    const __nv_bfloat16* __restrict__ Ah, const __nv_bfloat16* __restrict__ Am,
    const __nv_bfloat16* __restrict__ Wh, const __nv_bfloat16* __restrict__ Wm,
    const float* __restrict__ bias, float* __restrict__ C)
{
    extern __shared__ uint32_t smw[];
    const uint32_t sbase = smem_u32(smw);
    const int tid  = threadIdx.x;
    const int wid  = tid >> 5;
    const int lane = tid & 31;
    const int wm   = (wid & 1) * 64;
    const int wn   = (wid >> 1) * 32;
    const int brow = blockIdx.y * 128;
    const int bcol = blockIdx.x * 128;
    const int g    = lane >> 2;
    const int t    = lane & 3;

    float acc[4][4][4];
#pragma unroll
    for (int mf = 0; mf < 4; mf++)
#pragma unroll
        for (int nf = 0; nf < 4; nf++)
#pragma unroll
            for (int r = 0; r < 4; r++) acc[mf][nf][r] = 0.0f;

    const __nv_bfloat16* Ah_r = Ah + brow * D_MODEL;
    const __nv_bfloat16* Am_r = Am + brow * D_MODEL;
    const __nv_bfloat16* Wh_r = Wh + bcol * D_MODEL;
    const __nv_bfloat16* Wm_r = Wm + bcol * D_MODEL;

    stage_chunk2(Ah_r, Am_r, Wh_r, Wm_r, sbase, 0, 0, tid);
    stage_chunk2(Ah_r, Am_r, Wh_r, Wm_r, sbase, 1, BK2, tid);

    int buf = 0;
    for (int c = 0; c < NCH2; c++) {
        if (c < NCH2 - 1) cp_wait<1>(); else cp_wait<0>();
        __syncthreads();
        if (c + 2 < NCH2) {
            int nb = buf + 2; if (nb >= 3) nb -= 3;
            stage_chunk2(Ah_r, Am_r, Wh_r, Wm_r, sbase, nb, (c + 2) * BK2, tid);
        }

        const uint32_t* S   = smw + buf * STAGE_W2;
        const uint32_t* sAh = S;
        const uint32_t* sAm = S + TILE_W2;
        const uint32_t* sBh = S + 2 * TILE_W2;
        const uint32_t* sBm = S + 3 * TILE_W2;

#pragma unroll
        for (int ks = 0; ks < 2; ks++) {
            const int kw = ks * 8 + t;
            uint32_t ah[4][4], am[4][4];
#pragma unroll
            for (int mf = 0; mf < 4; mf++) {
                int r0 = wm + mf * 16 + g;
                int sw = ((r0 >> 1) & 3) << 2;
                int i0 = r0 * 16 + (kw ^ sw);
                int i1 = (r0 + 8) * 16 + (kw ^ sw);
                int i2 = r0 * 16 + ((kw + 4) ^ sw);
                int i3 = (r0 + 8) * 16 + ((kw + 4) ^ sw);
                ah[mf][0] = sAh[i0]; ah[mf][1] = sAh[i1];
                ah[mf][2] = sAh[i2]; ah[mf][3] = sAh[i3];
                am[mf][0] = sAm[i0]; am[mf][1] = sAm[i1];
                am[mf][2] = sAm[i2]; am[mf][3] = sAm[i3];
            }
            uint32_t bh[4][2], bm[4][2];
#pragma unroll
            for (int nf = 0; nf < 4; nf++) {
                int rb = wn + nf * 8 + g;
                int sw = ((rb >> 1) & 3) << 2;
                int i0 = rb * 16 + (kw ^ sw);
                int i1 = rb * 16 + ((kw + 4) ^ sw);
                bh[nf][0] = sBh[i0]; bh[nf][1] = sBh[i1];
                bm[nf][0] = sBm[i0]; bm[nf][1] = sBm[i1];
            }
#pragma unroll
            for (int mf = 0; mf < 4; mf++)
#pragma unroll
                for (int nf = 0; nf < 4; nf++) {
                    mma_bf16(acc[mf][nf], am[mf], bh[nf]);
                    mma_bf16(acc[mf][nf], ah[mf], bm[nf]);
                    mma_bf16(acc[mf][nf], ah[mf], bh[nf]);
                }
        }
        buf++; if (buf >= 3) buf = 0;
    }

#pragma unroll
    for (int mf = 0; mf < 4; mf++) {
        int row0 = brow + wm + mf * 16 + g;
#pragma unroll
        for (int nf = 0; nf < 4; nf++) {
            int col = bcol + wn + nf * 8 + 2 * t;
            float b0 = bias[col], b1 = bias[col + 1];
            float2 v0 = make_float2(acc[mf][nf][0] + b0, acc[mf][nf][1] + b1);
            float2 v1 = make_float2(acc[mf][nf][2] + b0, acc[mf][nf][3] + b1);
            *(float2*)(C + row0 * D_MODEL + col)       = v0;
            *(float2*)(C + (row0 + 8) * D_MODEL + col) = v1;
        }
    }
}

__global__ __launch_bounds__(256)
void gemm_qkv_bf(const __nv_bfloat16* __restrict__ Xh, const __nv_bfloat16* __restrict__ Xm,
                 const __nv_bfloat16* __restrict__ Wqh, const __nv_bfloat16* __restrict__ Wqm,
                 const float* __restrict__ Bq, float* __restrict__ Oq,
                 const __nv_bfloat16* __restrict__ Wkh, const __nv_bfloat16* __restrict__ Wkm,
                 const float* __restrict__ Bk, float* __restrict__ Ok,
                 const __nv_bfloat16* __restrict__ Wvh, const __nv_bfloat16* __restrict__ Wvm,
                 const float* __restrict__ Bv, float* __restrict__ Ov)
{
    const __nv_bfloat16 *Wh, *Wm; const float* bb; float* C;
    if (blockIdx.z == 0)      { Wh = Wqh; Wm = Wqm; bb = Bq; C = Oq; }
    else if (blockIdx.z == 1) { Wh = Wkh; Wm = Wkm; bb = Bk; C = Ok; }
    else                      { Wh = Wvh; Wm = Wvm; bb = Bv; C = Ov; }
    gemm_bf_body(Xh, Xm, Wh, Wm, bb, C);
}

__global__ __launch_bounds__(256)
void gemm_out_bf(const __nv_bfloat16* __restrict__ Ah, const __nv_bfloat16* __restrict__ Am,
                 const __nv_bfloat16* __restrict__ Wh, const __nv_bfloat16* __restrict__ Wm,
                 const float* __restrict__ bb, float* __restrict__ C)
{
    gemm_bf_body(Ah, Am, Wh, Wm, bb, C);
}

// ---------------------------------------------------------------------------
// RoPE + split: read fp32 q,k; write rotated values as bf16 hi/mid pairs.
// ---------------------------------------------------------------------------
__global__ void rope_split_kernel(const float* __restrict__ q, const float* __restrict__ k,
                                  __nv_bfloat16* __restrict__ qh, __nv_bfloat16* __restrict__ qm,
                                  __nv_bfloat16* __restrict__ kh, __nv_bfloat16* __restrict__ km)
{
    int idx = blockIdx.x * blockDim.x + threadIdx.x;
    if (idx >= ROWS * N_HEADS * 32) return;
    int i   = idx & 31;
    int h   = (idx >> 5) & (N_HEADS - 1);
    int row = idx >> 9;
    int t   = row & (SEQ - 1);

    float inv = 1.0f / powf(10000.0f, (float)(2 * i) * (1.0f / 64.0f));
    float ang = (float)t * inv;
    float sn, cs;
    sincosf(ang, &sn, &cs);

    int base = row * D_MODEL + h * HDIM + i;
    float q1 = q[base], q2 = q[base + 32];
    float k1 = k[base], k2 = k[base + 32];
    float qa = q1 * cs - q2 * sn;
    float qb = q2 * cs + q1 * sn;
    float ka = k1 * cs - k2 * sn;
    float kb = k2 * cs + k1 * sn;

    __nv_bfloat16 hv;
    hv = __float2bfloat16_rn(qa); qh[base]      = hv; qm[base]      = __float2bfloat16_rn(qa - __bfloat162float(hv));
    hv = __float2bfloat16_rn(qb); qh[base + 32] = hv; qm[base + 32] = __float2bfloat16_rn(qb - __bfloat162float(hv));
    hv = __float2bfloat16_rn(ka); kh[base]      = hv; km[base]      = __float2bfloat16_rn(ka - __bfloat162float(hv));
    hv = __float2bfloat16_rn(kb); kh[base + 32] = hv; km[base + 32] = __float2bfloat16_rn(kb - __bfloat162float(hv));
}

// ---------------------------------------------------------------------------
// V split + transpose: v fp32 [b*S+s][h*64+d] -> vT hi/mid bf16 [(bh*64)+d][s]
// ---------------------------------------------------------------------------
__global__ __launch_bounds__(256)
void v_split_t_kernel(const float* __restrict__ v,
                      __nv_bfloat16* __restrict__ vth, __nv_bfloat16* __restrict__ vtm)
{
    __shared__ __nv_bfloat16 th[64][66];
    __shared__ __nv_bfloat16 tm[64][66];
    const int tid = threadIdx.x;
    const int st  = blockIdx.x;
    const int bh  = blockIdx.y;
    const int b   = bh >> 4;
    const int h   = bh & 15;
    const int s0  = st * 64;

#pragma unroll
    for (int l = 0; l < 16; l++) {
        int e = l * 256 + tid;
        int r = e >> 6, d = e & 63;
        float x = v[(b * SEQ + s0 + r) * D_MODEL + h * HDIM + d];
        __nv_bfloat16 hv = __float2bfloat16_rn(x);
        th[d][r] = hv;
        tm[d][r] = __float2bfloat16_rn(x - __bfloat162float(hv));
    }
    __syncthreads();
#pragma unroll
    for (int l = 0; l < 16; l++) {
        int e = l * 256 + tid;
        int d = e >> 6, sc = e & 63;
        int o = (bh * HDIM + d) * SEQ + s0 + sc;
        vth[o] = th[d][sc];
        vtm[o] = tm[d][sc];
    }
}

// ---------------------------------------------------------------------------
// Flash attention, bf16x3 mma.sync (validated). Epilogue now writes the
// bf16 hi/mid split of the output directly (feeds gemm_out_bf).
// ---------------------------------------------------------------------------
#define NT       (SEQ / 64)
#define FL_QH    0
#define FL_QM    18432
#define FL_KH(s) (36864  + (s) * 9216)
#define FL_KM(s) (55296  + (s) * 9216)
#define FL_VH(s) (73728  + (s) * 9216)
#define FL_VM(s) (92160  + (s) * 9216)
#define FL_MS(s) (110592 + (s) * 256)
#define FA2_SMEM 111104

__global__ __launch_bounds__(256)
void flash2_kernel(const __nv_bfloat16* __restrict__ Qh, const __nv_bfloat16* __restrict__ Qm,
                   const __nv_bfloat16* __restrict__ Kh, const __nv_bfloat16* __restrict__ Km,
                   const __nv_bfloat16* __restrict__ Vth, const __nv_bfloat16* __restrict__ Vtm,
                   const float* __restrict__ mask,
                   __nv_bfloat16* __restrict__ Oh, __nv_bfloat16* __restrict__ Om)
{
    extern __shared__ char sm2[];
    const int tid  = threadIdx.x;
    const int w    = tid >> 5;
    const int lane = tid & 31;
    const int g    = lane >> 2;
    const int t    = lane & 3;
    const int qt   = blockIdx.x;
    const int bh   = blockIdx.y;
    const int b    = bh >> 4;
    const int h    = bh & 15;
    const uint32_t sbase = smem_u32(sm2);

    const __nv_bfloat16* qh_g = Qh + (b * SEQ + qt * 128) * D_MODEL + h * HDIM;
    const __nv_bfloat16* qm_g = Qm + (b * SEQ + qt * 128) * D_MODEL + h * HDIM;
    const __nv_bfloat16* kh_g = Kh + b * SEQ * D_MODEL + h * HDIM;
    const __nv_bfloat16* km_g = Km + b * SEQ * D_MODEL + h * HDIM;
    const __nv_bfloat16* vh_g = Vth + bh * HDIM * SEQ;
    const __nv_bfloat16* vm_g = Vtm + bh * HDIM * SEQ;
    const float* mask_g = mask + b * SEQ;

    auto stage = [&](int kt, int s) {
#pragma unroll
        for (int i = 0; i < 2; i++) {
            int idx = tid + i * 256;
            int r   = idx >> 3;
            int ch  = idx & 7;
            cp_async16(sbase + FL_KH(s) + r * 144 + ch * 16,
                       kh_g + (kt * 64 + r) * D_MODEL + ch * 8);
            cp_async16(sbase + FL_KM(s) + r * 144 + ch * 16,
                       km_g + (kt * 64 + r) * D_MODEL + ch * 8);
            cp_async16(sbase + FL_VH(s) + r * 144 + ch * 16,
                       vh_g + r * SEQ + kt * 64 + ch * 8);
            cp_async16(sbase + FL_VM(s) + r * 144 + ch * 16,
                       vm_g + r * SEQ + kt * 64 + ch * 8);
        }
        if (tid < 16)
            cp_async16(sbase + FL_MS(s) + tid * 16, mask_g + kt * 64 + tid * 4);
    };

#pragma unroll
    for (int i = 0; i < 4; i++) {
        int idx = tid + i * 256;
        int r   = idx >> 3;
        int ch  = idx & 7;
        cp_async16(sbase + FL_QH + r * 144 + ch * 16, qh_g + r * D_MODEL + ch * 8);
        cp_async16(sbase + FL_QM + r * 144 + ch * 16, qm_g + r * D_MODEL + ch * 8);
    }
    stage(0, 0);
    cp_commit();

    float o[8][4];
#pragma unroll
    for (int nf = 0; nf < 8; nf++)
#pragma unroll
        for (int j = 0; j < 4; j++) o[nf][j] = 0.0f;
    float m0 = -1e30f, m1 = -1e30f, l0 = 0.0f, l1 = 0.0f;

    const uint32_t qh_s = sbase + FL_QH + (w * 16 + g) * 144;
    const uint32_t qm_s = sbase + FL_QM + (w * 16 + g) * 144;

    for (int kt = 0; kt < NT; kt++) {
        const int s = kt & 1;
        if (kt + 1 < NT) { stage(kt + 1, s ^ 1); cp_commit(); cp_wait<1>(); }
        else             { cp_wait<0>(); }
        __syncthreads();

        float sc[8][4];
#pragma unroll
        for (int nf = 0; nf < 8; nf++)
#pragma unroll
            for (int j = 0; j < 4; j++) sc[nf][j] = 0.0f;

        const uint32_t kh_s = sbase + FL_KH(s) + g * 144;
        const uint32_t km_s = sbase + FL_KM(s) + g * 144;
#pragma unroll
        for (int ks = 0; ks < 4; ks++) {
            uint32_t ah[4], am[4];
            ah[0] = *(const uint32_t*)(sm2 + (qh_s - sbase) + (ks * 8 + t) * 4);
            ah[1] = *(const uint32_t*)(sm2 + (qh_s - sbase) + 8 * 144 + (ks * 8 + t) * 4);
            ah[2] = *(const uint32_t*)(sm2 + (qh_s - sbase) + (ks * 8 + t + 4) * 4);
            ah[3] = *(const uint32_t*)(sm2 + (qh_s - sbase) + 8 * 144 + (ks * 8 + t + 4) * 4);
            am[0] = *(const uint32_t*)(sm2 + (qm_s - sbase) + (ks * 8 + t) * 4);
            am[1] = *(const uint32_t*)(sm2 + (qm_s - sbase) + 8 * 144 + (ks * 8 + t) * 4);
            am[2] = *(const uint32_t*)(sm2 + (qm_s - sbase) + (ks * 8 + t + 4) * 4);
            am[3] = *(const uint32_t*)(sm2 + (qm_s - sbase) + 8 * 144 + (ks * 8 + t + 4) * 4);
#pragma unroll
            for (int nf = 0; nf < 8; nf++) {
                uint32_t bh2[2], bm2[2];
                bh2[0] = *(const uint32_t*)(sm2 + (kh_s - sbase) + nf * 8 * 144 + (ks * 8 + t) * 4);
                bh2[1] = *(const uint32_t*)(sm2 + (kh_s - sbase) + nf * 8 * 144 + (ks * 8 + t + 4) * 4);
                bm2[0] = *(const uint32_t*)(sm2 + (km_s - sbase) + nf * 8 * 144 + (ks * 8 + t) * 4);
                bm2[1] = *(const uint32_t*)(sm2 + (km_s - sbase) + nf * 8 * 144 + (ks * 8 + t + 4) * 4);
                mma_bf16(sc[nf], am, bh2);
                mma_bf16(sc[nf], ah, bm2);
                mma_bf16(sc[nf], ah, bh2);
            }
        }

        float rmax0 = -1e30f, rmax1 = -1e30f;
#pragma unroll
        for (int nf = 0; nf < 8; nf++) {
            float2 mk = *(const float2*)(sm2 + FL_MS(s) + (nf * 8 + 2 * t) * 4);
            sc[nf][0] = fmaf(sc[nf][0], 0.125f, mk.x);
            sc[nf][1] = fmaf(sc[nf][1], 0.125f, mk.y);
            sc[nf][2] = fmaf(sc[nf][2], 0.125f, mk.x);
            sc[nf][3] = fmaf(sc[nf][3], 0.125f, mk.y);
            rmax0 = fmaxf(rmax0, fmaxf(sc[nf][0], sc[nf][1]));
            rmax1 = fmaxf(rmax1, fmaxf(sc[nf][2], sc[nf][3]));
        }
        rmax0 = fmaxf(rmax0, __shfl_xor_sync(0xffffffffu, rmax0, 1));
        rmax0 = fmaxf(rmax0, __shfl_xor_sync(0xffffffffu, rmax0, 2));
        rmax1 = fmaxf(rmax1, __shfl_xor_sync(0xffffffffu, rmax1, 1));
        rmax1 = fmaxf(rmax1, __shfl_xor_sync(0xffffffffu, rmax1, 2));
        float mn0 = fmaxf(m0, rmax0), mn1 = fmaxf(m1, rmax1);
        float c0 = fast_exp(m0 - mn0), c1 = fast_exp(m1 - mn1);
        float sum0 = 0.0f, sum1 = 0.0f;
#pragma unroll
        for (int nf = 0; nf < 8; nf++) {
            sc[nf][0] = fast_exp(sc[nf][0] - mn0);
            sc[nf][1] = fast_exp(sc[nf][1] - mn0);
            sc[nf][2] = fast_exp(sc[nf][2] - mn1);
            sc[nf][3] = fast_exp(sc[nf][3] - mn1);
            sum0 += sc[nf][0] + sc[nf][1];
            sum1 += sc[nf][2] + sc[nf][3];
        }
        sum0 += __shfl_xor_sync(0xffffffffu, sum0, 1);
        sum0 += __shfl_xor_sync(0xffffffffu, sum0, 2);
        sum1 += __shfl_xor_sync(0xffffffffu, sum1, 1);
        sum1 += __shfl_xor_sync(0xffffffffu, sum1, 2);
        l0 = l0 * c0 + sum0;
        l1 = l1 * c1 + sum1;
        m0 = mn0; m1 = mn1;
#pragma unroll
        for (int nf = 0; nf < 8; nf++) {
            o[nf][0] *= c0; o[nf][1] *= c0;
            o[nf][2] *= c1; o[nf][3] *= c1;
        }

        const uint32_t vh_s = sbase + FL_VH(s) + g * 144;
        const uint32_t vm_s = sbase + FL_VM(s) + g * 144;
#pragma unroll
        for (int ks = 0; ks < 4; ks++) {
            uint32_t ph[4], pm[4];
            ph[0] = pack_bf16(sc[2 * ks][0],     sc[2 * ks][1]);
            ph[1] = pack_bf16(sc[2 * ks][2],     sc[2 * ks][3]);
            ph[2] = pack_bf16(sc[2 * ks + 1][0], sc[2 * ks + 1][1]);
            ph[3] = pack_bf16(sc[2 * ks + 1][2], sc[2 * ks + 1][3]);
            pm[0] = pack_bf16(sc[2 * ks][0]     - bf16lo_f(ph[0]), sc[2 * ks][1]     - bf16hi_f(ph[0]));
            pm[1] = pack_bf16(sc[2 * ks][2]     - bf16lo_f(ph[1]), sc[2 * ks][3]     - bf16hi_f(ph[1]));
            pm[2] = pack_bf16(sc[2 * ks + 1][0] - bf16lo_f(ph[2]), sc[2 * ks + 1][1] - bf16hi_f(ph[2]));
            pm[3] = pack_bf16(sc[2 * ks + 1][2] - bf16lo_f(ph[3]), sc[2 * ks + 1][3] - bf16hi_f(ph[3]));
#pragma unroll
            for (int nf = 0; nf < 8; nf++) {
                uint32_t bh2[2], bm2[2];
                bh2[0] = *(const uint32_t*)(sm2 + (vh_s - sbase) + nf * 8 * 144 + (ks * 8 + t) * 4);
                bh2[1] = *(const uint32_t*)(sm2 + (vh_s - sbase) + nf * 8 * 144 + (ks * 8 + t + 4) * 4);
                bm2[0] = *(const uint32_t*)(sm2 + (vm_s - sbase) + nf * 8 * 144 + (ks * 8 + t) * 4);
                bm2[1] = *(const uint32_t*)(sm2 + (vm_s - sbase) + nf * 8 * 144 + (ks * 8 + t + 4) * 4);
                mma_bf16(o[nf], pm, bh2);
                mma_bf16(o[nf], ph, bm2);
                mma_bf16(o[nf], ph, bh2);
            }
        }
        __syncthreads();
    }

    // Epilogue: write bf16 hi/mid split directly (consumed by gemm_out_bf)
    float i0 = 1.0f / l0, i1 = 1.0f / l1;
    int row0 = b * SEQ + qt * 128 + w * 16 + g;
    int colb = h * HDIM + 2 * t;
#pragma unroll
    for (int nf = 0; nf < 8; nf++) {
        float v0 = o[nf][0] * i0, v1 = o[nf][1] * i0;
        float v2 = o[nf][2] * i1, v3 = o[nf][3] * i1;
        uint32_t hw0 = pack_bf16(v0, v1);
        uint32_t hw1 = pack_bf16(v2, v3);
        uint32_t mw0 = pack_bf16(v0 - bf16lo_f(hw0), v1 - bf16hi_f(hw0));
        uint32_t mw1 = pack_bf16(v2 - bf16lo_f(hw1), v3 - bf16hi_f(hw1));
        int off0 = row0 * D_MODEL + colb + nf * 8;
        int off1 = (row0 + 8) * D_MODEL + colb + nf * 8;
        *(uint32_t*)(Oh + off0) = hw0;
        *(uint32_t*)(Om + off0) = mw0;
        *(uint32_t*)(Oh + off1) = hw1;
        *(uint32_t*)(Om + off1) = mw1;
    }
}

// ---------------------------------------------------------------------------
// Launch
// ---------------------------------------------------------------------------
extern "C" void kernel_launch(void* const* d_in, const int* in_sizes, int n_in,
                              void* d_out, int out_size)
{
    const float* x    = (const float*)d_in[0];
    const float* wq   = (const float*)d_in[1];
    const float* bq   = (const float*)d_in[2];
    const float* wk   = (const float*)d_in[3];
    const float* bk   = (const float*)d_in[4];
    const float* wv   = (const float*)d_in[5];
    const float* bv   = (const float*)d_in[6];
    const float* wo   = (const float*)d_in[7];
    const float* bo   = (const float*)d_in[8];
    const float* mask = (const float*)d_in[9];
    float* out = (float*)d_out;

    float *q, *k, *v;
    __nv_bfloat16 *qh, *qm, *kh, *km, *vth, *vtm;
    __nv_bfloat16 *xh, *xm, *ath, *atm;
    __nv_bfloat16 *wqh, *wqm, *wkh, *wkm, *wvh, *wvm, *woh, *wom;
    cudaGetSymbolAddress((void**)&q,   g_q);
    cudaGetSymbolAddress((void**)&k,   g_k);
    cudaGetSymbolAddress((void**)&v,   g_v);
    cudaGetSymbolAddress((void**)&qh,  g_qh);
    cudaGetSymbolAddress((void**)&qm,  g_qm);
    cudaGetSymbolAddress((void**)&kh,  g_kh);
    cudaGetSymbolAddress((void**)&km,  g_km);
    cudaGetSymbolAddress((void**)&vth, g_vth);
    cudaGetSymbolAddress((void**)&vtm, g_vtm);
    cudaGetSymbolAddress((void**)&xh,  g_xh);
    cudaGetSymbolAddress((void**)&xm,  g_xm);
    cudaGetSymbolAddress((void**)&ath, g_ath);
    cudaGetSymbolAddress((void**)&atm, g_atm);
    cudaGetSymbolAddress((void**)&wqh, g_wqh);
    cudaGetSymbolAddress((void**)&wqm, g_wqm);
    cudaGetSymbolAddress((void**)&wkh, g_wkh);
    cudaGetSymbolAddress((void**)&wkm, g_wkm);
    cudaGetSymbolAddress((void**)&wvh, g_wvh);
    cudaGetSymbolAddress((void**)&wvm, g_wvm);
    cudaGetSymbolAddress((void**)&woh, g_woh);
    cudaGetSymbolAddress((void**)&wom, g_wom);

    cudaFuncSetAttribute(gemm_qkv_bf,
                         cudaFuncAttributeMaxDynamicSharedMemorySize, GEMM_SMEM2);
    cudaFuncSetAttribute(gemm_out_bf,
                         cudaFuncAttributeMaxDynamicSharedMemorySize, GEMM_SMEM2);
    cudaFuncSetAttribute(flash2_kernel,
                         cudaFuncAttributeMaxDynamicSharedMemorySize, FA2_SMEM);

    // Split prepasses (bf16 hi/mid)
    const int NX4 = ROWS * D_MODEL / 4;       // 1M
    const int NW4 = D_MODEL * D_MODEL / 4;    // 256K
    split_kernel<<<NX4 / 256, 256>>>(x,  xh,  xm,  NX4);
    split_kernel<<<NW4 / 256, 256>>>(wq, wqh, wqm, NW4);
    split_kernel<<<NW4 / 256, 256>>>(wk, wkh, wkm, NW4);
    split_kernel<<<NW4 / 256, 256>>>(wv, wvh, wvm, NW4);
    split_kernel<<<NW4 / 256, 256>>>(wo, woh, wom, NW4);

    // QKV projections (bf16x3 mma.sync, 3-stage ring)
    dim3 g1(D_MODEL / 128, ROWS / 128, 3);
    gemm_qkv_bf<<<g1, 256, GEMM_SMEM2>>>(xh, xm, wqh, wqm, bq, q,
                                         wkh, wkm, bk, k, wvh, wvm, bv, v);

    // RoPE + bf16 hi/mid split of q, k
    int rope_threads = ROWS * N_HEADS * 32;
    rope_split_kernel<<<rope_threads / 256, 256>>>(q, k, qh, qm, kh, km);

    // V split + transpose
    v_split_t_kernel<<<dim3(SEQ / 64, BATCH * N_HEADS), 256>>>(v, vth, vtm);

    // Flash attention (bf16x3) — writes split output directly
    flash2_kernel<<<dim3(SEQ / 128, BATCH * N_HEADS), 256, FA2_SMEM>>>(
        qh, qm, kh, km, vth, vtm, mask, ath, atm);

    // Output projection (bf16x3) -> d_out
    dim3 g3(D_MODEL / 128, ROWS / 128);
    gemm_out_bf<<<g3, 256, GEMM_SMEM2>>>(ath, atm, woh, wom, bo, out);
}

// round 9
// speedup vs baseline: 3.2472x; 1.0184x over previous
#include <cuda_runtime.h>
#include <cuda_bf16.h>
#include <cstdint>
#include <math.h>

#define D_MODEL 1024
#define N_HEADS 16
#define HDIM    64
#define SEQ     2048
#define BATCH   2
#define ROWS    (BATCH * SEQ)   // 4096

// ---------------------------------------------------------------------------
// Scratch (static device globals — no allocation allowed)
// ---------------------------------------------------------------------------
__device__ float g_q[ROWS * D_MODEL];
__device__ float g_k[ROWS * D_MODEL];
__device__ float g_v[ROWS * D_MODEL];
__device__ __nv_bfloat16 g_qh[ROWS * D_MODEL];
__device__ __nv_bfloat16 g_qm[ROWS * D_MODEL];
__device__ __nv_bfloat16 g_kh[ROWS * D_MODEL];
__device__ __nv_bfloat16 g_km[ROWS * D_MODEL];
__device__ __nv_bfloat16 g_vth[BATCH * N_HEADS * HDIM * SEQ];  // [bh*64+d][s]
__device__ __nv_bfloat16 g_vtm[BATCH * N_HEADS * HDIM * SEQ];
__device__ __nv_bfloat16 g_xh[ROWS * D_MODEL];
__device__ __nv_bfloat16 g_xm[ROWS * D_MODEL];
__device__ __nv_bfloat16 g_ath[ROWS * D_MODEL];
__device__ __nv_bfloat16 g_atm[ROWS * D_MODEL];
__device__ __nv_bfloat16 g_wqh[D_MODEL * D_MODEL];
__device__ __nv_bfloat16 g_wqm[D_MODEL * D_MODEL];
__device__ __nv_bfloat16 g_wkh[D_MODEL * D_MODEL];
__device__ __nv_bfloat16 g_wkm[D_MODEL * D_MODEL];
__device__ __nv_bfloat16 g_wvh[D_MODEL * D_MODEL];
__device__ __nv_bfloat16 g_wvm[D_MODEL * D_MODEL];
__device__ __nv_bfloat16 g_woh[D_MODEL * D_MODEL];
__device__ __nv_bfloat16 g_wom[D_MODEL * D_MODEL];

// ---------------------------------------------------------------------------
// Helpers
// ---------------------------------------------------------------------------
__device__ __forceinline__ uint32_t smem_u32(const void* p) {
    uint32_t a;
    asm("{ .reg .u64 t; cvta.to.shared.u64 t, %1; cvt.u32.u64 %0, t; }"
        : "=r"(a) : "l"(p));
    return a;
}
__device__ __forceinline__ void cp_async16(uint32_t saddr, const void* gptr) {
    asm volatile("cp.async.cg.shared.global [%0], [%1], 16;"
                 :: "r"(saddr), "l"(gptr) : "memory");
}
__device__ __forceinline__ void cp_commit() {
    asm volatile("cp.async.commit_group;" ::: "memory");
}
template <int N>
__device__ __forceinline__ void cp_wait() {
    asm volatile("cp.async.wait_group %0;" :: "n"(N) : "memory");
}
__device__ __forceinline__ void mma_bf16(float* d, const uint32_t* a,
                                         const uint32_t* b) {
    asm volatile(
        "mma.sync.aligned.m16n8k16.row.col.f32.bf16.bf16.f32 "
        "{%0,%1,%2,%3}, {%4,%5,%6,%7}, {%8,%9}, {%0,%1,%2,%3};"
        : "+f"(d[0]), "+f"(d[1]), "+f"(d[2]), "+f"(d[3])
        : "r"(a[0]), "r"(a[1]), "r"(a[2]), "r"(a[3]), "r"(b[0]), "r"(b[1]));
}
// ldmatrix x4: loads 4 8x8 b16 matrices; lane L supplies the address of
// row (L%16) / column-half (L/16) per the standard fragment mapping.
__device__ __forceinline__ void ldsm4(uint32_t* r, uint32_t addr) {
    asm volatile("ldmatrix.sync.aligned.m8n8.x4.shared.b16 {%0,%1,%2,%3}, [%4];"
                 : "=r"(r[0]), "=r"(r[1]), "=r"(r[2]), "=r"(r[3]) : "r"(addr));
}
__device__ __forceinline__ uint32_t pack_bf16(float lo, float hi) {
    uint32_t r;
    asm("cvt.rn.bf16x2.f32 %0, %1, %2;" : "=r"(r) : "f"(hi), "f"(lo));
    return r;
}
__device__ __forceinline__ float bf16lo_f(uint32_t w) { return __uint_as_float(w << 16); }
__device__ __forceinline__ float bf16hi_f(uint32_t w) { return __uint_as_float(w & 0xffff0000u); }

// FFMA-only exp, accurate ~1e-7 on [-87, 0]
__device__ __forceinline__ float fast_exp(float x) {
    x = fmaxf(x, -87.0f);
    float y = x * 1.4426950408889634f;
    float r = y + 12582912.0f;
    float n = r - 12582912.0f;
    float f = y - n;
    float t = f * 0.6931471805599453f;
    float p = 1.3888889e-3f;
    p = fmaf(p, t, 8.3333333e-3f);
    p = fmaf(p, t, 4.1666667e-2f);
    p = fmaf(p, t, 1.6666667e-1f);
    p = fmaf(p, t, 0.5f);
    p = fmaf(p, t, 1.0f);
    p = fmaf(p, t, 1.0f);
    int ni = __float_as_int(r) - 0x4B400000;
    float scale = __int_as_float((ni << 23) + 0x3F800000);
    return p * scale;
}

// ---------------------------------------------------------------------------
// Split prepass: fp32 -> bf16 hi + mid (residual). Vectorized by 4.
// ---------------------------------------------------------------------------
__global__ __launch_bounds__(256)
void split_kernel(const float* __restrict__ src,
                  __nv_bfloat16* __restrict__ h, __nv_bfloat16* __restrict__ m,
                  int n4)
{
    int i = blockIdx.x * blockDim.x + threadIdx.x;
    if (i >= n4) return;
    float4 x = *(const float4*)(src + i * 4);
    __nv_bfloat16 h0 = __float2bfloat16_rn(x.x);
    __nv_bfloat16 h1 = __float2bfloat16_rn(x.y);
    __nv_bfloat16 h2 = __float2bfloat16_rn(x.z);
    __nv_bfloat16 h3 = __float2bfloat16_rn(x.w);
    __nv_bfloat162* hp = (__nv_bfloat162*)(h + i * 4);
    hp[0] = __nv_bfloat162(h0, h1);
    hp[1] = __nv_bfloat162(h2, h3);
    __nv_bfloat162* mp = (__nv_bfloat162*)(m + i * 4);
    mp[0] = __nv_bfloat162(__float2bfloat16_rn(x.x - __bfloat162float(h0)),
                           __float2bfloat16_rn(x.y - __bfloat162float(h1)));
    mp[1] = __nv_bfloat162(__float2bfloat16_rn(x.z - __bfloat162float(h2)),
                           __float2bfloat16_rn(x.w - __bfloat162float(h3)));
}

// ---------------------------------------------------------------------------
// bf16x3 GEMM with ldmatrix fragment loads.
// 128x128x32 CTA tile, 256 threads (8 warps as 2x4), warp tile 64x32.
// 3-stage cp.async ring, one __syncthreads per chunk. XOR-swizzled smem.
// ---------------------------------------------------------------------------
#define BK2      32
#define NCH2     (D_MODEL / BK2)       // 32 chunks
#define TILE_W2  (128 * 16)            // 2048 words per tile
#define STAGE_W2 (4 * TILE_W2)         // Ah, Am, Bh, Bm = 8192 words (32KB)
#define GEMM_SMEM2 (3 * STAGE_W2 * 4)  // 98304 bytes
#define TILE_B2  (TILE_W2 * 4)         // tile bytes

__device__ __forceinline__ int swz(int r, int w) {
    return r * 16 + (w ^ (((r >> 1) & 3) << 2));
}

__device__ __forceinline__ void stage_chunk2(
    const __nv_bfloat16* __restrict__ Ah, const __nv_bfloat16* __restrict__ Am,
    const __nv_bfloat16* __restrict__ Wh, const __nv_bfloat16* __restrict__ Wm,
    uint32_t sbase, int buf, int k0, int tid)
{
    const __nv_bfloat16* src[4] = { Ah, Am, Wh, Wm };
    uint32_t s0 = sbase + buf * STAGE_W2 * 4;
#pragma unroll
    for (int i = 0; i < 8; i++) {
        int idx  = tid + i * 256;         // 0..2047
        int tile = idx >> 9;              // 0..3
        int wi   = idx & 511;
        int r    = wi >> 2;               // row 0..127
        int ch   = wi & 3;                // 16B chunk (4 words)
        cp_async16(s0 + (tile * TILE_W2 + swz(r, ch * 4)) * 4,
                   src[tile] + r * D_MODEL + k0 + ch * 8);
    }
    cp_commit();
}

__device__ __forceinline__ void gemm_bf_body(
    const __nv_bfloat16* __restrict__ Ah, const __nv_bfloat16* __restrict__ Am,
    const __nv_bfloat16* __restrict__ Wh, const __nv_bfloat16* __restrict__ Wm,
    const float* __restrict__ bias, float* __restrict__ C)
{
    extern __shared__ uint32_t smw[];
    const uint32_t sbase = smem_u32(smw);
    const int tid  = threadIdx.x;
    const int wid  = tid >> 5;
    const int lane = tid & 31;
    const int wm   = (wid & 1) * 64;
    const int wn   = (wid >> 1) * 32;
    const int brow = blockIdx.y * 128;
    const int bcol = blockIdx.x * 128;
    const int g    = lane >> 2;
    const int t    = lane & 3;
    const int lrow16 = lane & 15;
    const int lrow8  = lane & 7;
    const int half   = lane >> 4;          // 0/1
    const int midbit = (lane >> 3) & 1;

    // Precomputed ldmatrix byte offsets (relative to stage base)
    uint32_t aoff[4][2], boff[2][2];
#pragma unroll
    for (int mf = 0; mf < 4; mf++)
#pragma unroll
        for (int ks = 0; ks < 2; ks++) {
            int row = wm + mf * 16 + lrow16;
            int ch  = ks * 2 + half;
            aoff[mf][ks] = (uint32_t)((row * 16 +
                ((ch * 4) ^ (((row >> 1) & 3) << 2))) * 4);
        }
#pragma unroll
    for (int p = 0; p < 2; p++)
#pragma unroll
        for (int ks = 0; ks < 2; ks++) {
            int row = wn + (2 * p + half) * 8 + lrow8;
            int ch  = ks * 2 + midbit;
            boff[p][ks] = (uint32_t)((row * 16 +
                ((ch * 4) ^ (((row >> 1) & 3) << 2))) * 4);
        }

    float acc[4][4][4];
#pragma unroll
    for (int mf = 0; mf < 4; mf++)
#pragma unroll
        for (int nf = 0; nf < 4; nf++)
#pragma unroll
            for (int r = 0; r < 4; r++) acc[mf][nf][r] = 0.0f;

    const __nv_bfloat16* Ah_r = Ah + brow * D_MODEL;
    const __nv_bfloat16* Am_r = Am + brow * D_MODEL;
    const __nv_bfloat16* Wh_r = Wh + bcol * D_MODEL;
    const __nv_bfloat16* Wm_r = Wm + bcol * D_MODEL;

    stage_chunk2(Ah_r, Am_r, Wh_r, Wm_r, sbase, 0, 0, tid);
    stage_chunk2(Ah_r, Am_r, Wh_r, Wm_r, sbase, 1, BK2, tid);

    int buf = 0;
    for (int c = 0; c < NCH2; c++) {
        if (c < NCH2 - 1) cp_wait<1>(); else cp_wait<0>();
        __syncthreads();
        if (c + 2 < NCH2) {
            int nb = buf + 2; if (nb >= 3) nb -= 3;
            stage_chunk2(Ah_r, Am_r, Wh_r, Wm_r, sbase, nb, (c + 2) * BK2, tid);
        }

        const uint32_t sb0 = sbase + buf * (STAGE_W2 * 4);

#pragma unroll
        for (int ks = 0; ks < 2; ks++) {
            uint32_t ah[4][4], am[4][4];
#pragma unroll
            for (int mf = 0; mf < 4; mf++) {
                ldsm4(ah[mf], sb0 + aoff[mf][ks]);
                ldsm4(am[mf], sb0 + TILE_B2 + aoff[mf][ks]);
            }
#pragma unroll
            for (int p = 0; p < 2; p++) {
                uint32_t bh4[4], bm4[4];
                ldsm4(bh4, sb0 + 2 * TILE_B2 + boff[p][ks]);
                ldsm4(bm4, sb0 + 3 * TILE_B2 + boff[p][ks]);
#pragma unroll
                for (int qq = 0; qq < 2; qq++) {
                    const int nf = 2 * p + qq;
                    uint32_t bh[2] = { bh4[2 * qq], bh4[2 * qq + 1] };
                    uint32_t bm[2] = { bm4[2 * qq], bm4[2 * qq + 1] };
#pragma unroll
                    for (int mf = 0; mf < 4; mf++) {
                        mma_bf16(acc[mf][nf], am[mf], bh);
                        mma_bf16(acc[mf][nf], ah[mf], bm);
                        mma_bf16(acc[mf][nf], ah[mf], bh);
                    }
                }
            }
        }
        buf++; if (buf >= 3) buf = 0;
    }

#pragma unroll
    for (int mf = 0; mf < 4; mf++) {
        int row0 = brow + wm + mf * 16 + g;
#pragma unroll
        for (int nf = 0; nf < 4; nf++) {
            int col = bcol + wn + nf * 8 + 2 * t;
            float b0 = bias[col], b1 = bias[col + 1];
            float2 v0 = make_float2(acc[mf][nf][0] + b0, acc[mf][nf][1] + b1);
            float2 v1 = make_float2(acc[mf][nf][2] + b0, acc[mf][nf][3] + b1);
            *(float2*)(C + row0 * D_MODEL + col)       = v0;
            *(float2*)(C + (row0 + 8) * D_MODEL + col) = v1;
        }
    }
}

__global__ __launch_bounds__(256)
void gemm_qkv_bf(const __nv_bfloat16* __restrict__ Xh, const __nv_bfloat16* __restrict__ Xm,
                 const __nv_bfloat16* __restrict__ Wqh, const __nv_bfloat16* __restrict__ Wqm,
                 const float* __restrict__ Bq, float* __restrict__ Oq,
                 const __nv_bfloat16* __restrict__ Wkh, const __nv_bfloat16* __restrict__ Wkm,
                 const float* __restrict__ Bk, float* __restrict__ Ok,
                 const __nv_bfloat16* __restrict__ Wvh, const __nv_bfloat16* __restrict__ Wvm,
                 const float* __restrict__ Bv, float* __restrict__ Ov)
{
    const __nv_bfloat16 *Wh, *Wm; const float* bb; float* C;
    if (blockIdx.z == 0)      { Wh = Wqh; Wm = Wqm; bb = Bq; C = Oq; }
    else if (blockIdx.z == 1) { Wh = Wkh; Wm = Wkm; bb = Bk; C = Ok; }
    else                      { Wh = Wvh; Wm = Wvm; bb = Bv; C = Ov; }
    gemm_bf_body(Xh, Xm, Wh, Wm, bb, C);
}

__global__ __launch_bounds__(256)
void gemm_out_bf(const __nv_bfloat16* __restrict__ Ah, const __nv_bfloat16* __restrict__ Am,
                 const __nv_bfloat16* __restrict__ Wh, const __nv_bfloat16* __restrict__ Wm,
                 const float* __restrict__ bb, float* __restrict__ C)
{
    gemm_bf_body(Ah, Am, Wh, Wm, bb, C);
}

// ---------------------------------------------------------------------------
// RoPE + split
// ---------------------------------------------------------------------------
__global__ void rope_split_kernel(const float* __restrict__ q, const float* __restrict__ k,
                                  __nv_bfloat16* __restrict__ qh, __nv_bfloat16* __restrict__ qm,
                                  __nv_bfloat16* __restrict__ kh, __nv_bfloat16* __restrict__ km)
{
    int idx = blockIdx.x * blockDim.x + threadIdx.x;
    if (idx >= ROWS * N_HEADS * 32) return;
    int i   = idx & 31;
    int h   = (idx >> 5) & (N_HEADS - 1);
    int row = idx >> 9;
    int t   = row & (SEQ - 1);

    float inv = 1.0f / powf(10000.0f, (float)(2 * i) * (1.0f / 64.0f));
    float ang = (float)t * inv;
    float sn, cs;
    sincosf(ang, &sn, &cs);

    int base = row * D_MODEL + h * HDIM + i;
    float q1 = q[base], q2 = q[base + 32];
    float k1 = k[base], k2 = k[base + 32];
    float qa = q1 * cs - q2 * sn;
    float qb = q2 * cs + q1 * sn;
    float ka = k1 * cs - k2 * sn;
    float kb = k2 * cs + k1 * sn;

    __nv_bfloat16 hv;
    hv = __float2bfloat16_rn(qa); qh[base]      = hv; qm[base]      = __float2bfloat16_rn(qa - __bfloat162float(hv));
    hv = __float2bfloat16_rn(qb); qh[base + 32] = hv; qm[base + 32] = __float2bfloat16_rn(qb - __bfloat162float(hv));
    hv = __float2bfloat16_rn(ka); kh[base]      = hv; km[base]      = __float2bfloat16_rn(ka - __bfloat162float(hv));
    hv = __float2bfloat16_rn(kb); kh[base + 32] = hv; km[base + 32] = __float2bfloat16_rn(kb - __bfloat162float(hv));
}

// ---------------------------------------------------------------------------
// V split + transpose
// ---------------------------------------------------------------------------
__global__ __launch_bounds__(256)
void v_split_t_kernel(const float* __restrict__ v,
                      __nv_bfloat16* __restrict__ vth, __nv_bfloat16* __restrict__ vtm)
{
    __shared__ __nv_bfloat16 th[64][66];
    __shared__ __nv_bfloat16 tm[64][66];
    const int tid = threadIdx.x;
    const int st  = blockIdx.x;
    const int bh  = blockIdx.y;
    const int b   = bh >> 4;
    const int h   = bh & 15;
    const int s0  = st * 64;

#pragma unroll
    for (int l = 0; l < 16; l++) {
        int e = l * 256 + tid;
        int r = e >> 6, d = e & 63;
        float x = v[(b * SEQ + s0 + r) * D_MODEL + h * HDIM + d];
        __nv_bfloat16 hv = __float2bfloat16_rn(x);
        th[d][r] = hv;
        tm[d][r] = __float2bfloat16_rn(x - __bfloat162float(hv));
    }
    __syncthreads();
#pragma unroll
    for (int l = 0; l < 16; l++) {
        int e = l * 256 + tid;
        int d = e >> 6, sc = e & 63;
        int o = (bh * HDIM + d) * SEQ + s0 + sc;
        vth[o] = th[d][sc];
        vtm[o] = tm[d][sc];
    }
}

// ---------------------------------------------------------------------------
// Flash attention, bf16x3 mma.sync with ldmatrix fragment loads.
// ---------------------------------------------------------------------------
#define NT       (SEQ / 64)
#define FL_QH    0
#define FL_QM    18432
#define FL_KH(s) (36864  + (s) * 9216)
#define FL_KM(s) (55296  + (s) * 9216)
#define FL_VH(s) (73728  + (s) * 9216)
#define FL_VM(s) (92160  + (s) * 9216)
#define FL_MS(s) (110592 + (s) * 256)
#define FA2_SMEM 111104

__global__ __launch_bounds__(256)
void flash2_kernel(const __nv_bfloat16* __restrict__ Qh, const __nv_bfloat16* __restrict__ Qm,
                   const __nv_bfloat16* __restrict__ Kh, const __nv_bfloat16* __restrict__ Km,
                   const __nv_bfloat16* __restrict__ Vth, const __nv_bfloat16* __restrict__ Vtm,
                   const float* __restrict__ mask,
                   __nv_bfloat16* __restrict__ Oh, __nv_bfloat16* __restrict__ Om)
{
    extern __shared__ char sm2[];
    const int tid  = threadIdx.x;
    const int w    = tid >> 5;
    const int lane = tid & 31;
    const int g    = lane >> 2;
    const int t    = lane & 3;
    const int qt   = blockIdx.x;
    const int bh   = blockIdx.y;
    const int b    = bh >> 4;
    const int h    = bh & 15;
    const uint32_t sbase = smem_u32(sm2);
    const int lrow16 = lane & 15;
    const int lrow8  = lane & 7;
    const int half   = lane >> 4;
    const int midbit = (lane >> 3) & 1;

    // ldmatrix offsets (within a tile, 144B rows)
    uint32_t qoff[4], koff[4][4];
#pragma unroll
    for (int ks = 0; ks < 4; ks++)
        qoff[ks] = (uint32_t)((w * 16 + lrow16) * 144 + (ks * 2 + half) * 16);
#pragma unroll
    for (int p = 0; p < 4; p++)
#pragma unroll
        for (int ks = 0; ks < 4; ks++)
            koff[p][ks] = (uint32_t)(((2 * p + half) * 8 + lrow8) * 144 +
                                     (ks * 2 + midbit) * 16);

    const __nv_bfloat16* qh_g = Qh + (b * SEQ + qt * 128) * D_MODEL + h * HDIM;
    const __nv_bfloat16* qm_g = Qm + (b * SEQ + qt * 128) * D_MODEL + h * HDIM;
    const __nv_bfloat16* kh_g = Kh + b * SEQ * D_MODEL + h * HDIM;
    const __nv_bfloat16* km_g = Km + b * SEQ * D_MODEL + h * HDIM;
    const __nv_bfloat16* vh_g = Vth + bh * HDIM * SEQ;
    const __nv_bfloat16* vm_g = Vtm + bh * HDIM * SEQ;
    const float* mask_g = mask + b * SEQ;

    auto stage = [&](int kt, int s) {
#pragma unroll
        for (int i = 0; i < 2; i++) {
            int idx = tid + i * 256;
            int r   = idx >> 3;
            int ch  = idx & 7;
            cp_async16(sbase + FL_KH(s) + r * 144 + ch * 16,
                       kh_g + (kt * 64 + r) * D_MODEL + ch * 8);
            cp_async16(sbase + FL_KM(s) + r * 144 + ch * 16,
                       km_g + (kt * 64 + r) * D_MODEL + ch * 8);
            cp_async16(sbase + FL_VH(s) + r * 144 + ch * 16,
                       vh_g + r * SEQ + kt * 64 + ch * 8);
            cp_async16(sbase + FL_VM(s) + r * 144 + ch * 16,
                       vm_g + r * SEQ + kt * 64 + ch * 8);
        }
        if (tid < 16)
            cp_async16(sbase + FL_MS(s) + tid * 16, mask_g + kt * 64 + tid * 4);
    };

#pragma unroll
    for (int i = 0; i < 4; i++) {
        int idx = tid + i * 256;
        int r   = idx >> 3;
        int ch  = idx & 7;
        cp_async16(sbase + FL_QH + r * 144 + ch * 16, qh_g + r * D_MODEL + ch * 8);
        cp_async16(sbase + FL_QM + r * 144 + ch * 16, qm_g + r * D_MODEL + ch * 8);
    }
    stage(0, 0);
    cp_commit();

    float o[8][4];
#pragma unroll
    for (int nf = 0; nf < 8; nf++)
#pragma unroll
        for (int j = 0; j < 4; j++) o[nf][j] = 0.0f;
    float m0 = -1e30f, m1 = -1e30f, l0 = 0.0f, l1 = 0.0f;

    for (int kt = 0; kt < NT; kt++) {
        const int s = kt & 1;
        if (kt + 1 < NT) { stage(kt + 1, s ^ 1); cp_commit(); cp_wait<1>(); }
        else             { cp_wait<0>(); }
        __syncthreads();

        // ---- S = Q K^T (bf16x3, ldmatrix) ----
        float sc[8][4];
#pragma unroll
        for (int nf = 0; nf < 8; nf++)
#pragma unroll
            for (int j = 0; j < 4; j++) sc[nf][j] = 0.0f;

#pragma unroll
        for (int ks = 0; ks < 4; ks++) {
            uint32_t ah[4], am[4];
            ldsm4(ah, sbase + FL_QH + qoff[ks]);
            ldsm4(am, sbase + FL_QM + qoff[ks]);
#pragma unroll
            for (int p = 0; p < 4; p++) {
                uint32_t bh4[4], bm4[4];
                ldsm4(bh4, sbase + FL_KH(s) + koff[p][ks]);
                ldsm4(bm4, sbase + FL_KM(s) + koff[p][ks]);
#pragma unroll
                for (int qq = 0; qq < 2; qq++) {
                    const int nf = 2 * p + qq;
                    uint32_t bhf[2] = { bh4[2 * qq], bh4[2 * qq + 1] };
                    uint32_t bmf[2] = { bm4[2 * qq], bm4[2 * qq + 1] };
                    mma_bf16(sc[nf], am, bhf);
                    mma_bf16(sc[nf], ah, bmf);
                    mma_bf16(sc[nf], ah, bhf);
                }
            }
        }

        // ---- scale + mask + online softmax (warp-local) ----
        float rmax0 = -1e30f, rmax1 = -1e30f;
#pragma unroll
        for (int nf = 0; nf < 8; nf++) {
            float2 mk = *(const float2*)(sm2 + FL_MS(s) + (nf * 8 + 2 * t) * 4);
            sc[nf][0] = fmaf(sc[nf][0], 0.125f, mk.x);
            sc[nf][1] = fmaf(sc[nf][1], 0.125f, mk.y);
            sc[nf][2] = fmaf(sc[nf][2], 0.125f, mk.x);
            sc[nf][3] = fmaf(sc[nf][3], 0.125f, mk.y);
            rmax0 = fmaxf(rmax0, fmaxf(sc[nf][0], sc[nf][1]));
            rmax1 = fmaxf(rmax1, fmaxf(sc[nf][2], sc[nf][3]));
        }
        rmax0 = fmaxf(rmax0, __shfl_xor_sync(0xffffffffu, rmax0, 1));
        rmax0 = fmaxf(rmax0, __shfl_xor_sync(0xffffffffu, rmax0, 2));
        rmax1 = fmaxf(rmax1, __shfl_xor_sync(0xffffffffu, rmax1, 1));
        rmax1 = fmaxf(rmax1, __shfl_xor_sync(0xffffffffu, rmax1, 2));
        float mn0 = fmaxf(m0, rmax0), mn1 = fmaxf(m1, rmax1);
        float c0 = fast_exp(m0 - mn0), c1 = fast_exp(m1 - mn1);
        float sum0 = 0.0f, sum1 = 0.0f;
#pragma unroll
        for (int nf = 0; nf < 8; nf++) {
            sc[nf][0] = fast_exp(sc[nf][0] - mn0);
            sc[nf][1] = fast_exp(sc[nf][1] - mn0);
            sc[nf][2] = fast_exp(sc[nf][2] - mn1);
            sc[nf][3] = fast_exp(sc[nf][3] - mn1);
            sum0 += sc[nf][0] + sc[nf][1];
            sum1 += sc[nf][2] + sc[nf][3];
        }
        sum0 += __shfl_xor_sync(0xffffffffu, sum0, 1);
        sum0 += __shfl_xor_sync(0xffffffffu, sum0, 2);
        sum1 += __shfl_xor_sync(0xffffffffu, sum1, 1);
        sum1 += __shfl_xor_sync(0xffffffffu, sum1, 2);
        l0 = l0 * c0 + sum0;
        l1 = l1 * c1 + sum1;
        m0 = mn0; m1 = mn1;
#pragma unroll
        for (int nf = 0; nf < 8; nf++) {
            o[nf][0] *= c0; o[nf][1] *= c0;
            o[nf][2] *= c1; o[nf][3] *= c1;
        }

        // ---- O += P V (bf16x3; P split in registers, ldmatrix V) ----
#pragma unroll
        for (int ks = 0; ks < 4; ks++) {
            uint32_t ph[4], pm[4];
            ph[0] = pack_bf16(sc[2 * ks][0],     sc[2 * ks][1]);
            ph[1] = pack_bf16(sc[2 * ks][2],     sc[2 * ks][3]);
            ph[2] = pack_bf16(sc[2 * ks + 1][0], sc[2 * ks + 1][1]);
            ph[3] = pack_bf16(sc[2 * ks + 1][2], sc[2 * ks + 1][3]);
            pm[0] = pack_bf16(sc[2 * ks][0]     - bf16lo_f(ph[0]), sc[2 * ks][1]     - bf16hi_f(ph[0]));
            pm[1] = pack_bf16(sc[2 * ks][2]     - bf16lo_f(ph[1]), sc[2 * ks][3]     - bf16hi_f(ph[1]));
            pm[2] = pack_bf16(sc[2 * ks + 1][0] - bf16lo_f(ph[2]), sc[2 * ks + 1][1] - bf16hi_f(ph[2]));
            pm[3] = pack_bf16(sc[2 * ks + 1][2] - bf16lo_f(ph[3]), sc[2 * ks + 1][3] - bf16hi_f(ph[3]));
#pragma unroll
            for (int p = 0; p < 4; p++) {
                uint32_t bh4[4], bm4[4];
                ldsm4(bh4, sbase + FL_VH(s) + koff[p][ks]);
                ldsm4(bm4, sbase + FL_VM(s) + koff[p][ks]);
#pragma unroll
                for (int qq = 0; qq < 2; qq++) {
                    const int nf = 2 * p + qq;
                    uint32_t bhf[2] = { bh4[2 * qq], bh4[2 * qq + 1] };
                    uint32_t bmf[2] = { bm4[2 * qq], bm4[2 * qq + 1] };
                    mma_bf16(o[nf], pm, bhf);
                    mma_bf16(o[nf], ph, bmf);
                    mma_bf16(o[nf], ph, bhf);
                }
            }
        }
        __syncthreads();
    }

    // Epilogue: write bf16 hi/mid split directly (consumed by gemm_out_bf)
    float i0 = 1.0f / l0, i1 = 1.0f / l1;
    int row0 = b * SEQ + qt * 128 + w * 16 + g;
    int colb = h * HDIM + 2 * t;
#pragma unroll
    for (int nf = 0; nf < 8; nf++) {
        float v0 = o[nf][0] * i0, v1 = o[nf][1] * i0;
        float v2 = o[nf][2] * i1, v3 = o[nf][3] * i1;
        uint32_t hw0 = pack_bf16(v0, v1);
        uint32_t hw1 = pack_bf16(v2, v3);
        uint32_t mw0 = pack_bf16(v0 - bf16lo_f(hw0), v1 - bf16hi_f(hw0));
        uint32_t mw1 = pack_bf16(v2 - bf16lo_f(hw1), v3 - bf16hi_f(hw1));
        int off0 = row0 * D_MODEL + colb + nf * 8;
        int off1 = (row0 + 8) * D_MODEL + colb + nf * 8;
        *(uint32_t*)(Oh + off0) = hw0;
        *(uint32_t*)(Om + off0) = mw0;
        *(uint32_t*)(Oh + off1) = hw1;
        *(uint32_t*)(Om + off1) = mw1;
    }
}

// ---------------------------------------------------------------------------
// Launch
// ---------------------------------------------------------------------------
extern "C" void kernel_launch(void* const* d_in, const int* in_sizes, int n_in,
                              void* d_out, int out_size)
{
    const float* x    = (const float*)d_in[0];
    const float* wq   = (const float*)d_in[1];
    const float* bq   = (const float*)d_in[2];
    const float* wk   = (const float*)d_in[3];
    const float* bk   = (const float*)d_in[4];
    const float* wv   = (const float*)d_in[5];
    const float* bv   = (const float*)d_in[6];
    const float* wo   = (const float*)d_in[7];
    const float* bo   = (const float*)d_in[8];
    const float* mask = (const float*)d_in[9];
    float* out = (float*)d_out;

    float *q, *k, *v;
    __nv_bfloat16 *qh, *qm, *kh, *km, *vth, *vtm;
    __nv_bfloat16 *xh, *xm, *ath, *atm;
    __nv_bfloat16 *wqh, *wqm, *wkh, *wkm, *wvh, *wvm, *woh, *wom;
    cudaGetSymbolAddress((void**)&q,   g_q);
    cudaGetSymbolAddress((void**)&k,   g_k);
    cudaGetSymbolAddress((void**)&v,   g_v);
    cudaGetSymbolAddress((void**)&qh,  g_qh);
    cudaGetSymbolAddress((void**)&qm,  g_qm);
    cudaGetSymbolAddress((void**)&kh,  g_kh);
    cudaGetSymbolAddress((void**)&km,  g_km);
    cudaGetSymbolAddress((void**)&vth, g_vth);
    cudaGetSymbolAddress((void**)&vtm, g_vtm);
    cudaGetSymbolAddress((void**)&xh,  g_xh);
    cudaGetSymbolAddress((void**)&xm,  g_xm);
    cudaGetSymbolAddress((void**)&ath, g_ath);
    cudaGetSymbolAddress((void**)&atm, g_atm);
    cudaGetSymbolAddress((void**)&wqh, g_wqh);
    cudaGetSymbolAddress((void**)&wqm, g_wqm);
    cudaGetSymbolAddress((void**)&wkh, g_wkh);
    cudaGetSymbolAddress((void**)&wkm, g_wkm);
    cudaGetSymbolAddress((void**)&wvh, g_wvh);
    cudaGetSymbolAddress((void**)&wvm, g_wvm);
    cudaGetSymbolAddress((void**)&woh, g_woh);
    cudaGetSymbolAddress((void**)&wom, g_wom);

    cudaFuncSetAttribute(gemm_qkv_bf,
                         cudaFuncAttributeMaxDynamicSharedMemorySize, GEMM_SMEM2);
    cudaFuncSetAttribute(gemm_out_bf,
                         cudaFuncAttributeMaxDynamicSharedMemorySize, GEMM_SMEM2);
    cudaFuncSetAttribute(flash2_kernel,
                         cudaFuncAttributeMaxDynamicSharedMemorySize, FA2_SMEM);

    // Split prepasses (bf16 hi/mid)
    const int NX4 = ROWS * D_MODEL / 4;       // 1M
    const int NW4 = D_MODEL * D_MODEL / 4;    // 256K
    split_kernel<<<NX4 / 256, 256>>>(x,  xh,  xm,  NX4);
    split_kernel<<<NW4 / 256, 256>>>(wq, wqh, wqm, NW4);
    split_kernel<<<NW4 / 256, 256>>>(wk, wkh, wkm, NW4);
    split_kernel<<<NW4 / 256, 256>>>(wv, wvh, wvm, NW4);
    split_kernel<<<NW4 / 256, 256>>>(wo, woh, wom, NW4);

    // QKV projections (bf16x3 mma.sync + ldmatrix)
    dim3 g1(D_MODEL / 128, ROWS / 128, 3);
    gemm_qkv_bf<<<g1, 256, GEMM_SMEM2>>>(xh, xm, wqh, wqm, bq, q,
                                         wkh, wkm, bk, k, wvh, wvm, bv, v);

    // RoPE + bf16 hi/mid split of q, k
    int rope_threads = ROWS * N_HEADS * 32;
    rope_split_kernel<<<rope_threads / 256, 256>>>(q, k, qh, qm, kh, km);

    // V split + transpose
    v_split_t_kernel<<<dim3(SEQ / 64, BATCH * N_HEADS), 256>>>(v, vth, vtm);

    // Flash attention (bf16x3 + ldmatrix) — writes split output directly
    flash2_kernel<<<dim3(SEQ / 128, BATCH * N_HEADS), 256, FA2_SMEM>>>(
        qh, qm, kh, km, vth, vtm, mask, ath, atm);

    // Output projection (bf16x3 + ldmatrix) -> d_out
    dim3 g3(D_MODEL / 128, ROWS / 128);
    gemm_out_bf<<<g3, 256, GEMM_SMEM2>>>(ath, atm, woh, wom, bo, out);
}

// round 10
// speedup vs baseline: 4.7208x; 1.4538x over previous
#include <cuda_runtime.h>
#include <cuda_fp16.h>
#include <cstdint>
#include <math.h>

#define D_MODEL 1024
#define N_HEADS 16
#define HDIM    64
#define SEQ     2048
#define BATCH   2
#define ROWS    (BATCH * SEQ)   // 4096

// ---------------------------------------------------------------------------
// Scratch (static device globals — no allocation allowed)
// ---------------------------------------------------------------------------
__device__ float g_q[ROWS * D_MODEL];
__device__ float g_k[ROWS * D_MODEL];
__device__ float g_v[ROWS * D_MODEL];
__device__ __half g_qh[ROWS * D_MODEL];                       // Q hi only
__device__ __half g_kh[ROWS * D_MODEL];
__device__ __half g_km[ROWS * D_MODEL];
__device__ __half g_vth[BATCH * N_HEADS * HDIM * SEQ];        // [bh*64+d][s]
__device__ __half g_vtm[BATCH * N_HEADS * HDIM * SEQ];
__device__ __half g_xh[ROWS * D_MODEL];                       // X hi only
__device__ __half g_ath[ROWS * D_MODEL];                      // att hi only
__device__ __half g_wqh[D_MODEL * D_MODEL];
__device__ __half g_wqm[D_MODEL * D_MODEL];
__device__ __half g_wkh[D_MODEL * D_MODEL];
__device__ __half g_wkm[D_MODEL * D_MODEL];
__device__ __half g_wvh[D_MODEL * D_MODEL];
__device__ __half g_wvm[D_MODEL * D_MODEL];
__device__ __half g_woh[D_MODEL * D_MODEL];
__device__ __half g_wom[D_MODEL * D_MODEL];

// ---------------------------------------------------------------------------
// Helpers
// ---------------------------------------------------------------------------
__device__ __forceinline__ uint32_t smem_u32(const void* p) {
    uint32_t a;
    asm("{ .reg .u64 t; cvta.to.shared.u64 t, %1; cvt.u32.u64 %0, t; }"
        : "=r"(a) : "l"(p));
    return a;
}
__device__ __forceinline__ void cp_async16(uint32_t saddr, const void* gptr) {
    asm volatile("cp.async.cg.shared.global [%0], [%1], 16;"
                 :: "r"(saddr), "l"(gptr) : "memory");
}
__device__ __forceinline__ void cp_commit() {
    asm volatile("cp.async.commit_group;" ::: "memory");
}
template <int N>
__device__ __forceinline__ void cp_wait() {
    asm volatile("cp.async.wait_group %0;" :: "n"(N) : "memory");
}
__device__ __forceinline__ void mma_f16(float* d, const uint32_t* a,
                                        const uint32_t* b) {
    asm volatile(
        "mma.sync.aligned.m16n8k16.row.col.f32.f16.f16.f32 "
        "{%0,%1,%2,%3}, {%4,%5,%6,%7}, {%8,%9}, {%0,%1,%2,%3};"
        : "+f"(d[0]), "+f"(d[1]), "+f"(d[2]), "+f"(d[3])
        : "r"(a[0]), "r"(a[1]), "r"(a[2]), "r"(a[3]), "r"(b[0]), "r"(b[1]));
}
__device__ __forceinline__ void ldsm4(uint32_t* r, uint32_t addr) {
    asm volatile("ldmatrix.sync.aligned.m8n8.x4.shared.b16 {%0,%1,%2,%3}, [%4];"
                 : "=r"(r[0]), "=r"(r[1]), "=r"(r[2]), "=r"(r[3]) : "r"(addr));
}
// pack {lo, hi} floats into f16x2 word (lo in low half)
__device__ __forceinline__ uint32_t pack_f16(float lo, float hi) {
    uint32_t r;
    asm("cvt.rn.f16x2.f32 %0, %1, %2;" : "=r"(r) : "f"(hi), "f"(lo));
    return r;
}

// FFMA-only exp, accurate ~1e-7 on [-87, 0]
__device__ __forceinline__ float fast_exp(float x) {
    x = fmaxf(x, -87.0f);
    float y = x * 1.4426950408889634f;
    float r = y + 12582912.0f;
    float n = r - 12582912.0f;
    float f = y - n;
    float t = f * 0.6931471805599453f;
    float p = 1.3888889e-3f;
    p = fmaf(p, t, 8.3333333e-3f);
    p = fmaf(p, t, 4.1666667e-2f);
    p = fmaf(p, t, 1.6666667e-1f);
    p = fmaf(p, t, 0.5f);
    p = fmaf(p, t, 1.0f);
    p = fmaf(p, t, 1.0f);
    int ni = __float_as_int(r) - 0x4B400000;
    float scale = __int_as_float((ni << 23) + 0x3F800000);
    return p * scale;
}

// ---------------------------------------------------------------------------
// Split prepasses
// ---------------------------------------------------------------------------
__global__ __launch_bounds__(256)
void split2_kernel(const float* __restrict__ src,
                   __half* __restrict__ h, __half* __restrict__ m, int n4)
{
    int i = blockIdx.x * blockDim.x + threadIdx.x;
    if (i >= n4) return;
    float4 x = *(const float4*)(src + i * 4);
    __half h0 = __float2half_rn(x.x);
    __half h1 = __float2half_rn(x.y);
    __half h2 = __float2half_rn(x.z);
    __half h3 = __float2half_rn(x.w);
    __half2* hp = (__half2*)(h + i * 4);
    hp[0] = __half2(h0, h1);
    hp[1] = __half2(h2, h3);
    __half2* mp = (__half2*)(m + i * 4);
    mp[0] = __half2(__float2half_rn(x.x - __half2float(h0)),
                    __float2half_rn(x.y - __half2float(h1)));
    mp[1] = __half2(__float2half_rn(x.z - __half2float(h2)),
                    __float2half_rn(x.w - __half2float(h3)));
}

__global__ __launch_bounds__(256)
void split1_kernel(const float* __restrict__ src, __half* __restrict__ h, int n4)
{
    int i = blockIdx.x * blockDim.x + threadIdx.x;
    if (i >= n4) return;
    float4 x = *(const float4*)(src + i * 4);
    __half2* hp = (__half2*)(h + i * 4);
    hp[0] = __half2(__float2half_rn(x.x), __float2half_rn(x.y));
    hp[1] = __half2(__float2half_rn(x.z), __float2half_rn(x.w));
}

// ---------------------------------------------------------------------------
// fp16x2 GEMM: C[M,N] = A[M,K] @ W[N,K]^T + bias[N]
// Terms: ah*wh + ah*wm (A-side mid dropped; err ~2^-12 random-walk).
// 128x128x32 CTA tile, 256 threads (8 warps as 2x4), warp tile 64x32.
// 3-stage cp.async ring (tiles Ah, Wh, Wm = 24KB/stage -> 72KB), XOR swizzle,
// ldmatrix fragment loads, one __syncthreads per chunk.
// ---------------------------------------------------------------------------
#define BK2      32
#define NCH2     (D_MODEL / BK2)       // 32 chunks
#define TILE_W2  (128 * 16)            // 2048 words per tile
#define TILE_B2  (TILE_W2 * 4)         // 8192 bytes
#define STAGE_W3 (3 * TILE_W2)         // Ah, Wh, Wm
#define GEMM_SMEM3 (3 * STAGE_W3 * 4)  // 73728 bytes

__device__ __forceinline__ int swz(int r, int w) {
    return r * 16 + (w ^ (((r >> 1) & 3) << 2));
}

__device__ __forceinline__ void stage_chunk3(
    const __half* __restrict__ Ah, const __half* __restrict__ Wh,
    const __half* __restrict__ Wm,
    uint32_t sbase, int buf, int k0, int tid)
{
    const __half* src[3] = { Ah, Wh, Wm };
    uint32_t s0 = sbase + buf * STAGE_W3 * 4;
#pragma unroll
    for (int i = 0; i < 6; i++) {
        int idx  = tid + i * 256;         // 0..1535
        int tile = idx / 512;             // 0..2
        int wi   = idx & 511;
        int r    = wi >> 2;               // row 0..127
        int ch   = wi & 3;                // 16B chunk (4 words)
        cp_async16(s0 + (tile * TILE_W2 + swz(r, ch * 4)) * 4,
                   src[tile] + r * D_MODEL + k0 + ch * 8);
    }
    cp_commit();
}

__device__ __forceinline__ void gemm_f16_body(
    const __half* __restrict__ Ah, const __half* __restrict__ Wh,
    const __half* __restrict__ Wm,
    const float* __restrict__ bias, float* __restrict__ C)
{
    extern __shared__ uint32_t smw[];
    const uint32_t sbase = smem_u32(smw);
    const int tid  = threadIdx.x;
    const int wid  = tid >> 5;
    const int lane = tid & 31;
    const int wm_  = (wid & 1) * 64;
    const int wn   = (wid >> 1) * 32;
    const int brow = blockIdx.y * 128;
    const int bcol = blockIdx.x * 128;
    const int g    = lane >> 2;
    const int t    = lane & 3;
    const int lrow16 = lane & 15;
    const int lrow8  = lane & 7;
    const int half_  = lane >> 4;
    const int midbit = (lane >> 3) & 1;

    uint32_t aoff[4][2], boff[2][2];
#pragma unroll
    for (int mf = 0; mf < 4; mf++)
#pragma unroll
        for (int ks = 0; ks < 2; ks++) {
            int row = wm_ + mf * 16 + lrow16;
            int ch  = ks * 2 + half_;
            aoff[mf][ks] = (uint32_t)((row * 16 +
                ((ch * 4) ^ (((row >> 1) & 3) << 2))) * 4);
        }
#pragma unroll
    for (int p = 0; p < 2; p++)
#pragma unroll
        for (int ks = 0; ks < 2; ks++) {
            int row = wn + (2 * p + half_) * 8 + lrow8;
            int ch  = ks * 2 + midbit;
            boff[p][ks] = (uint32_t)((row * 16 +
                ((ch * 4) ^ (((row >> 1) & 3) << 2))) * 4);
        }

    float acc[4][4][4];
#pragma unroll
    for (int mf = 0; mf < 4; mf++)
#pragma unroll
        for (int nf = 0; nf < 4; nf++)
#pragma unroll
            for (int r = 0; r < 4; r++) acc[mf][nf][r] = 0.0f;

    const __half* Ah_r = Ah + brow * D_MODEL;
    const __half* Wh_r = Wh + bcol * D_MODEL;
    const __half* Wm_r = Wm + bcol * D_MODEL;

    stage_chunk3(Ah_r, Wh_r, Wm_r, sbase, 0, 0, tid);
    stage_chunk3(Ah_r, Wh_r, Wm_r, sbase, 1, BK2, tid);

    int buf = 0;
    for (int c = 0; c < NCH2; c++) {
        if (c < NCH2 - 1) cp_wait<1>(); else cp_wait<0>();
        __syncthreads();
        if (c + 2 < NCH2) {
            int nb = buf + 2; if (nb >= 3) nb -= 3;
            stage_chunk3(Ah_r, Wh_r, Wm_r, sbase, nb, (c + 2) * BK2, tid);
        }

        const uint32_t sb0 = sbase + buf * (STAGE_W3 * 4);

#pragma unroll
        for (int ks = 0; ks < 2; ks++) {
            uint32_t ah[4][4];
#pragma unroll
            for (int mf = 0; mf < 4; mf++)
                ldsm4(ah[mf], sb0 + aoff[mf][ks]);
#pragma unroll
            for (int p = 0; p < 2; p++) {
                uint32_t bh4[4], bm4[4];
                ldsm4(bh4, sb0 + TILE_B2 + boff[p][ks]);
                ldsm4(bm4, sb0 + 2 * TILE_B2 + boff[p][ks]);
#pragma unroll
                for (int qq = 0; qq < 2; qq++) {
                    const int nf = 2 * p + qq;
                    uint32_t bh[2] = { bh4[2 * qq], bh4[2 * qq + 1] };
                    uint32_t bm[2] = { bm4[2 * qq], bm4[2 * qq + 1] };
#pragma unroll
                    for (int mf = 0; mf < 4; mf++) {
                        mma_f16(acc[mf][nf], ah[mf], bm);
                        mma_f16(acc[mf][nf], ah[mf], bh);
                    }
                }
            }
        }
        buf++; if (buf >= 3) buf = 0;
    }

#pragma unroll
    for (int mf = 0; mf < 4; mf++) {
        int row0 = brow + wm_ + mf * 16 + g;
#pragma unroll
        for (int nf = 0; nf < 4; nf++) {
            int col = bcol + wn + nf * 8 + 2 * t;
            float b0 = bias[col], b1 = bias[col + 1];
            float2 v0 = make_float2(acc[mf][nf][0] + b0, acc[mf][nf][1] + b1);
            float2 v1 = make_float2(acc[mf][nf][2] + b0, acc[mf][nf][3] + b1);
            *(float2*)(C + row0 * D_MODEL + col)       = v0;
            *(float2*)(C + (row0 + 8) * D_MODEL + col) = v1;
        }
    }
}

__global__ __launch_bounds__(256)
void gemm_qkv_f16(const __half* __restrict__ Xh,
                  const __half* __restrict__ Wqh, const __half* __restrict__ Wqm,
                  const float* __restrict__ Bq, float* __restrict__ Oq,
                  const __half* __restrict__ Wkh, const __half* __restrict__ Wkm,
                  const float* __restrict__ Bk, float* __restrict__ Ok,
                  const __half* __restrict__ Wvh, const __half* __restrict__ Wvm,
                  const float* __restrict__ Bv, float* __restrict__ Ov)
{
    const __half *Wh, *Wm; const float* bb; float* C;
    if (blockIdx.z == 0)      { Wh = Wqh; Wm = Wqm; bb = Bq; C = Oq; }
    else if (blockIdx.z == 1) { Wh = Wkh; Wm = Wkm; bb = Bk; C = Ok; }
    else                      { Wh = Wvh; Wm = Wvm; bb = Bv; C = Ov; }
    gemm_f16_body(Xh, Wh, Wm, bb, C);
}

__global__ __launch_bounds__(256)
void gemm_out_f16(const __half* __restrict__ Ah,
                  const __half* __restrict__ Wh, const __half* __restrict__ Wm,
                  const float* __restrict__ bb, float* __restrict__ C)
{
    gemm_f16_body(Ah, Wh, Wm, bb, C);
}

// ---------------------------------------------------------------------------
// RoPE + split: q -> fp16 hi only; k -> fp16 hi/mid.
// ---------------------------------------------------------------------------
__global__ void rope_split_kernel(const float* __restrict__ q, const float* __restrict__ k,
                                  __half* __restrict__ qh,
                                  __half* __restrict__ kh, __half* __restrict__ km)
{
    int idx = blockIdx.x * blockDim.x + threadIdx.x;
    if (idx >= ROWS * N_HEADS * 32) return;
    int i   = idx & 31;
    int h   = (idx >> 5) & (N_HEADS - 1);
    int row = idx >> 9;
    int t   = row & (SEQ - 1);

    float inv = 1.0f / powf(10000.0f, (float)(2 * i) * (1.0f / 64.0f));
    float ang = (float)t * inv;
    float sn, cs;
    sincosf(ang, &sn, &cs);

    int base = row * D_MODEL + h * HDIM + i;
    float q1 = q[base], q2 = q[base + 32];
    float k1 = k[base], k2 = k[base + 32];
    float qa = q1 * cs - q2 * sn;
    float qb = q2 * cs + q1 * sn;
    float ka = k1 * cs - k2 * sn;
    float kb = k2 * cs + k1 * sn;

    qh[base]      = __float2half_rn(qa);
    qh[base + 32] = __float2half_rn(qb);
    __half hv;
    hv = __float2half_rn(ka); kh[base]      = hv; km[base]      = __float2half_rn(ka - __half2float(hv));
    hv = __float2half_rn(kb); kh[base + 32] = hv; km[base + 32] = __float2half_rn(kb - __half2float(hv));
}

// ---------------------------------------------------------------------------
// V split + transpose: fp32 [b*S+s][h*64+d] -> vT fp16 hi/mid [(bh*64)+d][s]
// ---------------------------------------------------------------------------
__global__ __launch_bounds__(256)
void v_split_t_kernel(const float* __restrict__ v,
                      __half* __restrict__ vth, __half* __restrict__ vtm)
{
    __shared__ __half th[64][66];
    __shared__ __half tm[64][66];
    const int tid = threadIdx.x;
    const int st  = blockIdx.x;
    const int bh  = blockIdx.y;
    const int b   = bh >> 4;
    const int h   = bh & 15;
    const int s0  = st * 64;

#pragma unroll
    for (int l = 0; l < 16; l++) {
        int e = l * 256 + tid;
        int r = e >> 6, d = e & 63;
        float x = v[(b * SEQ + s0 + r) * D_MODEL + h * HDIM + d];
        __half hv = __float2half_rn(x);
        th[d][r] = hv;
        tm[d][r] = __float2half_rn(x - __half2float(hv));
    }
    __syncthreads();
#pragma unroll
    for (int l = 0; l < 16; l++) {
        int e = l * 256 + tid;
        int d = e >> 6, sc = e & 63;
        int o = (bh * HDIM + d) * SEQ + s0 + sc;
        vth[o] = th[d][sc];
        vtm[o] = tm[d][sc];
    }
}

// ---------------------------------------------------------------------------
// Flash attention, fp16x2 mma.sync + ldmatrix.
// QK = qh*(kh+km); PV = ph*(vh+vm). Q and P carry no mid.
// Epilogue writes fp16 hi of att (consumed by gemm_out_f16).
// ---------------------------------------------------------------------------
#define NT        (SEQ / 64)
#define FL_QH     0
#define FL_STG    18432
#define FL_SSZ    37120
#define FL_KH(s)  (FL_STG + (s) * FL_SSZ)
#define FL_KM(s)  (FL_STG + (s) * FL_SSZ + 9216)
#define FL_VH(s)  (FL_STG + (s) * FL_SSZ + 18432)
#define FL_VM(s)  (FL_STG + (s) * FL_SSZ + 27648)
#define FL_MS(s)  (FL_STG + (s) * FL_SSZ + 36864)
#define FA3_SMEM  (FL_STG + 2 * FL_SSZ)   // 92672

__global__ __launch_bounds__(256)
void flash3_kernel(const __half* __restrict__ Qh,
                   const __half* __restrict__ Kh, const __half* __restrict__ Km,
                   const __half* __restrict__ Vth, const __half* __restrict__ Vtm,
                   const float* __restrict__ mask,
                   __half* __restrict__ Oh)
{
    extern __shared__ char sm2[];
    const int tid  = threadIdx.x;
    const int w    = tid >> 5;
    const int lane = tid & 31;
    const int g    = lane >> 2;
    const int t    = lane & 3;
    const int qt   = blockIdx.x;
    const int bh   = blockIdx.y;
    const int b    = bh >> 4;
    const int h    = bh & 15;
    const uint32_t sbase = smem_u32(sm2);
    const int lrow16 = lane & 15;
    const int lrow8  = lane & 7;
    const int half_  = lane >> 4;
    const int midbit = (lane >> 3) & 1;

    uint32_t qoff[4], koff[4][4];
#pragma unroll
    for (int ks = 0; ks < 4; ks++)
        qoff[ks] = (uint32_t)((w * 16 + lrow16) * 144 + (ks * 2 + half_) * 16);
#pragma unroll
    for (int p = 0; p < 4; p++)
#pragma unroll
        for (int ks = 0; ks < 4; ks++)
            koff[p][ks] = (uint32_t)(((2 * p + half_) * 8 + lrow8) * 144 +
                                     (ks * 2 + midbit) * 16);

    const __half* qh_g = Qh + (b * SEQ + qt * 128) * D_MODEL + h * HDIM;
    const __half* kh_g = Kh + b * SEQ * D_MODEL + h * HDIM;
    const __half* km_g = Km + b * SEQ * D_MODEL + h * HDIM;
    const __half* vh_g = Vth + bh * HDIM * SEQ;
    const __half* vm_g = Vtm + bh * HDIM * SEQ;
    const float* mask_g = mask + b * SEQ;

    auto stage = [&](int kt, int s) {
#pragma unroll
        for (int i = 0; i < 2; i++) {
            int idx = tid + i * 256;
            int r   = idx >> 3;
            int ch  = idx & 7;
            cp_async16(sbase + FL_KH(s) + r * 144 + ch * 16,
                       kh_g + (kt * 64 + r) * D_MODEL + ch * 8);
            cp_async16(sbase + FL_KM(s) + r * 144 + ch * 16,
                       km_g + (kt * 64 + r) * D_MODEL + ch * 8);
            cp_async16(sbase + FL_VH(s) + r * 144 + ch * 16,
                       vh_g + r * SEQ + kt * 64 + ch * 8);
            cp_async16(sbase + FL_VM(s) + r * 144 + ch * 16,
                       vm_g + r * SEQ + kt * 64 + ch * 8);
        }
        if (tid < 16)
            cp_async16(sbase + FL_MS(s) + tid * 16, mask_g + kt * 64 + tid * 4);
    };

#pragma unroll
    for (int i = 0; i < 2; i++) {
        int idx = tid + i * 256;
        int r   = idx >> 2;                // 0..127
        int ch  = (idx & 3) * 2;           // 0,2,4,6 (two 16B chunks)
        cp_async16(sbase + FL_QH + r * 144 + ch * 16, qh_g + r * D_MODEL + ch * 8);
        cp_async16(sbase + FL_QH + r * 144 + (ch + 1) * 16, qh_g + r * D_MODEL + (ch + 1) * 8);
    }
    stage(0, 0);
    cp_commit();

    float o[8][4];
#pragma unroll
    for (int nf = 0; nf < 8; nf++)
#pragma unroll
        for (int j = 0; j < 4; j++) o[nf][j] = 0.0f;
    float m0 = -1e30f, m1 = -1e30f, l0 = 0.0f, l1 = 0.0f;

    for (int kt = 0; kt < NT; kt++) {
        const int s = kt & 1;
        if (kt + 1 < NT) { stage(kt + 1, s ^ 1); cp_commit(); cp_wait<1>(); }
        else             { cp_wait<0>(); }
        __syncthreads();

        // ---- S = Q K^T ----
        float sc[8][4];
#pragma unroll
        for (int nf = 0; nf < 8; nf++)
#pragma unroll
            for (int j = 0; j < 4; j++) sc[nf][j] = 0.0f;

#pragma unroll
        for (int ks = 0; ks < 4; ks++) {
            uint32_t ah[4];
            ldsm4(ah, sbase + FL_QH + qoff[ks]);
#pragma unroll
            for (int p = 0; p < 4; p++) {
                uint32_t bh4[4], bm4[4];
                ldsm4(bh4, sbase + FL_KH(s) + koff[p][ks]);
                ldsm4(bm4, sbase + FL_KM(s) + koff[p][ks]);
#pragma unroll
                for (int qq = 0; qq < 2; qq++) {
                    const int nf = 2 * p + qq;
                    uint32_t bhf[2] = { bh4[2 * qq], bh4[2 * qq + 1] };
                    uint32_t bmf[2] = { bm4[2 * qq], bm4[2 * qq + 1] };
                    mma_f16(sc[nf], ah, bmf);
                    mma_f16(sc[nf], ah, bhf);
                }
            }
        }

        // ---- scale + mask + online softmax (warp-local) ----
        float rmax0 = -1e30f, rmax1 = -1e30f;
#pragma unroll
        for (int nf = 0; nf < 8; nf++) {
            float2 mk = *(const float2*)(sm2 + FL_MS(s) + (nf * 8 + 2 * t) * 4);
            sc[nf][0] = fmaf(sc[nf][0], 0.125f, mk.x);
            sc[nf][1] = fmaf(sc[nf][1], 0.125f, mk.y);
            sc[nf][2] = fmaf(sc[nf][2], 0.125f, mk.x);
            sc[nf][3] = fmaf(sc[nf][3], 0.125f, mk.y);
            rmax0 = fmaxf(rmax0, fmaxf(sc[nf][0], sc[nf][1]));
            rmax1 = fmaxf(rmax1, fmaxf(sc[nf][2], sc[nf][3]));
        }
        rmax0 = fmaxf(rmax0, __shfl_xor_sync(0xffffffffu, rmax0, 1));
        rmax0 = fmaxf(rmax0, __shfl_xor_sync(0xffffffffu, rmax0, 2));
        rmax1 = fmaxf(rmax1, __shfl_xor_sync(0xffffffffu, rmax1, 1));
        rmax1 = fmaxf(rmax1, __shfl_xor_sync(0xffffffffu, rmax1, 2));
        float mn0 = fmaxf(m0, rmax0), mn1 = fmaxf(m1, rmax1);
        float c0 = fast_exp(m0 - mn0), c1 = fast_exp(m1 - mn1);
        float sum0 = 0.0f, sum1 = 0.0f;
#pragma unroll
        for (int nf = 0; nf < 8; nf++) {
            sc[nf][0] = fast_exp(sc[nf][0] - mn0);
            sc[nf][1] = fast_exp(sc[nf][1] - mn0);
            sc[nf][2] = fast_exp(sc[nf][2] - mn1);
            sc[nf][3] = fast_exp(sc[nf][3] - mn1);
            sum0 += sc[nf][0] + sc[nf][1];
            sum1 += sc[nf][2] + sc[nf][3];
        }
        sum0 += __shfl_xor_sync(0xffffffffu, sum0, 1);
        sum0 += __shfl_xor_sync(0xffffffffu, sum0, 2);
        sum1 += __shfl_xor_sync(0xffffffffu, sum1, 1);
        sum1 += __shfl_xor_sync(0xffffffffu, sum1, 2);
        l0 = l0 * c0 + sum0;
        l1 = l1 * c1 + sum1;
        m0 = mn0; m1 = mn1;
#pragma unroll
        for (int nf = 0; nf < 8; nf++) {
            o[nf][0] *= c0; o[nf][1] *= c0;
            o[nf][2] *= c1; o[nf][3] *= c1;
        }

        // ---- O += P V (P hi only) ----
#pragma unroll
        for (int ks = 0; ks < 4; ks++) {
            uint32_t ph[4];
            ph[0] = pack_f16(sc[2 * ks][0],     sc[2 * ks][1]);
            ph[1] = pack_f16(sc[2 * ks][2],     sc[2 * ks][3]);
            ph[2] = pack_f16(sc[2 * ks + 1][0], sc[2 * ks + 1][1]);
            ph[3] = pack_f16(sc[2 * ks + 1][2], sc[2 * ks + 1][3]);
#pragma unroll
            for (int p = 0; p < 4; p++) {
                uint32_t bh4[4], bm4[4];
                ldsm4(bh4, sbase + FL_VH(s) + koff[p][ks]);
                ldsm4(bm4, sbase + FL_VM(s) + koff[p][ks]);
#pragma unroll
                for (int qq = 0; qq < 2; qq++) {
                    const int nf = 2 * p + qq;
                    uint32_t bhf[2] = { bh4[2 * qq], bh4[2 * qq + 1] };
                    uint32_t bmf[2] = { bm4[2 * qq], bm4[2 * qq + 1] };
                    mma_f16(o[nf], ph, bmf);
                    mma_f16(o[nf], ph, bhf);
                }
            }
        }
        __syncthreads();
    }

    // Epilogue: write fp16 hi of att (A-side of out-proj; mid dropped)
    float i0 = 1.0f / l0, i1 = 1.0f / l1;
    int row0 = b * SEQ + qt * 128 + w * 16 + g;
    int colb = h * HDIM + 2 * t;
#pragma unroll
    for (int nf = 0; nf < 8; nf++) {
        uint32_t hw0 = pack_f16(o[nf][0] * i0, o[nf][1] * i0);
        uint32_t hw1 = pack_f16(o[nf][2] * i1, o[nf][3] * i1);
        *(uint32_t*)(Oh + row0 * D_MODEL + colb + nf * 8)       = hw0;
        *(uint32_t*)(Oh + (row0 + 8) * D_MODEL + colb + nf * 8) = hw1;
    }
}

// ---------------------------------------------------------------------------
// Launch
// ---------------------------------------------------------------------------
extern "C" void kernel_launch(void* const* d_in, const int* in_sizes, int n_in,
                              void* d_out, int out_size)
{
    const float* x    = (const float*)d_in[0];
    const float* wq   = (const float*)d_in[1];
    const float* bq   = (const float*)d_in[2];
    const float* wk   = (const float*)d_in[3];
    const float* bk   = (const float*)d_in[4];
    const float* wv   = (const float*)d_in[5];
    const float* bv   = (const float*)d_in[6];
    const float* wo   = (const float*)d_in[7];
    const float* bo   = (const float*)d_in[8];
    const float* mask = (const float*)d_in[9];
    float* out = (float*)d_out;

    float *q, *k, *v;
    __half *qh, *kh, *km, *vth, *vtm, *xh, *ath;
    __half *wqh, *wqm, *wkh, *wkm, *wvh, *wvm, *woh, *wom;
    cudaGetSymbolAddress((void**)&q,   g_q);
    cudaGetSymbolAddress((void**)&k,   g_k);
    cudaGetSymbolAddress((void**)&v,   g_v);
    cudaGetSymbolAddress((void**)&qh,  g_qh);
    cudaGetSymbolAddress((void**)&kh,  g_kh);
    cudaGetSymbolAddress((void**)&km,  g_km);
    cudaGetSymbolAddress((void**)&vth, g_vth);
    cudaGetSymbolAddress((void**)&vtm, g_vtm);
    cudaGetSymbolAddress((void**)&xh,  g_xh);
    cudaGetSymbolAddress((void**)&ath, g_ath);
    cudaGetSymbolAddress((void**)&wqh, g_wqh);
    cudaGetSymbolAddress((void**)&wqm, g_wqm);
    cudaGetSymbolAddress((void**)&wkh, g_wkh);
    cudaGetSymbolAddress((void**)&wkm, g_wkm);
    cudaGetSymbolAddress((void**)&wvh, g_wvh);
    cudaGetSymbolAddress((void**)&wvm, g_wvm);
    cudaGetSymbolAddress((void**)&woh, g_woh);
    cudaGetSymbolAddress((void**)&wom, g_wom);

    cudaFuncSetAttribute(gemm_qkv_f16,
                         cudaFuncAttributeMaxDynamicSharedMemorySize, GEMM_SMEM3);
    cudaFuncSetAttribute(gemm_out_f16,
                         cudaFuncAttributeMaxDynamicSharedMemorySize, GEMM_SMEM3);
    cudaFuncSetAttribute(flash3_kernel,
                         cudaFuncAttributeMaxDynamicSharedMemorySize, FA3_SMEM);

    // Split prepasses
    const int NX4 = ROWS * D_MODEL / 4;       // 1M
    const int NW4 = D_MODEL * D_MODEL / 4;    // 256K
    split1_kernel<<<NX4 / 256, 256>>>(x,  xh,  NX4);
    split2_kernel<<<NW4 / 256, 256>>>(wq, wqh, wqm, NW4);
    split2_kernel<<<NW4 / 256, 256>>>(wk, wkh, wkm, NW4);
    split2_kernel<<<NW4 / 256, 256>>>(wv, wvh, wvm, NW4);
    split2_kernel<<<NW4 / 256, 256>>>(wo, woh, wom, NW4);

    // QKV projections (fp16x2 mma.sync)
    dim3 g1(D_MODEL / 128, ROWS / 128, 3);
    gemm_qkv_f16<<<g1, 256, GEMM_SMEM3>>>(xh, wqh, wqm, bq, q,
                                          wkh, wkm, bk, k, wvh, wvm, bv, v);

    // RoPE + fp16 split
    int rope_threads = ROWS * N_HEADS * 32;
    rope_split_kernel<<<rope_threads / 256, 256>>>(q, k, qh, kh, km);

    // V split + transpose
    v_split_t_kernel<<<dim3(SEQ / 64, BATCH * N_HEADS), 256>>>(v, vth, vtm);

    // Flash attention (fp16x2) — writes fp16 att hi directly
    flash3_kernel<<<dim3(SEQ / 128, BATCH * N_HEADS), 256, FA3_SMEM>>>(
        qh, kh, km, vth, vtm, mask, ath);

    // Output projection (fp16x2) -> d_out
    dim3 g3(D_MODEL / 128, ROWS / 128);
    gemm_out_f16<<<g3, 256, GEMM_SMEM3>>>(ath, woh, wom, bo, out);
}

// round 11
// speedup vs baseline: 4.7762x; 1.0117x over previous
#include <cuda_runtime.h>
#include <cuda_fp16.h>
#include <cstdint>
#include <math.h>

#define D_MODEL 1024
#define N_HEADS 16
#define HDIM    64
#define SEQ     2048
#define BATCH   2
#define ROWS    (BATCH * SEQ)   // 4096

// ---------------------------------------------------------------------------
// Scratch (static device globals — no allocation allowed)
// ---------------------------------------------------------------------------
__device__ float g_q[ROWS * D_MODEL];
__device__ float g_k[ROWS * D_MODEL];
__device__ float g_v[ROWS * D_MODEL];
__device__ float2 g_angtab[SEQ * 32];                         // (cos, sin)
__device__ __half g_qh[ROWS * D_MODEL];                       // Q hi only
__device__ __half g_kh[ROWS * D_MODEL];
__device__ __half g_km[ROWS * D_MODEL];
__device__ __half g_vth[BATCH * N_HEADS * HDIM * SEQ];        // [bh*64+d][s]
__device__ __half g_vtm[BATCH * N_HEADS * HDIM * SEQ];
__device__ __half g_xh[ROWS * D_MODEL];                       // X hi only
__device__ __half g_ath[ROWS * D_MODEL];                      // att hi only
__device__ __half g_wqh[D_MODEL * D_MODEL];
__device__ __half g_wqm[D_MODEL * D_MODEL];
__device__ __half g_wkh[D_MODEL * D_MODEL];
__device__ __half g_wkm[D_MODEL * D_MODEL];
__device__ __half g_wvh[D_MODEL * D_MODEL];
__device__ __half g_wvm[D_MODEL * D_MODEL];
__device__ __half g_woh[D_MODEL * D_MODEL];
__device__ __half g_wom[D_MODEL * D_MODEL];

// ---------------------------------------------------------------------------
// Helpers
// ---------------------------------------------------------------------------
__device__ __forceinline__ uint32_t smem_u32(const void* p) {
    uint32_t a;
    asm("{ .reg .u64 t; cvta.to.shared.u64 t, %1; cvt.u32.u64 %0, t; }"
        : "=r"(a) : "l"(p));
    return a;
}
__device__ __forceinline__ void cp_async16(uint32_t saddr, const void* gptr) {
    asm volatile("cp.async.cg.shared.global [%0], [%1], 16;"
                 :: "r"(saddr), "l"(gptr) : "memory");
}
__device__ __forceinline__ void cp_commit() {
    asm volatile("cp.async.commit_group;" ::: "memory");
}
template <int N>
__device__ __forceinline__ void cp_wait() {
    asm volatile("cp.async.wait_group %0;" :: "n"(N) : "memory");
}
__device__ __forceinline__ void mma_f16(float* d, const uint32_t* a,
                                        const uint32_t* b) {
    asm volatile(
        "mma.sync.aligned.m16n8k16.row.col.f32.f16.f16.f32 "
        "{%0,%1,%2,%3}, {%4,%5,%6,%7}, {%8,%9}, {%0,%1,%2,%3};"
        : "+f"(d[0]), "+f"(d[1]), "+f"(d[2]), "+f"(d[3])
        : "r"(a[0]), "r"(a[1]), "r"(a[2]), "r"(a[3]), "r"(b[0]), "r"(b[1]));
}
__device__ __forceinline__ void ldsm4(uint32_t* r, uint32_t addr) {
    asm volatile("ldmatrix.sync.aligned.m8n8.x4.shared.b16 {%0,%1,%2,%3}, [%4];"
                 : "=r"(r[0]), "=r"(r[1]), "=r"(r[2]), "=r"(r[3]) : "r"(addr));
}
__device__ __forceinline__ uint32_t pack_f16(float lo, float hi) {
    uint32_t r;
    asm("cvt.rn.f16x2.f32 %0, %1, %2;" : "=r"(r) : "f"(hi), "f"(lo));
    return r;
}

// FFMA-only exp, accurate ~1e-7 on [-87, 0]
__device__ __forceinline__ float fast_exp(float x) {
    x = fmaxf(x, -87.0f);
    float y = x * 1.4426950408889634f;
    float r = y + 12582912.0f;
    float n = r - 12582912.0f;
    float f = y - n;
    float t = f * 0.6931471805599453f;
    float p = 1.3888889e-3f;
    p = fmaf(p, t, 8.3333333e-3f);
    p = fmaf(p, t, 4.1666667e-2f);
    p = fmaf(p, t, 1.6666667e-1f);
    p = fmaf(p, t, 0.5f);
    p = fmaf(p, t, 1.0f);
    p = fmaf(p, t, 1.0f);
    int ni = __float_as_int(r) - 0x4B400000;
    float scale = __int_as_float((ni << 23) + 0x3F800000);
    return p * scale;
}

// ---------------------------------------------------------------------------
// RoPE angle table: tab[t*32+i] = (cos(t*inv_i), sin(t*inv_i))
// ---------------------------------------------------------------------------
__global__ __launch_bounds__(256)
void angtab_kernel(float2* __restrict__ tab)
{
    int idx = blockIdx.x * blockDim.x + threadIdx.x;   // 0..65535
    int t = idx >> 5;
    int i = idx & 31;
    float inv = 1.0f / powf(10000.0f, (float)(2 * i) * (1.0f / 64.0f));
    float ang = (float)t * inv;
    float sn, cs;
    sincosf(ang, &sn, &cs);
    tab[idx] = make_float2(cs, sn);
}

// ---------------------------------------------------------------------------
// Fused weight split: all 4 weight matrices, 2 float4 units per thread.
// ---------------------------------------------------------------------------
#define W_UNITS (D_MODEL * D_MODEL / 4)    // 262144 float4 units per matrix

__global__ __launch_bounds__(256)
void split_w4_kernel(const float* __restrict__ w0, const float* __restrict__ w1,
                     const float* __restrict__ w2, const float* __restrict__ w3,
                     __half* __restrict__ h0, __half* __restrict__ m0,
                     __half* __restrict__ h1, __half* __restrict__ m1,
                     __half* __restrict__ h2, __half* __restrict__ m2,
                     __half* __restrict__ h3, __half* __restrict__ m3)
{
    int idx = blockIdx.x * blockDim.x + threadIdx.x;   // 0..524287
    int u   = idx * 2;                                  // first float4 unit
    int mat = u >> 18;                                  // /262144
    int rem = u & (W_UNITS - 1);
    const float* src; __half *hh, *mm;
    if (mat == 0)      { src = w0; hh = h0; mm = m0; }
    else if (mat == 1) { src = w1; hh = h1; mm = m1; }
    else if (mat == 2) { src = w2; hh = h2; mm = m2; }
    else               { src = w3; hh = h3; mm = m3; }
#pragma unroll
    for (int j = 0; j < 2; j++) {
        int o = rem + j;
        float4 x = *(const float4*)(src + o * 4);
        __half ha = __float2half_rn(x.x);
        __half hb = __float2half_rn(x.y);
        __half hc = __float2half_rn(x.z);
        __half hd = __float2half_rn(x.w);
        __half2* hp = (__half2*)(hh + o * 4);
        hp[0] = __half2(ha, hb);
        hp[1] = __half2(hc, hd);
        __half2* mp = (__half2*)(mm + o * 4);
        mp[0] = __half2(__float2half_rn(x.x - __half2float(ha)),
                        __float2half_rn(x.y - __half2float(hb)));
        mp[1] = __half2(__float2half_rn(x.z - __half2float(hc)),
                        __float2half_rn(x.w - __half2float(hd)));
    }
}

// X split (hi only), 2 float4 units per thread.
__global__ __launch_bounds__(256)
void split1_kernel(const float* __restrict__ src, __half* __restrict__ h, int n4)
{
    int idx = blockIdx.x * blockDim.x + threadIdx.x;
#pragma unroll
    for (int j = 0; j < 2; j++) {
        int o = idx * 2 + j;
        if (o >= n4) return;
        float4 x = *(const float4*)(src + o * 4);
        __half2* hp = (__half2*)(h + o * 4);
        hp[0] = __half2(__float2half_rn(x.x), __float2half_rn(x.y));
        hp[1] = __half2(__float2half_rn(x.z), __float2half_rn(x.w));
    }
}

// ---------------------------------------------------------------------------
// fp16x2 GEMM (validated round 10): C = A @ W^T + bias; terms ah*wh + ah*wm.
// ---------------------------------------------------------------------------
#define BK2      32
#define NCH2     (D_MODEL / BK2)       // 32 chunks
#define TILE_W2  (128 * 16)            // 2048 words per tile
#define TILE_B2  (TILE_W2 * 4)         // 8192 bytes
#define STAGE_W3 (3 * TILE_W2)         // Ah, Wh, Wm
#define GEMM_SMEM3 (3 * STAGE_W3 * 4)  // 73728 bytes

__device__ __forceinline__ int swz(int r, int w) {
    return r * 16 + (w ^ (((r >> 1) & 3) << 2));
}

__device__ __forceinline__ void stage_chunk3(
    const __half* __restrict__ Ah, const __half* __restrict__ Wh,
    const __half* __restrict__ Wm,
    uint32_t sbase, int buf, int k0, int tid)
{
    const __half* src[3] = { Ah, Wh, Wm };
    uint32_t s0 = sbase + buf * STAGE_W3 * 4;
#pragma unroll
    for (int i = 0; i < 6; i++) {
        int idx  = tid + i * 256;
        int tile = idx / 512;
        int wi   = idx & 511;
        int r    = wi >> 2;
        int ch   = wi & 3;
        cp_async16(s0 + (tile * TILE_W2 + swz(r, ch * 4)) * 4,
                   src[tile] + r * D_MODEL + k0 + ch * 8);
    }
    cp_commit();
}

__device__ __forceinline__ void gemm_f16_body(
    const __half* __restrict__ Ah, const __half* __restrict__ Wh,
    const __half* __restrict__ Wm,
    const float* __restrict__ bias, float* __restrict__ C)
{
    extern __shared__ uint32_t smw[];
    const uint32_t sbase = smem_u32(smw);
    const int tid  = threadIdx.x;
    const int wid  = tid >> 5;
    const int lane = tid & 31;
    const int wm_  = (wid & 1) * 64;
    const int wn   = (wid >> 1) * 32;
    const int brow = blockIdx.y * 128;
    const int bcol = blockIdx.x * 128;
    const int g    = lane >> 2;
    const int t    = lane & 3;
    const int lrow16 = lane & 15;
    const int lrow8  = lane & 7;
    const int half_  = lane >> 4;
    const int midbit = (lane >> 3) & 1;

    uint32_t aoff[4][2], boff[2][2];
#pragma unroll
    for (int mf = 0; mf < 4; mf++)
#pragma unroll
        for (int ks = 0; ks < 2; ks++) {
            int row = wm_ + mf * 16 + lrow16;
            int ch  = ks * 2 + half_;
            aoff[mf][ks] = (uint32_t)((row * 16 +
                ((ch * 4) ^ (((row >> 1) & 3) << 2))) * 4);
        }
#pragma unroll
    for (int p = 0; p < 2; p++)
#pragma unroll
        for (int ks = 0; ks < 2; ks++) {
            int row = wn + (2 * p + half_) * 8 + lrow8;
            int ch  = ks * 2 + midbit;
            boff[p][ks] = (uint32_t)((row * 16 +
                ((ch * 4) ^ (((row >> 1) & 3) << 2))) * 4);
        }

    float acc[4][4][4];
#pragma unroll
    for (int mf = 0; mf < 4; mf++)
#pragma unroll
        for (int nf = 0; nf < 4; nf++)
#pragma unroll
            for (int r = 0; r < 4; r++) acc[mf][nf][r] = 0.0f;

    const __half* Ah_r = Ah + brow * D_MODEL;
    const __half* Wh_r = Wh + bcol * D_MODEL;
    const __half* Wm_r = Wm + bcol * D_MODEL;

    stage_chunk3(Ah_r, Wh_r, Wm_r, sbase, 0, 0, tid);
    stage_chunk3(Ah_r, Wh_r, Wm_r, sbase, 1, BK2, tid);

    int buf = 0;
    for (int c = 0; c < NCH2; c++) {
        if (c < NCH2 - 1) cp_wait<1>(); else cp_wait<0>();
        __syncthreads();
        if (c + 2 < NCH2) {
            int nb = buf + 2; if (nb >= 3) nb -= 3;
            stage_chunk3(Ah_r, Wh_r, Wm_r, sbase, nb, (c + 2) * BK2, tid);
        }

        const uint32_t sb0 = sbase + buf * (STAGE_W3 * 4);

#pragma unroll
        for (int ks = 0; ks < 2; ks++) {
            uint32_t ah[4][4];
#pragma unroll
            for (int mf = 0; mf < 4; mf++)
                ldsm4(ah[mf], sb0 + aoff[mf][ks]);
#pragma unroll
            for (int p = 0; p < 2; p++) {
                uint32_t bh4[4], bm4[4];
                ldsm4(bh4, sb0 + TILE_B2 + boff[p][ks]);
                ldsm4(bm4, sb0 + 2 * TILE_B2 + boff[p][ks]);
#pragma unroll
                for (int qq = 0; qq < 2; qq++) {
                    const int nf = 2 * p + qq;
                    uint32_t bh[2] = { bh4[2 * qq], bh4[2 * qq + 1] };
                    uint32_t bm[2] = { bm4[2 * qq], bm4[2 * qq + 1] };
#pragma unroll
                    for (int mf = 0; mf < 4; mf++) {
                        mma_f16(acc[mf][nf], ah[mf], bm);
                        mma_f16(acc[mf][nf], ah[mf], bh);
                    }
                }
            }
        }
        buf++; if (buf >= 3) buf = 0;
    }

#pragma unroll
    for (int mf = 0; mf < 4; mf++) {
        int row0 = brow + wm_ + mf * 16 + g;
#pragma unroll
        for (int nf = 0; nf < 4; nf++) {
            int col = bcol + wn + nf * 8 + 2 * t;
            float b0 = bias[col], b1 = bias[col + 1];
            float2 v0 = make_float2(acc[mf][nf][0] + b0, acc[mf][nf][1] + b1);
            float2 v1 = make_float2(acc[mf][nf][2] + b0, acc[mf][nf][3] + b1);
            *(float2*)(C + row0 * D_MODEL + col)       = v0;
            *(float2*)(C + (row0 + 8) * D_MODEL + col) = v1;
        }
    }
}

__global__ __launch_bounds__(256)
void gemm_qkv_f16(const __half* __restrict__ Xh,
                  const __half* __restrict__ Wqh, const __half* __restrict__ Wqm,
                  const float* __restrict__ Bq, float* __restrict__ Oq,
                  const __half* __restrict__ Wkh, const __half* __restrict__ Wkm,
                  const float* __restrict__ Bk, float* __restrict__ Ok,
                  const __half* __restrict__ Wvh, const __half* __restrict__ Wvm,
                  const float* __restrict__ Bv, float* __restrict__ Ov)
{
    const __half *Wh, *Wm; const float* bb; float* C;
    if (blockIdx.z == 0)      { Wh = Wqh; Wm = Wqm; bb = Bq; C = Oq; }
    else if (blockIdx.z == 1) { Wh = Wkh; Wm = Wkm; bb = Bk; C = Ok; }
    else                      { Wh = Wvh; Wm = Wvm; bb = Bv; C = Ov; }
    gemm_f16_body(Xh, Wh, Wm, bb, C);
}

__global__ __launch_bounds__(256)
void gemm_out_f16(const __half* __restrict__ Ah,
                  const __half* __restrict__ Wh, const __half* __restrict__ Wm,
                  const float* __restrict__ bb, float* __restrict__ C)
{
    gemm_f16_body(Ah, Wh, Wm, bb, C);
}

// ---------------------------------------------------------------------------
// RoPE + split, table-based, 4 freq pairs per thread.
// q -> fp16 hi; k -> fp16 hi/mid.
// ---------------------------------------------------------------------------
__global__ __launch_bounds__(256)
void rope_split_kernel(const float* __restrict__ q, const float* __restrict__ k,
                       const float2* __restrict__ tab,
                       __half* __restrict__ qh,
                       __half* __restrict__ kh, __half* __restrict__ km)
{
    int idx = blockIdx.x * blockDim.x + threadIdx.x;   // 0..524287
    int i4  = idx & 7;                 // freq group (4 freqs)
    int h   = (idx >> 3) & (N_HEADS - 1);
    int row = idx >> 7;
    int t   = row & (SEQ - 1);

    int base = row * D_MODEL + h * HDIM + i4 * 4;
    float4 qa = *(const float4*)(q + base);
    float4 qb = *(const float4*)(q + base + 32);
    float4 ka = *(const float4*)(k + base);
    float4 kb = *(const float4*)(k + base + 32);
    const float2* tp = tab + (t << 5) + i4 * 4;

    float qr_a[4], qr_b[4], kr_a[4], kr_b[4];
    float qa_[4] = { qa.x, qa.y, qa.z, qa.w };
    float qb_[4] = { qb.x, qb.y, qb.z, qb.w };
    float ka_[4] = { ka.x, ka.y, ka.z, ka.w };
    float kb_[4] = { kb.x, kb.y, kb.z, kb.w };
#pragma unroll
    for (int j = 0; j < 4; j++) {
        float2 cs = tp[j];
        qr_a[j] = qa_[j] * cs.x - qb_[j] * cs.y;
        qr_b[j] = qb_[j] * cs.x + qa_[j] * cs.y;
        kr_a[j] = ka_[j] * cs.x - kb_[j] * cs.y;
        kr_b[j] = kb_[j] * cs.x + ka_[j] * cs.y;
    }

    // q hi
    *(uint2*)(qh + base)      = make_uint2(pack_f16(qr_a[0], qr_a[1]),
                                           pack_f16(qr_a[2], qr_a[3]));
    *(uint2*)(qh + base + 32) = make_uint2(pack_f16(qr_b[0], qr_b[1]),
                                           pack_f16(qr_b[2], qr_b[3]));
    // k hi + mid
    __half kha[4], khb[4];
#pragma unroll
    for (int j = 0; j < 4; j++) { kha[j] = __float2half_rn(kr_a[j]); khb[j] = __float2half_rn(kr_b[j]); }
    *(uint2*)(kh + base)      = make_uint2(
        __float_as_uint(0), 0);  // placeholder overwritten below
    // write hi
    ((__half2*)(kh + base))[0]      = __half2(kha[0], kha[1]);
    ((__half2*)(kh + base))[1]      = __half2(kha[2], kha[3]);
    ((__half2*)(kh + base + 32))[0] = __half2(khb[0], khb[1]);
    ((__half2*)(kh + base + 32))[1] = __half2(khb[2], khb[3]);
    // mid
    ((__half2*)(km + base))[0]      = __half2(__float2half_rn(kr_a[0] - __half2float(kha[0])),
                                              __float2half_rn(kr_a[1] - __half2float(kha[1])));
    ((__half2*)(km + base))[1]      = __half2(__float2half_rn(kr_a[2] - __half2float(kha[2])),
                                              __float2half_rn(kr_a[3] - __half2float(kha[3])));
    ((__half2*)(km + base + 32))[0] = __half2(__float2half_rn(kr_b[0] - __half2float(khb[0])),
                                              __float2half_rn(kr_b[1] - __half2float(khb[1])));
    ((__half2*)(km + base + 32))[1] = __half2(__float2half_rn(kr_b[2] - __half2float(khb[2])),
                                              __float2half_rn(kr_b[3] - __half2float(khb[3])));
}

// ---------------------------------------------------------------------------
// V split + transpose: fp32 [b*S+s][h*64+d] -> vT fp16 hi/mid [(bh*64)+d][s]
// ---------------------------------------------------------------------------
__global__ __launch_bounds__(256)
void v_split_t_kernel(const float* __restrict__ v,
                      __half* __restrict__ vth, __half* __restrict__ vtm)
{
    __shared__ __half th[64][66];
    __shared__ __half tm[64][66];
    const int tid = threadIdx.x;
    const int st  = blockIdx.x;
    const int bh  = blockIdx.y;
    const int b   = bh >> 4;
    const int h   = bh & 15;
    const int s0  = st * 64;

#pragma unroll
    for (int l = 0; l < 16; l++) {
        int e = l * 256 + tid;
        int r = e >> 6, d = e & 63;
        float x = v[(b * SEQ + s0 + r) * D_MODEL + h * HDIM + d];
        __half hv = __float2half_rn(x);
        th[d][r] = hv;
        tm[d][r] = __float2half_rn(x - __half2float(hv));
    }
    __syncthreads();
#pragma unroll
    for (int l = 0; l < 16; l++) {
        int e = l * 256 + tid;
        int d = e >> 6, sc = e & 63;
        int o = (bh * HDIM + d) * SEQ + s0 + sc;
        vth[o] = th[d][sc];
        vtm[o] = tm[d][sc];
    }
}

// ---------------------------------------------------------------------------
// Flash attention, fp16x2 mma.sync + ldmatrix (validated round 10).
// ---------------------------------------------------------------------------
#define NT        (SEQ / 64)
#define FL_QH     0
#define FL_STG    18432
#define FL_SSZ    37120
#define FL_KH(s)  (FL_STG + (s) * FL_SSZ)
#define FL_KM(s)  (FL_STG + (s) * FL_SSZ + 9216)
#define FL_VH(s)  (FL_STG + (s) * FL_SSZ + 18432)
#define FL_VM(s)  (FL_STG + (s) * FL_SSZ + 27648)
#define FL_MS(s)  (FL_STG + (s) * FL_SSZ + 36864)
#define FA3_SMEM  (FL_STG + 2 * FL_SSZ)   // 92672

__global__ __launch_bounds__(256)
void flash3_kernel(const __half* __restrict__ Qh,
                   const __half* __restrict__ Kh, const __half* __restrict__ Km,
                   const __half* __restrict__ Vth, const __half* __restrict__ Vtm,
                   const float* __restrict__ mask,
                   __half* __restrict__ Oh)
{
    extern __shared__ char sm2[];
    const int tid  = threadIdx.x;
    const int w    = tid >> 5;
    const int lane = tid & 31;
    const int g    = lane >> 2;
    const int t    = lane & 3;
    const int qt   = blockIdx.x;
    const int bh   = blockIdx.y;
    const int b    = bh >> 4;
    const int h    = bh & 15;
    const uint32_t sbase = smem_u32(sm2);
    const int lrow16 = lane & 15;
    const int lrow8  = lane & 7;
    const int half_  = lane >> 4;
    const int midbit = (lane >> 3) & 1;

    uint32_t qoff[4], koff[4][4];
#pragma unroll
    for (int ks = 0; ks < 4; ks++)
        qoff[ks] = (uint32_t)((w * 16 + lrow16) * 144 + (ks * 2 + half_) * 16);
#pragma unroll
    for (int p = 0; p < 4; p++)
#pragma unroll
        for (int ks = 0; ks < 4; ks++)
            koff[p][ks] = (uint32_t)(((2 * p + half_) * 8 + lrow8) * 144 +
                                     (ks * 2 + midbit) * 16);

    const __half* qh_g = Qh + (b * SEQ + qt * 128) * D_MODEL + h * HDIM;
    const __half* kh_g = Kh + b * SEQ * D_MODEL + h * HDIM;
    const __half* km_g = Km + b * SEQ * D_MODEL + h * HDIM;
    const __half* vh_g = Vth + bh * HDIM * SEQ;
    const __half* vm_g = Vtm + bh * HDIM * SEQ;
    const float* mask_g = mask + b * SEQ;

    auto stage = [&](int kt, int s) {
#pragma unroll
        for (int i = 0; i < 2; i++) {
            int idx = tid + i * 256;
            int r   = idx >> 3;
            int ch  = idx & 7;
            cp_async16(sbase + FL_KH(s) + r * 144 + ch * 16,
                       kh_g + (kt * 64 + r) * D_MODEL + ch * 8);
            cp_async16(sbase + FL_KM(s) + r * 144 + ch * 16,
                       km_g + (kt * 64 + r) * D_MODEL + ch * 8);
            cp_async16(sbase + FL_VH(s) + r * 144 + ch * 16,
                       vh_g + r * SEQ + kt * 64 + ch * 8);
            cp_async16(sbase + FL_VM(s) + r * 144 + ch * 16,
                       vm_g + r * SEQ + kt * 64 + ch * 8);
        }
        if (tid < 16)
            cp_async16(sbase + FL_MS(s) + tid * 16, mask_g + kt * 64 + tid * 4);
    };

#pragma unroll
    for (int i = 0; i < 2; i++) {
        int idx = tid + i * 256;
        int r   = idx >> 2;
        int ch  = (idx & 3) * 2;
        cp_async16(sbase + FL_QH + r * 144 + ch * 16, qh_g + r * D_MODEL + ch * 8);
        cp_async16(sbase + FL_QH + r * 144 + (ch + 1) * 16, qh_g + r * D_MODEL + (ch + 1) * 8);
    }
    stage(0, 0);
    cp_commit();

    float o[8][4];
#pragma unroll
    for (int nf = 0; nf < 8; nf++)
#pragma unroll
        for (int j = 0; j < 4; j++) o[nf][j] = 0.0f;
    float m0 = -1e30f, m1 = -1e30f, l0 = 0.0f, l1 = 0.0f;

    for (int kt = 0; kt < NT; kt++) {
        const int s = kt & 1;
        if (kt + 1 < NT) { stage(kt + 1, s ^ 1); cp_commit(); cp_wait<1>(); }
        else             { cp_wait<0>(); }
        __syncthreads();

        float sc[8][4];
#pragma unroll
        for (int nf = 0; nf < 8; nf++)
#pragma unroll
            for (int j = 0; j < 4; j++) sc[nf][j] = 0.0f;

#pragma unroll
        for (int ks = 0; ks < 4; ks++) {
            uint32_t ah[4];
            ldsm4(ah, sbase + FL_QH + qoff[ks]);
#pragma unroll
            for (int p = 0; p < 4; p++) {
                uint32_t bh4[4], bm4[4];
                ldsm4(bh4, sbase + FL_KH(s) + koff[p][ks]);
                ldsm4(bm4, sbase + FL_KM(s) + koff[p][ks]);
#pragma unroll
                for (int qq = 0; qq < 2; qq++) {
                    const int nf = 2 * p + qq;
                    uint32_t bhf[2] = { bh4[2 * qq], bh4[2 * qq + 1] };
                    uint32_t bmf[2] = { bm4[2 * qq], bm4[2 * qq + 1] };
                    mma_f16(sc[nf], ah, bmf);
                    mma_f16(sc[nf], ah, bhf);
                }
            }
        }

        float rmax0 = -1e30f, rmax1 = -1e30f;
#pragma unroll
        for (int nf = 0; nf < 8; nf++) {
            float2 mk = *(const float2*)(sm2 + FL_MS(s) + (nf * 8 + 2 * t) * 4);
            sc[nf][0] = fmaf(sc[nf][0], 0.125f, mk.x);
            sc[nf][1] = fmaf(sc[nf][1], 0.125f, mk.y);
            sc[nf][2] = fmaf(sc[nf][2], 0.125f, mk.x);
            sc[nf][3] = fmaf(sc[nf][3], 0.125f, mk.y);
            rmax0 = fmaxf(rmax0, fmaxf(sc[nf][0], sc[nf][1]));
            rmax1 = fmaxf(rmax1, fmaxf(sc[nf][2], sc[nf][3]));
        }
        rmax0 = fmaxf(rmax0, __shfl_xor_sync(0xffffffffu, rmax0, 1));
        rmax0 = fmaxf(rmax0, __shfl_xor_sync(0xffffffffu, rmax0, 2));
        rmax1 = fmaxf(rmax1, __shfl_xor_sync(0xffffffffu, rmax1, 1));
        rmax1 = fmaxf(rmax1, __shfl_xor_sync(0xffffffffu, rmax1, 2));
        float mn0 = fmaxf(m0, rmax0), mn1 = fmaxf(m1, rmax1);
        float c0 = fast_exp(m0 - mn0), c1 = fast_exp(m1 - mn1);
        float sum0 = 0.0f, sum1 = 0.0f;
#pragma unroll
        for (int nf = 0; nf < 8; nf++) {
            sc[nf][0] = fast_exp(sc[nf][0] - mn0);
            sc[nf][1] = fast_exp(sc[nf][1] - mn0);
            sc[nf][2] = fast_exp(sc[nf][2] - mn1);
            sc[nf][3] = fast_exp(sc[nf][3] - mn1);
            sum0 += sc[nf][0] + sc[nf][1];
            sum1 += sc[nf][2] + sc[nf][3];
        }
        sum0 += __shfl_xor_sync(0xffffffffu, sum0, 1);
        sum0 += __shfl_xor_sync(0xffffffffu, sum0, 2);
        sum1 += __shfl_xor_sync(0xffffffffu, sum1, 1);
        sum1 += __shfl_xor_sync(0xffffffffu, sum1, 2);
        l0 = l0 * c0 + sum0;
        l1 = l1 * c1 + sum1;
        m0 = mn0; m1 = mn1;
#pragma unroll
        for (int nf = 0; nf < 8; nf++) {
            o[nf][0] *= c0; o[nf][1] *= c0;
            o[nf][2] *= c1; o[nf][3] *= c1;
        }

#pragma unroll
        for (int ks = 0; ks < 4; ks++) {
            uint32_t ph[4];
            ph[0] = pack_f16(sc[2 * ks][0],     sc[2 * ks][1]);
            ph[1] = pack_f16(sc[2 * ks][2],     sc[2 * ks][3]);
            ph[2] = pack_f16(sc[2 * ks + 1][0], sc[2 * ks + 1][1]);
            ph[3] = pack_f16(sc[2 * ks + 1][2], sc[2 * ks + 1][3]);
#pragma unroll
            for (int p = 0; p < 4; p++) {
                uint32_t bh4[4], bm4[4];
                ldsm4(bh4, sbase + FL_VH(s) + koff[p][ks]);
                ldsm4(bm4, sbase + FL_VM(s) + koff[p][ks]);
#pragma unroll
                for (int qq = 0; qq < 2; qq++) {
                    const int nf = 2 * p + qq;
                    uint32_t bhf[2] = { bh4[2 * qq], bh4[2 * qq + 1] };
                    uint32_t bmf[2] = { bm4[2 * qq], bm4[2 * qq + 1] };
                    mma_f16(o[nf], ph, bmf);
                    mma_f16(o[nf], ph, bhf);
                }
            }
        }
        __syncthreads();
    }

    float i0 = 1.0f / l0, i1 = 1.0f / l1;
    int row0 = b * SEQ + qt * 128 + w * 16 + g;
    int colb = h * HDIM + 2 * t;
#pragma unroll
    for (int nf = 0; nf < 8; nf++) {
        uint32_t hw0 = pack_f16(o[nf][0] * i0, o[nf][1] * i0);
        uint32_t hw1 = pack_f16(o[nf][2] * i1, o[nf][3] * i1);
        *(uint32_t*)(Oh + row0 * D_MODEL + colb + nf * 8)       = hw0;
        *(uint32_t*)(Oh + (row0 + 8) * D_MODEL + colb + nf * 8) = hw1;
    }
}

// ---------------------------------------------------------------------------
// Launch
// ---------------------------------------------------------------------------
extern "C" void kernel_launch(void* const* d_in, const int* in_sizes, int n_in,
                              void* d_out, int out_size)
{
    const float* x    = (const float*)d_in[0];
    const float* wq   = (const float*)d_in[1];
    const float* bq   = (const float*)d_in[2];
    const float* wk   = (const float*)d_in[3];
    const float* bk   = (const float*)d_in[4];
    const float* wv   = (const float*)d_in[5];
    const float* bv   = (const float*)d_in[6];
    const float* wo   = (const float*)d_in[7];
    const float* bo   = (const float*)d_in[8];
    const float* mask = (const float*)d_in[9];
    float* out = (float*)d_out;

    float *q, *k, *v;
    float2* angtab;
    __half *qh, *kh, *km, *vth, *vtm, *xh, *ath;
    __half *wqh, *wqm, *wkh, *wkm, *wvh, *wvm, *woh, *wom;
    cudaGetSymbolAddress((void**)&q,      g_q);
    cudaGetSymbolAddress((void**)&k,      g_k);
    cudaGetSymbolAddress((void**)&v,      g_v);
    cudaGetSymbolAddress((void**)&angtab, g_angtab);
    cudaGetSymbolAddress((void**)&qh,  g_qh);
    cudaGetSymbolAddress((void**)&kh,  g_kh);
    cudaGetSymbolAddress((void**)&km,  g_km);
    cudaGetSymbolAddress((void**)&vth, g_vth);
    cudaGetSymbolAddress((void**)&vtm, g_vtm);
    cudaGetSymbolAddress((void**)&xh,  g_xh);
    cudaGetSymbolAddress((void**)&ath, g_ath);
    cudaGetSymbolAddress((void**)&wqh, g_wqh);
    cudaGetSymbolAddress((void**)&wqm, g_wqm);
    cudaGetSymbolAddress((void**)&wkh, g_wkh);
    cudaGetSymbolAddress((void**)&wkm, g_wkm);
    cudaGetSymbolAddress((void**)&wvh, g_wvh);
    cudaGetSymbolAddress((void**)&wvm, g_wvm);
    cudaGetSymbolAddress((void**)&woh, g_woh);
    cudaGetSymbolAddress((void**)&wom, g_wom);

    cudaFuncSetAttribute(gemm_qkv_f16,
                         cudaFuncAttributeMaxDynamicSharedMemorySize, GEMM_SMEM3);
    cudaFuncSetAttribute(gemm_out_f16,
                         cudaFuncAttributeMaxDynamicSharedMemorySize, GEMM_SMEM3);
    cudaFuncSetAttribute(flash3_kernel,
                         cudaFuncAttributeMaxDynamicSharedMemorySize, FA3_SMEM);

    // Prepasses
    const int NX4 = ROWS * D_MODEL / 4;       // 1M float4 units
    angtab_kernel<<<SEQ * 32 / 256, 256>>>(angtab);
    split_w4_kernel<<<(4 * W_UNITS / 2) / 256, 256>>>(
        wq, wk, wv, wo, wqh, wqm, wkh, wkm, wvh, wvm, woh, wom);
    split1_kernel<<<(NX4 / 2) / 256, 256>>>(x, xh, NX4);

    // QKV projections (fp16x2 mma.sync)
    dim3 g1(D_MODEL / 128, ROWS / 128, 3);
    gemm_qkv_f16<<<g1, 256, GEMM_SMEM3>>>(xh, wqh, wqm, bq, q,
                                          wkh, wkm, bk, k, wvh, wvm, bv, v);

    // RoPE (table) + fp16 split
    int rope_items = ROWS * N_HEADS * 8;      // 4 freq pairs per thread
    rope_split_kernel<<<rope_items / 256, 256>>>(q, k, angtab, qh, kh, km);

    // V split + transpose
    v_split_t_kernel<<<dim3(SEQ / 64, BATCH * N_HEADS), 256>>>(v, vth, vtm);

    // Flash attention (fp16x2) — writes fp16 att hi directly
    flash3_kernel<<<dim3(SEQ / 128, BATCH * N_HEADS), 256, FA3_SMEM>>>(
        qh, kh, km, vth, vtm, mask, ath);

    // Output projection (fp16x2) -> d_out
    dim3 g3(D_MODEL / 128, ROWS / 128);
    gemm_out_f16<<<g3, 256, GEMM_SMEM3>>>(ath, woh, wom, bo, out);
}

// round 12
// speedup vs baseline: 5.7180x; 1.1972x over previous
#include <cuda_runtime.h>
#include <cuda_fp16.h>
#include <cstdint>
#include <math.h>

#define D_MODEL 1024
#define N_HEADS 16
#define HDIM    64
#define SEQ     2048
#define BATCH   2
#define ROWS    (BATCH * SEQ)   // 4096

// ---------------------------------------------------------------------------
// Scratch (static device globals — no allocation allowed)
// ---------------------------------------------------------------------------
__device__ float g_q[ROWS * D_MODEL];
__device__ float g_k[ROWS * D_MODEL];
__device__ float g_v[ROWS * D_MODEL];
__device__ float2 g_angtab[SEQ * 32];                         // (cos, sin)
__device__ __half g_qh[ROWS * D_MODEL];                       // Q hi
__device__ __half g_kh[ROWS * D_MODEL];                       // K hi
__device__ __half g_vth[BATCH * N_HEADS * HDIM * SEQ];        // V^T hi [bh*64+d][s]
__device__ __half g_xh[ROWS * D_MODEL];                       // X hi
__device__ __half g_ath[ROWS * D_MODEL];                      // att hi
__device__ __half g_wqh[D_MODEL * D_MODEL];
__device__ __half g_wqm[D_MODEL * D_MODEL];
__device__ __half g_wkh[D_MODEL * D_MODEL];
__device__ __half g_wkm[D_MODEL * D_MODEL];
__device__ __half g_wvh[D_MODEL * D_MODEL];
__device__ __half g_wvm[D_MODEL * D_MODEL];
__device__ __half g_woh[D_MODEL * D_MODEL];
__device__ __half g_wom[D_MODEL * D_MODEL];

// ---------------------------------------------------------------------------
// Helpers
// ---------------------------------------------------------------------------
__device__ __forceinline__ uint32_t smem_u32(const void* p) {
    uint32_t a;
    asm("{ .reg .u64 t; cvta.to.shared.u64 t, %1; cvt.u32.u64 %0, t; }"
        : "=r"(a) : "l"(p));
    return a;
}
__device__ __forceinline__ void cp_async16(uint32_t saddr, const void* gptr) {
    asm volatile("cp.async.cg.shared.global [%0], [%1], 16;"
                 :: "r"(saddr), "l"(gptr) : "memory");
}
__device__ __forceinline__ void cp_commit() {
    asm volatile("cp.async.commit_group;" ::: "memory");
}
template <int N>
__device__ __forceinline__ void cp_wait() {
    asm volatile("cp.async.wait_group %0;" :: "n"(N) : "memory");
}
__device__ __forceinline__ void mma_f16(float* d, const uint32_t* a,
                                        const uint32_t* b) {
    asm volatile(
        "mma.sync.aligned.m16n8k16.row.col.f32.f16.f16.f32 "
        "{%0,%1,%2,%3}, {%4,%5,%6,%7}, {%8,%9}, {%0,%1,%2,%3};"
        : "+f"(d[0]), "+f"(d[1]), "+f"(d[2]), "+f"(d[3])
        : "r"(a[0]), "r"(a[1]), "r"(a[2]), "r"(a[3]), "r"(b[0]), "r"(b[1]));
}
__device__ __forceinline__ void ldsm4(uint32_t* r, uint32_t addr) {
    asm volatile("ldmatrix.sync.aligned.m8n8.x4.shared.b16 {%0,%1,%2,%3}, [%4];"
                 : "=r"(r[0]), "=r"(r[1]), "=r"(r[2]), "=r"(r[3]) : "r"(addr));
}
__device__ __forceinline__ uint32_t pack_f16(float lo, float hi) {
    uint32_t r;
    asm("cvt.rn.f16x2.f32 %0, %1, %2;" : "=r"(r) : "f"(hi), "f"(lo));
    return r;
}

// FFMA-only exp, accurate ~1e-7 on [-87, 0]
__device__ __forceinline__ float fast_exp(float x) {
    x = fmaxf(x, -87.0f);
    float y = x * 1.4426950408889634f;
    float r = y + 12582912.0f;
    float n = r - 12582912.0f;
    float f = y - n;
    float t = f * 0.6931471805599453f;
    float p = 1.3888889e-3f;
    p = fmaf(p, t, 8.3333333e-3f);
    p = fmaf(p, t, 4.1666667e-2f);
    p = fmaf(p, t, 1.6666667e-1f);
    p = fmaf(p, t, 0.5f);
    p = fmaf(p, t, 1.0f);
    p = fmaf(p, t, 1.0f);
    int ni = __float_as_int(r) - 0x4B400000;
    float scale = __int_as_float((ni << 23) + 0x3F800000);
    return p * scale;
}

// ---------------------------------------------------------------------------
// RoPE angle table
// ---------------------------------------------------------------------------
__global__ __launch_bounds__(256)
void angtab_kernel(float2* __restrict__ tab)
{
    int idx = blockIdx.x * blockDim.x + threadIdx.x;
    int t = idx >> 5;
    int i = idx & 31;
    float inv = 1.0f / powf(10000.0f, (float)(2 * i) * (1.0f / 64.0f));
    float ang = (float)t * inv;
    float sn, cs;
    sincosf(ang, &sn, &cs);
    tab[idx] = make_float2(cs, sn);
}

// ---------------------------------------------------------------------------
// Weight split (hi + mid), fused over the 4 matrices.
// ---------------------------------------------------------------------------
#define W_UNITS (D_MODEL * D_MODEL / 4)

__global__ __launch_bounds__(256)
void split_w4_kernel(const float* __restrict__ w0, const float* __restrict__ w1,
                     const float* __restrict__ w2, const float* __restrict__ w3,
                     __half* __restrict__ h0, __half* __restrict__ m0,
                     __half* __restrict__ h1, __half* __restrict__ m1,
                     __half* __restrict__ h2, __half* __restrict__ m2,
                     __half* __restrict__ h3, __half* __restrict__ m3)
{
    int idx = blockIdx.x * blockDim.x + threadIdx.x;
    int u   = idx * 2;
    int mat = u >> 18;
    int rem = u & (W_UNITS - 1);
    const float* src; __half *hh, *mm;
    if (mat == 0)      { src = w0; hh = h0; mm = m0; }
    else if (mat == 1) { src = w1; hh = h1; mm = m1; }
    else if (mat == 2) { src = w2; hh = h2; mm = m2; }
    else               { src = w3; hh = h3; mm = m3; }
#pragma unroll
    for (int j = 0; j < 2; j++) {
        int o = rem + j;
        float4 x = *(const float4*)(src + o * 4);
        __half ha = __float2half_rn(x.x);
        __half hb = __float2half_rn(x.y);
        __half hc = __float2half_rn(x.z);
        __half hd = __float2half_rn(x.w);
        __half2* hp = (__half2*)(hh + o * 4);
        hp[0] = __half2(ha, hb);
        hp[1] = __half2(hc, hd);
        __half2* mp = (__half2*)(mm + o * 4);
        mp[0] = __half2(__float2half_rn(x.x - __half2float(ha)),
                        __float2half_rn(x.y - __half2float(hb)));
        mp[1] = __half2(__float2half_rn(x.z - __half2float(hc)),
                        __float2half_rn(x.w - __half2float(hd)));
    }
}

// X split (hi only)
__global__ __launch_bounds__(256)
void split1_kernel(const float* __restrict__ src, __half* __restrict__ h, int n4)
{
    int idx = blockIdx.x * blockDim.x + threadIdx.x;
#pragma unroll
    for (int j = 0; j < 2; j++) {
        int o = idx * 2 + j;
        if (o >= n4) return;
        float4 x = *(const float4*)(src + o * 4);
        __half2* hp = (__half2*)(h + o * 4);
        hp[0] = __half2(__float2half_rn(x.x), __float2half_rn(x.y));
        hp[1] = __half2(__float2half_rn(x.z), __float2half_rn(x.w));
    }
}

// ---------------------------------------------------------------------------
// fp16x2 GEMM (validated): C = A @ W^T + bias; terms ah*wh + ah*wm.
// ---------------------------------------------------------------------------
#define BK2      32
#define NCH2     (D_MODEL / BK2)
#define TILE_W2  (128 * 16)
#define TILE_B2  (TILE_W2 * 4)
#define STAGE_W3 (3 * TILE_W2)
#define GEMM_SMEM3 (3 * STAGE_W3 * 4)

__device__ __forceinline__ int swz(int r, int w) {
    return r * 16 + (w ^ (((r >> 1) & 3) << 2));
}

__device__ __forceinline__ void stage_chunk3(
    const __half* __restrict__ Ah, const __half* __restrict__ Wh,
    const __half* __restrict__ Wm,
    uint32_t sbase, int buf, int k0, int tid)
{
    const __half* src[3] = { Ah, Wh, Wm };
    uint32_t s0 = sbase + buf * STAGE_W3 * 4;
#pragma unroll
    for (int i = 0; i < 6; i++) {
        int idx  = tid + i * 256;
        int tile = idx / 512;
        int wi   = idx & 511;
        int r    = wi >> 2;
        int ch   = wi & 3;
        cp_async16(s0 + (tile * TILE_W2 + swz(r, ch * 4)) * 4,
                   src[tile] + r * D_MODEL + k0 + ch * 8);
    }
    cp_commit();
}

__device__ __forceinline__ void gemm_f16_body(
    const __half* __restrict__ Ah, const __half* __restrict__ Wh,
    const __half* __restrict__ Wm,
    const float* __restrict__ bias, float* __restrict__ C)
{
    extern __shared__ uint32_t smw[];
    const uint32_t sbase = smem_u32(smw);
    const int tid  = threadIdx.x;
    const int wid  = tid >> 5;
    const int lane = tid & 31;
    const int wm_  = (wid & 1) * 64;
    const int wn   = (wid >> 1) * 32;
    const int brow = blockIdx.y * 128;
    const int bcol = blockIdx.x * 128;
    const int g    = lane >> 2;
    const int t    = lane & 3;
    const int lrow16 = lane & 15;
    const int lrow8  = lane & 7;
    const int half_  = lane >> 4;
    const int midbit = (lane >> 3) & 1;

    uint32_t aoff[4][2], boff[2][2];
#pragma unroll
    for (int mf = 0; mf < 4; mf++)
#pragma unroll
        for (int ks = 0; ks < 2; ks++) {
            int row = wm_ + mf * 16 + lrow16;
            int ch  = ks * 2 + half_;
            aoff[mf][ks] = (uint32_t)((row * 16 +
                ((ch * 4) ^ (((row >> 1) & 3) << 2))) * 4);
        }
#pragma unroll
    for (int p = 0; p < 2; p++)
#pragma unroll
        for (int ks = 0; ks < 2; ks++) {
            int row = wn + (2 * p + half_) * 8 + lrow8;
            int ch  = ks * 2 + midbit;
            boff[p][ks] = (uint32_t)((row * 16 +
                ((ch * 4) ^ (((row >> 1) & 3) << 2))) * 4);
        }

    float acc[4][4][4];
#pragma unroll
    for (int mf = 0; mf < 4; mf++)
#pragma unroll
        for (int nf = 0; nf < 4; nf++)
#pragma unroll
            for (int r = 0; r < 4; r++) acc[mf][nf][r] = 0.0f;

    const __half* Ah_r = Ah + brow * D_MODEL;
    const __half* Wh_r = Wh + bcol * D_MODEL;
    const __half* Wm_r = Wm + bcol * D_MODEL;

    stage_chunk3(Ah_r, Wh_r, Wm_r, sbase, 0, 0, tid);
    stage_chunk3(Ah_r, Wh_r, Wm_r, sbase, 1, BK2, tid);

    int buf = 0;
    for (int c = 0; c < NCH2; c++) {
        if (c < NCH2 - 1) cp_wait<1>(); else cp_wait<0>();
        __syncthreads();
        if (c + 2 < NCH2) {
            int nb = buf + 2; if (nb >= 3) nb -= 3;
            stage_chunk3(Ah_r, Wh_r, Wm_r, sbase, nb, (c + 2) * BK2, tid);
        }

        const uint32_t sb0 = sbase + buf * (STAGE_W3 * 4);

#pragma unroll
        for (int ks = 0; ks < 2; ks++) {
            uint32_t ah[4][4];
#pragma unroll
            for (int mf = 0; mf < 4; mf++)
                ldsm4(ah[mf], sb0 + aoff[mf][ks]);
#pragma unroll
            for (int p = 0; p < 2; p++) {
                uint32_t bh4[4], bm4[4];
                ldsm4(bh4, sb0 + TILE_B2 + boff[p][ks]);
                ldsm4(bm4, sb0 + 2 * TILE_B2 + boff[p][ks]);
#pragma unroll
                for (int qq = 0; qq < 2; qq++) {
                    const int nf = 2 * p + qq;
                    uint32_t bh[2] = { bh4[2 * qq], bh4[2 * qq + 1] };
                    uint32_t bm[2] = { bm4[2 * qq], bm4[2 * qq + 1] };
#pragma unroll
                    for (int mf = 0; mf < 4; mf++) {
                        mma_f16(acc[mf][nf], ah[mf], bm);
                        mma_f16(acc[mf][nf], ah[mf], bh);
                    }
                }
            }
        }
        buf++; if (buf >= 3) buf = 0;
    }

#pragma unroll
    for (int mf = 0; mf < 4; mf++) {
        int row0 = brow + wm_ + mf * 16 + g;
#pragma unroll
        for (int nf = 0; nf < 4; nf++) {
            int col = bcol + wn + nf * 8 + 2 * t;
            float b0 = bias[col], b1 = bias[col + 1];
            float2 v0 = make_float2(acc[mf][nf][0] + b0, acc[mf][nf][1] + b1);
            float2 v1 = make_float2(acc[mf][nf][2] + b0, acc[mf][nf][3] + b1);
            *(float2*)(C + row0 * D_MODEL + col)       = v0;
            *(float2*)(C + (row0 + 8) * D_MODEL + col) = v1;
        }
    }
}

__global__ __launch_bounds__(256)
void gemm_qkv_f16(const __half* __restrict__ Xh,
                  const __half* __restrict__ Wqh, const __half* __restrict__ Wqm,
                  const float* __restrict__ Bq, float* __restrict__ Oq,
                  const __half* __restrict__ Wkh, const __half* __restrict__ Wkm,
                  const float* __restrict__ Bk, float* __restrict__ Ok,
                  const __half* __restrict__ Wvh, const __half* __restrict__ Wvm,
                  const float* __restrict__ Bv, float* __restrict__ Ov)
{
    const __half *Wh, *Wm; const float* bb; float* C;
    if (blockIdx.z == 0)      { Wh = Wqh; Wm = Wqm; bb = Bq; C = Oq; }
    else if (blockIdx.z == 1) { Wh = Wkh; Wm = Wkm; bb = Bk; C = Ok; }
    else                      { Wh = Wvh; Wm = Wvm; bb = Bv; C = Ov; }
    gemm_f16_body(Xh, Wh, Wm, bb, C);
}

__global__ __launch_bounds__(256)
void gemm_out_f16(const __half* __restrict__ Ah,
                  const __half* __restrict__ Wh, const __half* __restrict__ Wm,
                  const float* __restrict__ bb, float* __restrict__ C)
{
    gemm_f16_body(Ah, Wh, Wm, bb, C);
}

// ---------------------------------------------------------------------------
// RoPE + split, table-based: q,k -> fp16 hi only.
// ---------------------------------------------------------------------------
__global__ __launch_bounds__(256)
void rope_split_kernel(const float* __restrict__ q, const float* __restrict__ k,
                       const float2* __restrict__ tab,
                       __half* __restrict__ qh, __half* __restrict__ kh)
{
    int idx = blockIdx.x * blockDim.x + threadIdx.x;
    int i4  = idx & 7;
    int h   = (idx >> 3) & (N_HEADS - 1);
    int row = idx >> 7;
    int t   = row & (SEQ - 1);

    int base = row * D_MODEL + h * HDIM + i4 * 4;
    float4 qa = *(const float4*)(q + base);
    float4 qb = *(const float4*)(q + base + 32);
    float4 ka = *(const float4*)(k + base);
    float4 kb = *(const float4*)(k + base + 32);
    const float2* tp = tab + (t << 5) + i4 * 4;

    float qa_[4] = { qa.x, qa.y, qa.z, qa.w };
    float qb_[4] = { qb.x, qb.y, qb.z, qb.w };
    float ka_[4] = { ka.x, ka.y, ka.z, ka.w };
    float kb_[4] = { kb.x, kb.y, kb.z, kb.w };
    float qr_a[4], qr_b[4], kr_a[4], kr_b[4];
#pragma unroll
    for (int j = 0; j < 4; j++) {
        float2 cs = tp[j];
        qr_a[j] = qa_[j] * cs.x - qb_[j] * cs.y;
        qr_b[j] = qb_[j] * cs.x + qa_[j] * cs.y;
        kr_a[j] = ka_[j] * cs.x - kb_[j] * cs.y;
        kr_b[j] = kb_[j] * cs.x + ka_[j] * cs.y;
    }

    *(uint2*)(qh + base)      = make_uint2(pack_f16(qr_a[0], qr_a[1]),
                                           pack_f16(qr_a[2], qr_a[3]));
    *(uint2*)(qh + base + 32) = make_uint2(pack_f16(qr_b[0], qr_b[1]),
                                           pack_f16(qr_b[2], qr_b[3]));
    *(uint2*)(kh + base)      = make_uint2(pack_f16(kr_a[0], kr_a[1]),
                                           pack_f16(kr_a[2], kr_a[3]));
    *(uint2*)(kh + base + 32) = make_uint2(pack_f16(kr_b[0], kr_b[1]),
                                           pack_f16(kr_b[2], kr_b[3]));
}

// ---------------------------------------------------------------------------
// V transpose to fp16 hi: fp32 [b*S+s][h*64+d] -> [(bh*64)+d][s]
// ---------------------------------------------------------------------------
__global__ __launch_bounds__(256)
void v_split_t_kernel(const float* __restrict__ v, __half* __restrict__ vth)
{
    __shared__ __half th[64][66];
    const int tid = threadIdx.x;
    const int st  = blockIdx.x;
    const int bh  = blockIdx.y;
    const int b   = bh >> 4;
    const int h   = bh & 15;
    const int s0  = st * 64;

#pragma unroll
    for (int l = 0; l < 16; l++) {
        int e = l * 256 + tid;
        int r = e >> 6, d = e & 63;
        th[d][r] = __float2half_rn(v[(b * SEQ + s0 + r) * D_MODEL + h * HDIM + d]);
    }
    __syncthreads();
#pragma unroll
    for (int l = 0; l < 16; l++) {
        int e = l * 256 + tid;
        int d = e >> 6, sc = e & 63;
        vth[(bh * HDIM + d) * SEQ + s0 + sc] = th[d][sc];
    }
}

// ---------------------------------------------------------------------------
// Flash attention, single-term fp16 mma.sync + ldmatrix (fp32 accumulate).
// ---------------------------------------------------------------------------
#define NT        (SEQ / 64)
#define FL_QH     0
#define FL_STG    18432
#define FL_SSZ    18688     // KH 9216 + VH 9216 + mask 256
#define FL_KH(s)  (FL_STG + (s) * FL_SSZ)
#define FL_VH(s)  (FL_STG + (s) * FL_SSZ + 9216)
#define FL_MS(s)  (FL_STG + (s) * FL_SSZ + 18432)
#define FA4_SMEM  (FL_STG + 2 * FL_SSZ)   // 55808

__global__ __launch_bounds__(256)
void flash4_kernel(const __half* __restrict__ Qh,
                   const __half* __restrict__ Kh,
                   const __half* __restrict__ Vth,
                   const float* __restrict__ mask,
                   __half* __restrict__ Oh)
{
    extern __shared__ char sm2[];
    const int tid  = threadIdx.x;
    const int w    = tid >> 5;
    const int lane = tid & 31;
    const int g    = lane >> 2;
    const int t    = lane & 3;
    const int qt   = blockIdx.x;
    const int bh   = blockIdx.y;
    const int b    = bh >> 4;
    const int h    = bh & 15;
    const uint32_t sbase = smem_u32(sm2);
    const int lrow16 = lane & 15;
    const int lrow8  = lane & 7;
    const int half_  = lane >> 4;
    const int midbit = (lane >> 3) & 1;

    uint32_t qoff[4], koff[4][4];
#pragma unroll
    for (int ks = 0; ks < 4; ks++)
        qoff[ks] = (uint32_t)((w * 16 + lrow16) * 144 + (ks * 2 + half_) * 16);
#pragma unroll
    for (int p = 0; p < 4; p++)
#pragma unroll
        for (int ks = 0; ks < 4; ks++)
            koff[p][ks] = (uint32_t)(((2 * p + half_) * 8 + lrow8) * 144 +
                                     (ks * 2 + midbit) * 16);

    const __half* qh_g = Qh + (b * SEQ + qt * 128) * D_MODEL + h * HDIM;
    const __half* kh_g = Kh + b * SEQ * D_MODEL + h * HDIM;
    const __half* vh_g = Vth + bh * HDIM * SEQ;
    const float* mask_g = mask + b * SEQ;

    auto stage = [&](int kt, int s) {
#pragma unroll
        for (int i = 0; i < 2; i++) {
            int idx = tid + i * 256;
            int r   = idx >> 3;
            int ch  = idx & 7;
            cp_async16(sbase + FL_KH(s) + r * 144 + ch * 16,
                       kh_g + (kt * 64 + r) * D_MODEL + ch * 8);
            cp_async16(sbase + FL_VH(s) + r * 144 + ch * 16,
                       vh_g + r * SEQ + kt * 64 + ch * 8);
        }
        if (tid < 16)
            cp_async16(sbase + FL_MS(s) + tid * 16, mask_g + kt * 64 + tid * 4);
    };

#pragma unroll
    for (int i = 0; i < 2; i++) {
        int idx = tid + i * 256;
        int r   = idx >> 2;
        int ch  = (idx & 3) * 2;
        cp_async16(sbase + FL_QH + r * 144 + ch * 16, qh_g + r * D_MODEL + ch * 8);
        cp_async16(sbase + FL_QH + r * 144 + (ch + 1) * 16, qh_g + r * D_MODEL + (ch + 1) * 8);
    }
    stage(0, 0);
    cp_commit();

    float o[8][4];
#pragma unroll
    for (int nf = 0; nf < 8; nf++)
#pragma unroll
        for (int j = 0; j < 4; j++) o[nf][j] = 0.0f;
    float m0 = -1e30f, m1 = -1e30f, l0 = 0.0f, l1 = 0.0f;

    for (int kt = 0; kt < NT; kt++) {
        const int s = kt & 1;
        if (kt + 1 < NT) { stage(kt + 1, s ^ 1); cp_commit(); cp_wait<1>(); }
        else             { cp_wait<0>(); }
        __syncthreads();

        // ---- S = Q K^T ----
        float sc[8][4];
#pragma unroll
        for (int nf = 0; nf < 8; nf++)
#pragma unroll
            for (int j = 0; j < 4; j++) sc[nf][j] = 0.0f;

#pragma unroll
        for (int ks = 0; ks < 4; ks++) {
            uint32_t ah[4];
            ldsm4(ah, sbase + FL_QH + qoff[ks]);
#pragma unroll
            for (int p = 0; p < 4; p++) {
                uint32_t bh4[4];
                ldsm4(bh4, sbase + FL_KH(s) + koff[p][ks]);
#pragma unroll
                for (int qq = 0; qq < 2; qq++) {
                    uint32_t bhf[2] = { bh4[2 * qq], bh4[2 * qq + 1] };
                    mma_f16(sc[2 * p + qq], ah, bhf);
                }
            }
        }

        // ---- scale + mask + online softmax (warp-local) ----
        float rmax0 = -1e30f, rmax1 = -1e30f;
#pragma unroll
        for (int nf = 0; nf < 8; nf++) {
            float2 mk = *(const float2*)(sm2 + FL_MS(s) + (nf * 8 + 2 * t) * 4);
            sc[nf][0] = fmaf(sc[nf][0], 0.125f, mk.x);
            sc[nf][1] = fmaf(sc[nf][1], 0.125f, mk.y);
            sc[nf][2] = fmaf(sc[nf][2], 0.125f, mk.x);
            sc[nf][3] = fmaf(sc[nf][3], 0.125f, mk.y);
            rmax0 = fmaxf(rmax0, fmaxf(sc[nf][0], sc[nf][1]));
            rmax1 = fmaxf(rmax1, fmaxf(sc[nf][2], sc[nf][3]));
        }
        rmax0 = fmaxf(rmax0, __shfl_xor_sync(0xffffffffu, rmax0, 1));
        rmax0 = fmaxf(rmax0, __shfl_xor_sync(0xffffffffu, rmax0, 2));
        rmax1 = fmaxf(rmax1, __shfl_xor_sync(0xffffffffu, rmax1, 1));
        rmax1 = fmaxf(rmax1, __shfl_xor_sync(0xffffffffu, rmax1, 2));
        float mn0 = fmaxf(m0, rmax0), mn1 = fmaxf(m1, rmax1);
        float c0 = fast_exp(m0 - mn0), c1 = fast_exp(m1 - mn1);
        float sum0 = 0.0f, sum1 = 0.0f;
#pragma unroll
        for (int nf = 0; nf < 8; nf++) {
            sc[nf][0] = fast_exp(sc[nf][0] - mn0);
            sc[nf][1] = fast_exp(sc[nf][1] - mn0);
            sc[nf][2] = fast_exp(sc[nf][2] - mn1);
            sc[nf][3] = fast_exp(sc[nf][3] - mn1);
            sum0 += sc[nf][0] + sc[nf][1];
            sum1 += sc[nf][2] + sc[nf][3];
        }
        sum0 += __shfl_xor_sync(0xffffffffu, sum0, 1);
        sum0 += __shfl_xor_sync(0xffffffffu, sum0, 2);
        sum1 += __shfl_xor_sync(0xffffffffu, sum1, 1);
        sum1 += __shfl_xor_sync(0xffffffffu, sum1, 2);
        l0 = l0 * c0 + sum0;
        l1 = l1 * c1 + sum1;
        m0 = mn0; m1 = mn1;
#pragma unroll
        for (int nf = 0; nf < 8; nf++) {
            o[nf][0] *= c0; o[nf][1] *= c0;
            o[nf][2] *= c1; o[nf][3] *= c1;
        }

        // ---- O += P V ----
#pragma unroll
        for (int ks = 0; ks < 4; ks++) {
            uint32_t ph[4];
            ph[0] = pack_f16(sc[2 * ks][0],     sc[2 * ks][1]);
            ph[1] = pack_f16(sc[2 * ks][2],     sc[2 * ks][3]);
            ph[2] = pack_f16(sc[2 * ks + 1][0], sc[2 * ks + 1][1]);
            ph[3] = pack_f16(sc[2 * ks + 1][2], sc[2 * ks + 1][3]);
#pragma unroll
            for (int p = 0; p < 4; p++) {
                uint32_t bh4[4];
                ldsm4(bh4, sbase + FL_VH(s) + koff[p][ks]);
#pragma unroll
                for (int qq = 0; qq < 2; qq++) {
                    uint32_t bhf[2] = { bh4[2 * qq], bh4[2 * qq + 1] };
                    mma_f16(o[2 * p + qq], ph, bhf);
                }
            }
        }
        __syncthreads();
    }

    float i0 = 1.0f / l0, i1 = 1.0f / l1;
    int row0 = b * SEQ + qt * 128 + w * 16 + g;
    int colb = h * HDIM + 2 * t;
#pragma unroll
    for (int nf = 0; nf < 8; nf++) {
        uint32_t hw0 = pack_f16(o[nf][0] * i0, o[nf][1] * i0);
        uint32_t hw1 = pack_f16(o[nf][2] * i1, o[nf][3] * i1);
        *(uint32_t*)(Oh + row0 * D_MODEL + colb + nf * 8)       = hw0;
        *(uint32_t*)(Oh + (row0 + 8) * D_MODEL + colb + nf * 8) = hw1;
    }
}

// ---------------------------------------------------------------------------
// Launch
// ---------------------------------------------------------------------------
extern "C" void kernel_launch(void* const* d_in, const int* in_sizes, int n_in,
                              void* d_out, int out_size)
{
    const float* x    = (const float*)d_in[0];
    const float* wq   = (const float*)d_in[1];
    const float* bq   = (const float*)d_in[2];
    const float* wk   = (const float*)d_in[3];
    const float* bk   = (const float*)d_in[4];
    const float* wv   = (const float*)d_in[5];
    const float* bv   = (const float*)d_in[6];
    const float* wo   = (const float*)d_in[7];
    const float* bo   = (const float*)d_in[8];
    const float* mask = (const float*)d_in[9];
    float* out = (float*)d_out;

    float *q, *k, *v;
    float2* angtab;
    __half *qh, *kh, *vth, *xh, *ath;
    __half *wqh, *wqm, *wkh, *wkm, *wvh, *wvm, *woh, *wom;
    cudaGetSymbolAddress((void**)&q,      g_q);
    cudaGetSymbolAddress((void**)&k,      g_k);
    cudaGetSymbolAddress((void**)&v,      g_v);
    cudaGetSymbolAddress((void**)&angtab, g_angtab);
    cudaGetSymbolAddress((void**)&qh,  g_qh);
    cudaGetSymbolAddress((void**)&kh,  g_kh);
    cudaGetSymbolAddress((void**)&vth, g_vth);
    cudaGetSymbolAddress((void**)&xh,  g_xh);
    cudaGetSymbolAddress((void**)&ath, g_ath);
    cudaGetSymbolAddress((void**)&wqh, g_wqh);
    cudaGetSymbolAddress((void**)&wqm, g_wqm);
    cudaGetSymbolAddress((void**)&wkh, g_wkh);
    cudaGetSymbolAddress((void**)&wkm, g_wkm);
    cudaGetSymbolAddress((void**)&wvh, g_wvh);
    cudaGetSymbolAddress((void**)&wvm, g_wvm);
    cudaGetSymbolAddress((void**)&woh, g_woh);
    cudaGetSymbolAddress((void**)&wom, g_wom);

    cudaFuncSetAttribute(gemm_qkv_f16,
                         cudaFuncAttributeMaxDynamicSharedMemorySize, GEMM_SMEM3);
    cudaFuncSetAttribute(gemm_out_f16,
                         cudaFuncAttributeMaxDynamicSharedMemorySize, GEMM_SMEM3);
    cudaFuncSetAttribute(flash4_kernel,
                         cudaFuncAttributeMaxDynamicSharedMemorySize, FA4_SMEM);

    // Prepasses
    const int NX4 = ROWS * D_MODEL / 4;
    angtab_kernel<<<SEQ * 32 / 256, 256>>>(angtab);
    split_w4_kernel<<<(4 * W_UNITS / 2) / 256, 256>>>(
        wq, wk, wv, wo, wqh, wqm, wkh, wkm, wvh, wvm, woh, wom);
    split1_kernel<<<(NX4 / 2) / 256, 256>>>(x, xh, NX4);

    // QKV projections (fp16x2 mma.sync)
    dim3 g1(D_MODEL / 128, ROWS / 128, 3);
    gemm_qkv_f16<<<g1, 256, GEMM_SMEM3>>>(xh, wqh, wqm, bq, q,
                                          wkh, wkm, bk, k, wvh, wvm, bv, v);

    // RoPE (table) + fp16 hi split
    int rope_items = ROWS * N_HEADS * 8;
    rope_split_kernel<<<rope_items / 256, 256>>>(q, k, angtab, qh, kh);

    // V transpose (hi only)
    v_split_t_kernel<<<dim3(SEQ / 64, BATCH * N_HEADS), 256>>>(v, vth);

    // Flash attention (single-term fp16)
    flash4_kernel<<<dim3(SEQ / 128, BATCH * N_HEADS), 256, FA4_SMEM>>>(
        qh, kh, vth, mask, ath);

    // Output projection (fp16x2) -> d_out
    dim3 g3(D_MODEL / 128, ROWS / 128);
    gemm_out_f16<<<g3, 256, GEMM_SMEM3>>>(ath, woh, wom, bo, out);
}

// round 13
// speedup vs baseline: 6.0167x; 1.0522x over previous
#include <cuda_runtime.h>
#include <cuda_fp16.h>
#include <cstdint>
#include <math.h>

#define D_MODEL 1024
#define N_HEADS 16
#define HDIM    64
#define SEQ     2048
#define BATCH   2
#define ROWS    (BATCH * SEQ)   // 4096

// ---------------------------------------------------------------------------
// Scratch (static device globals — no allocation allowed)
// ---------------------------------------------------------------------------
__device__ float g_q[ROWS * D_MODEL];
__device__ float g_k[ROWS * D_MODEL];
__device__ float g_v[ROWS * D_MODEL];
__device__ float2 g_angtab[SEQ * 32];                         // (cos, sin)
__device__ __half g_qh[ROWS * D_MODEL];                       // Q hi
__device__ __half g_kh[ROWS * D_MODEL];                       // K hi
__device__ __half g_vth[BATCH * N_HEADS * HDIM * SEQ];        // V^T hi [bh*64+d][s]
__device__ __half g_xh[ROWS * D_MODEL];                       // X hi
__device__ __half g_ath[ROWS * D_MODEL];                      // att hi
__device__ __half g_wqh[D_MODEL * D_MODEL];
__device__ __half g_wqm[D_MODEL * D_MODEL];
__device__ __half g_wkh[D_MODEL * D_MODEL];
__device__ __half g_wkm[D_MODEL * D_MODEL];
__device__ __half g_wvh[D_MODEL * D_MODEL];
__device__ __half g_wvm[D_MODEL * D_MODEL];
__device__ __half g_woh[D_MODEL * D_MODEL];
__device__ __half g_wom[D_MODEL * D_MODEL];

// ---------------------------------------------------------------------------
// Helpers
// ---------------------------------------------------------------------------
__device__ __forceinline__ uint32_t smem_u32(const void* p) {
    uint32_t a;
    asm("{ .reg .u64 t; cvta.to.shared.u64 t, %1; cvt.u32.u64 %0, t; }"
        : "=r"(a) : "l"(p));
    return a;
}
__device__ __forceinline__ void cp_async16(uint32_t saddr, const void* gptr) {
    asm volatile("cp.async.cg.shared.global [%0], [%1], 16;"
                 :: "r"(saddr), "l"(gptr) : "memory");
}
__device__ __forceinline__ void cp_commit() {
    asm volatile("cp.async.commit_group;" ::: "memory");
}
template <int N>
__device__ __forceinline__ void cp_wait() {
    asm volatile("cp.async.wait_group %0;" :: "n"(N) : "memory");
}
__device__ __forceinline__ void mma_f16(float* d, const uint32_t* a,
                                        const uint32_t* b) {
    asm volatile(
        "mma.sync.aligned.m16n8k16.row.col.f32.f16.f16.f32 "
        "{%0,%1,%2,%3}, {%4,%5,%6,%7}, {%8,%9}, {%0,%1,%2,%3};"
        : "+f"(d[0]), "+f"(d[1]), "+f"(d[2]), "+f"(d[3])
        : "r"(a[0]), "r"(a[1]), "r"(a[2]), "r"(a[3]), "r"(b[0]), "r"(b[1]));
}
__device__ __forceinline__ void ldsm4(uint32_t* r, uint32_t addr) {
    asm volatile("ldmatrix.sync.aligned.m8n8.x4.shared.b16 {%0,%1,%2,%3}, [%4];"
                 : "=r"(r[0]), "=r"(r[1]), "=r"(r[2]), "=r"(r[3]) : "r"(addr));
}
__device__ __forceinline__ uint32_t pack_f16(float lo, float hi) {
    uint32_t r;
    asm("cvt.rn.f16x2.f32 %0, %1, %2;" : "=r"(r) : "f"(hi), "f"(lo));
    return r;
}

// FFMA-only exp, accurate ~1e-7 on [-87, 0]
__device__ __forceinline__ float fast_exp(float x) {
    x = fmaxf(x, -87.0f);
    float y = x * 1.4426950408889634f;
    float r = y + 12582912.0f;
    float n = r - 12582912.0f;
    float f = y - n;
    float t = f * 0.6931471805599453f;
    float p = 1.3888889e-3f;
    p = fmaf(p, t, 8.3333333e-3f);
    p = fmaf(p, t, 4.1666667e-2f);
    p = fmaf(p, t, 1.6666667e-1f);
    p = fmaf(p, t, 0.5f);
    p = fmaf(p, t, 1.0f);
    p = fmaf(p, t, 1.0f);
    int ni = __float_as_int(r) - 0x4B400000;
    float scale = __int_as_float((ni << 23) + 0x3F800000);
    return p * scale;
}

// ---------------------------------------------------------------------------
// RoPE angle table
// ---------------------------------------------------------------------------
__global__ __launch_bounds__(256)
void angtab_kernel(float2* __restrict__ tab)
{
    int idx = blockIdx.x * blockDim.x + threadIdx.x;
    int t = idx >> 5;
    int i = idx & 31;
    float inv = 1.0f / powf(10000.0f, (float)(2 * i) * (1.0f / 64.0f));
    float ang = (float)t * inv;
    float sn, cs;
    sincosf(ang, &sn, &cs);
    tab[idx] = make_float2(cs, sn);
}

// ---------------------------------------------------------------------------
// Weight split (hi + mid), fused over the 4 matrices.
// ---------------------------------------------------------------------------
#define W_UNITS (D_MODEL * D_MODEL / 4)

__global__ __launch_bounds__(256)
void split_w4_kernel(const float* __restrict__ w0, const float* __restrict__ w1,
                     const float* __restrict__ w2, const float* __restrict__ w3,
                     __half* __restrict__ h0, __half* __restrict__ m0,
                     __half* __restrict__ h1, __half* __restrict__ m1,
                     __half* __restrict__ h2, __half* __restrict__ m2,
                     __half* __restrict__ h3, __half* __restrict__ m3)
{
    int idx = blockIdx.x * blockDim.x + threadIdx.x;
    int u   = idx * 2;
    int mat = u >> 18;
    int rem = u & (W_UNITS - 1);
    const float* src; __half *hh, *mm;
    if (mat == 0)      { src = w0; hh = h0; mm = m0; }
    else if (mat == 1) { src = w1; hh = h1; mm = m1; }
    else if (mat == 2) { src = w2; hh = h2; mm = m2; }
    else               { src = w3; hh = h3; mm = m3; }
#pragma unroll
    for (int j = 0; j < 2; j++) {
        int o = rem + j;
        float4 x = *(const float4*)(src + o * 4);
        __half ha = __float2half_rn(x.x);
        __half hb = __float2half_rn(x.y);
        __half hc = __float2half_rn(x.z);
        __half hd = __float2half_rn(x.w);
        __half2* hp = (__half2*)(hh + o * 4);
        hp[0] = __half2(ha, hb);
        hp[1] = __half2(hc, hd);
        __half2* mp = (__half2*)(mm + o * 4);
        mp[0] = __half2(__float2half_rn(x.x - __half2float(ha)),
                        __float2half_rn(x.y - __half2float(hb)));
        mp[1] = __half2(__float2half_rn(x.z - __half2float(hc)),
                        __float2half_rn(x.w - __half2float(hd)));
    }
}

// X split (hi only)
__global__ __launch_bounds__(256)
void split1_kernel(const float* __restrict__ src, __half* __restrict__ h, int n4)
{
    int idx = blockIdx.x * blockDim.x + threadIdx.x;
#pragma unroll
    for (int j = 0; j < 2; j++) {
        int o = idx * 2 + j;
        if (o >= n4) return;
        float4 x = *(const float4*)(src + o * 4);
        __half2* hp = (__half2*)(h + o * 4);
        hp[0] = __half2(__float2half_rn(x.x), __float2half_rn(x.y));
        hp[1] = __half2(__float2half_rn(x.z), __float2half_rn(x.w));
    }
}

// ---------------------------------------------------------------------------
// fp16x2 GEMM: C[M,N] = A[M,K] @ W[N,K]^T + bias; terms ah*wh + ah*wm.
// 128-thread CTA (4 warps as 2x2), CTA tile 128x64, warp tile 64x32.
// 3-stage cp.async ring (16KB/stage: A 8KB + Wh 4KB + Wm 4KB), XOR swizzle,
// ldmatrix, one __syncthreads per chunk. 4 CTAs/SM -> 4 barrier domains.
// ---------------------------------------------------------------------------
#define BK2      32
#define NCH2     (D_MODEL / BK2)       // 32 chunks
#define BUF_W    4096                  // words per stage (16KB)
#define A_OFF_W  0                     // A: 128 rows x 16 words
#define WH_OFF_W 2048                  // Wh: 64 rows x 16 words
#define WM_OFF_W 3072                  // Wm: 64 rows x 16 words
#define GEMM_SMEM3 (3 * BUF_W * 4)     // 49152 bytes

__device__ __forceinline__ int swz(int r, int w) {
    return r * 16 + (w ^ (((r >> 1) & 3) << 2));
}

__device__ __forceinline__ void stage_chunk3(
    const __half* __restrict__ Ah, const __half* __restrict__ Wh,
    const __half* __restrict__ Wm,
    uint32_t sbase, int buf, int k0, int tid)
{
    uint32_t s0 = sbase + buf * (BUF_W * 4);
#pragma unroll
    for (int i = 0; i < 8; i++) {
        int u = tid + i * 128;            // 0..1023 16B-units
        if (u < 512) {                    // A: 128 rows x 4 units
            int r = u >> 2, ch = u & 3;
            cp_async16(s0 + (A_OFF_W + swz(r, ch * 4)) * 4,
                       Ah + r * D_MODEL + k0 + ch * 8);
        } else if (u < 768) {             // Wh: 64 rows x 4 units
            int u2 = u - 512;
            int r = u2 >> 2, ch = u2 & 3;
            cp_async16(s0 + (WH_OFF_W + swz(r, ch * 4)) * 4,
                       Wh + r * D_MODEL + k0 + ch * 8);
        } else {                          // Wm
            int u2 = u - 768;
            int r = u2 >> 2, ch = u2 & 3;
            cp_async16(s0 + (WM_OFF_W + swz(r, ch * 4)) * 4,
                       Wm + r * D_MODEL + k0 + ch * 8);
        }
    }
    cp_commit();
}

__device__ __forceinline__ void gemm_f16_body(
    const __half* __restrict__ Ah, const __half* __restrict__ Wh,
    const __half* __restrict__ Wm,
    const float* __restrict__ bias, float* __restrict__ C)
{
    extern __shared__ uint32_t smw[];
    const uint32_t sbase = smem_u32(smw);
    const int tid  = threadIdx.x;
    const int wid  = tid >> 5;           // 0..3
    const int lane = tid & 31;
    const int wm_  = (wid & 1) * 64;     // m offset
    const int wn   = (wid >> 1) * 32;    // n offset (0/32 of 64)
    const int brow = blockIdx.y * 128;
    const int bcol = blockIdx.x * 64;
    const int g    = lane >> 2;
    const int t    = lane & 3;
    const int lrow16 = lane & 15;
    const int lrow8  = lane & 7;
    const int half_  = lane >> 4;
    const int midbit = (lane >> 3) & 1;

    uint32_t aoff[4][2], boff[2][2];
#pragma unroll
    for (int mf = 0; mf < 4; mf++)
#pragma unroll
        for (int ks = 0; ks < 2; ks++) {
            int row = wm_ + mf * 16 + lrow16;
            int ch  = ks * 2 + half_;
            aoff[mf][ks] = (uint32_t)((A_OFF_W + row * 16 +
                ((ch * 4) ^ (((row >> 1) & 3) << 2))) * 4);
        }
#pragma unroll
    for (int p = 0; p < 2; p++)
#pragma unroll
        for (int ks = 0; ks < 2; ks++) {
            int row = wn + (2 * p + half_) * 8 + lrow8;   // < 64
            int ch  = ks * 2 + midbit;
            boff[p][ks] = (uint32_t)((row * 16 +
                ((ch * 4) ^ (((row >> 1) & 3) << 2))) * 4);
        }

    float acc[4][4][4];
#pragma unroll
    for (int mf = 0; mf < 4; mf++)
#pragma unroll
        for (int nf = 0; nf < 4; nf++)
#pragma unroll
            for (int r = 0; r < 4; r++) acc[mf][nf][r] = 0.0f;

    const __half* Ah_r = Ah + brow * D_MODEL;
    const __half* Wh_r = Wh + bcol * D_MODEL;
    const __half* Wm_r = Wm + bcol * D_MODEL;

    stage_chunk3(Ah_r, Wh_r, Wm_r, sbase, 0, 0, tid);
    stage_chunk3(Ah_r, Wh_r, Wm_r, sbase, 1, BK2, tid);

    int buf = 0;
    for (int c = 0; c < NCH2; c++) {
        if (c < NCH2 - 1) cp_wait<1>(); else cp_wait<0>();
        __syncthreads();
        if (c + 2 < NCH2) {
            int nb = buf + 2; if (nb >= 3) nb -= 3;
            stage_chunk3(Ah_r, Wh_r, Wm_r, sbase, nb, (c + 2) * BK2, tid);
        }

        const uint32_t sb0 = sbase + buf * (BUF_W * 4);

#pragma unroll
        for (int ks = 0; ks < 2; ks++) {
            uint32_t ah[4][4];
#pragma unroll
            for (int mf = 0; mf < 4; mf++)
                ldsm4(ah[mf], sb0 + aoff[mf][ks]);
#pragma unroll
            for (int p = 0; p < 2; p++) {
                uint32_t bh4[4], bm4[4];
                ldsm4(bh4, sb0 + WH_OFF_W * 4 + boff[p][ks]);
                ldsm4(bm4, sb0 + WM_OFF_W * 4 + boff[p][ks]);
#pragma unroll
                for (int qq = 0; qq < 2; qq++) {
                    const int nf = 2 * p + qq;
                    uint32_t bh[2] = { bh4[2 * qq], bh4[2 * qq + 1] };
                    uint32_t bm[2] = { bm4[2 * qq], bm4[2 * qq + 1] };
#pragma unroll
                    for (int mf = 0; mf < 4; mf++) {
                        mma_f16(acc[mf][nf], ah[mf], bm);
                        mma_f16(acc[mf][nf], ah[mf], bh);
                    }
                }
            }
        }
        buf++; if (buf >= 3) buf = 0;
    }

#pragma unroll
    for (int mf = 0; mf < 4; mf++) {
        int row0 = brow + wm_ + mf * 16 + g;
#pragma unroll
        for (int nf = 0; nf < 4; nf++) {
            int col = bcol + wn + nf * 8 + 2 * t;
            float b0 = bias[col], b1 = bias[col + 1];
            float2 v0 = make_float2(acc[mf][nf][0] + b0, acc[mf][nf][1] + b1);
            float2 v1 = make_float2(acc[mf][nf][2] + b0, acc[mf][nf][3] + b1);
            *(float2*)(C + row0 * D_MODEL + col)       = v0;
            *(float2*)(C + (row0 + 8) * D_MODEL + col) = v1;
        }
    }
}

__global__ __launch_bounds__(128, 4)
void gemm_qkv_f16(const __half* __restrict__ Xh,
                  const __half* __restrict__ Wqh, const __half* __restrict__ Wqm,
                  const float* __restrict__ Bq, float* __restrict__ Oq,
                  const __half* __restrict__ Wkh, const __half* __restrict__ Wkm,
                  const float* __restrict__ Bk, float* __restrict__ Ok,
                  const __half* __restrict__ Wvh, const __half* __restrict__ Wvm,
                  const float* __restrict__ Bv, float* __restrict__ Ov)
{
    const __half *Wh, *Wm; const float* bb; float* C;
    if (blockIdx.z == 0)      { Wh = Wqh; Wm = Wqm; bb = Bq; C = Oq; }
    else if (blockIdx.z == 1) { Wh = Wkh; Wm = Wkm; bb = Bk; C = Ok; }
    else                      { Wh = Wvh; Wm = Wvm; bb = Bv; C = Ov; }
    gemm_f16_body(Xh, Wh, Wm, bb, C);
}

__global__ __launch_bounds__(128, 4)
void gemm_out_f16(const __half* __restrict__ Ah,
                  const __half* __restrict__ Wh, const __half* __restrict__ Wm,
                  const float* __restrict__ bb, float* __restrict__ C)
{
    gemm_f16_body(Ah, Wh, Wm, bb, C);
}

// ---------------------------------------------------------------------------
// RoPE + split, table-based: q,k -> fp16 hi only.
// ---------------------------------------------------------------------------
__global__ __launch_bounds__(256)
void rope_split_kernel(const float* __restrict__ q, const float* __restrict__ k,
                       const float2* __restrict__ tab,
                       __half* __restrict__ qh, __half* __restrict__ kh)
{
    int idx = blockIdx.x * blockDim.x + threadIdx.x;
    int i4  = idx & 7;
    int h   = (idx >> 3) & (N_HEADS - 1);
    int row = idx >> 7;
    int t   = row & (SEQ - 1);

    int base = row * D_MODEL + h * HDIM + i4 * 4;
    float4 qa = *(const float4*)(q + base);
    float4 qb = *(const float4*)(q + base + 32);
    float4 ka = *(const float4*)(k + base);
    float4 kb = *(const float4*)(k + base + 32);
    const float2* tp = tab + (t << 5) + i4 * 4;

    float qa_[4] = { qa.x, qa.y, qa.z, qa.w };
    float qb_[4] = { qb.x, qb.y, qb.z, qb.w };
    float ka_[4] = { ka.x, ka.y, ka.z, ka.w };
    float kb_[4] = { kb.x, kb.y, kb.z, kb.w };
    float qr_a[4], qr_b[4], kr_a[4], kr_b[4];
#pragma unroll
    for (int j = 0; j < 4; j++) {
        float2 cs = tp[j];
        qr_a[j] = qa_[j] * cs.x - qb_[j] * cs.y;
        qr_b[j] = qb_[j] * cs.x + qa_[j] * cs.y;
        kr_a[j] = ka_[j] * cs.x - kb_[j] * cs.y;
        kr_b[j] = kb_[j] * cs.x + ka_[j] * cs.y;
    }

    *(uint2*)(qh + base)      = make_uint2(pack_f16(qr_a[0], qr_a[1]),
                                           pack_f16(qr_a[2], qr_a[3]));
    *(uint2*)(qh + base + 32) = make_uint2(pack_f16(qr_b[0], qr_b[1]),
                                           pack_f16(qr_b[2], qr_b[3]));
    *(uint2*)(kh + base)      = make_uint2(pack_f16(kr_a[0], kr_a[1]),
                                           pack_f16(kr_a[2], kr_a[3]));
    *(uint2*)(kh + base + 32) = make_uint2(pack_f16(kr_b[0], kr_b[1]),
                                           pack_f16(kr_b[2], kr_b[3]));
}

// ---------------------------------------------------------------------------
// V transpose to fp16 hi
// ---------------------------------------------------------------------------
__global__ __launch_bounds__(256)
void v_split_t_kernel(const float* __restrict__ v, __half* __restrict__ vth)
{
    __shared__ __half th[64][66];
    const int tid = threadIdx.x;
    const int st  = blockIdx.x;
    const int bh  = blockIdx.y;
    const int b   = bh >> 4;
    const int h   = bh & 15;
    const int s0  = st * 64;

#pragma unroll
    for (int l = 0; l < 16; l++) {
        int e = l * 256 + tid;
        int r = e >> 6, d = e & 63;
        th[d][r] = __float2half_rn(v[(b * SEQ + s0 + r) * D_MODEL + h * HDIM + d]);
    }
    __syncthreads();
#pragma unroll
    for (int l = 0; l < 16; l++) {
        int e = l * 256 + tid;
        int d = e >> 6, sc = e & 63;
        vth[(bh * HDIM + d) * SEQ + s0 + sc] = th[d][sc];
    }
}

// ---------------------------------------------------------------------------
// Flash attention, single-term fp16 (validated round 12).
// ---------------------------------------------------------------------------
#define NT        (SEQ / 64)
#define FL_QH     0
#define FL_STG    18432
#define FL_SSZ    18688
#define FL_KH(s)  (FL_STG + (s) * FL_SSZ)
#define FL_VH(s)  (FL_STG + (s) * FL_SSZ + 9216)
#define FL_MS(s)  (FL_STG + (s) * FL_SSZ + 18432)
#define FA4_SMEM  (FL_STG + 2 * FL_SSZ)   // 55808

__global__ __launch_bounds__(256)
void flash4_kernel(const __half* __restrict__ Qh,
                   const __half* __restrict__ Kh,
                   const __half* __restrict__ Vth,
                   const float* __restrict__ mask,
                   __half* __restrict__ Oh)
{
    extern __shared__ char sm2[];
    const int tid  = threadIdx.x;
    const int w    = tid >> 5;
    const int lane = tid & 31;
    const int g    = lane >> 2;
    const int t    = lane & 3;
    const int qt   = blockIdx.x;
    const int bh   = blockIdx.y;
    const int b    = bh >> 4;
    const int h    = bh & 15;
    const uint32_t sbase = smem_u32(sm2);
    const int lrow16 = lane & 15;
    const int lrow8  = lane & 7;
    const int half_  = lane >> 4;
    const int midbit = (lane >> 3) & 1;

    uint32_t qoff[4], koff[4][4];
#pragma unroll
    for (int ks = 0; ks < 4; ks++)
        qoff[ks] = (uint32_t)((w * 16 + lrow16) * 144 + (ks * 2 + half_) * 16);
#pragma unroll
    for (int p = 0; p < 4; p++)
#pragma unroll
        for (int ks = 0; ks < 4; ks++)
            koff[p][ks] = (uint32_t)(((2 * p + half_) * 8 + lrow8) * 144 +
                                     (ks * 2 + midbit) * 16);

    const __half* qh_g = Qh + (b * SEQ + qt * 128) * D_MODEL + h * HDIM;
    const __half* kh_g = Kh + b * SEQ * D_MODEL + h * HDIM;
    const __half* vh_g = Vth + bh * HDIM * SEQ;
    const float* mask_g = mask + b * SEQ;

    auto stage = [&](int kt, int s) {
#pragma unroll
        for (int i = 0; i < 2; i++) {
            int idx = tid + i * 256;
            int r   = idx >> 3;
            int ch  = idx & 7;
            cp_async16(sbase + FL_KH(s) + r * 144 + ch * 16,
                       kh_g + (kt * 64 + r) * D_MODEL + ch * 8);
            cp_async16(sbase + FL_VH(s) + r * 144 + ch * 16,
                       vh_g + r * SEQ + kt * 64 + ch * 8);
        }
        if (tid < 16)
            cp_async16(sbase + FL_MS(s) + tid * 16, mask_g + kt * 64 + tid * 4);
    };

#pragma unroll
    for (int i = 0; i < 2; i++) {
        int idx = tid + i * 256;
        int r   = idx >> 2;
        int ch  = (idx & 3) * 2;
        cp_async16(sbase + FL_QH + r * 144 + ch * 16, qh_g + r * D_MODEL + ch * 8);
        cp_async16(sbase + FL_QH + r * 144 + (ch + 1) * 16, qh_g + r * D_MODEL + (ch + 1) * 8);
    }
    stage(0, 0);
    cp_commit();

    float o[8][4];
#pragma unroll
    for (int nf = 0; nf < 8; nf++)
#pragma unroll
        for (int j = 0; j < 4; j++) o[nf][j] = 0.0f;
    float m0 = -1e30f, m1 = -1e30f, l0 = 0.0f, l1 = 0.0f;

    for (int kt = 0; kt < NT; kt++) {
        const int s = kt & 1;
        if (kt + 1 < NT) { stage(kt + 1, s ^ 1); cp_commit(); cp_wait<1>(); }
        else             { cp_wait<0>(); }
        __syncthreads();

        float sc[8][4];
#pragma unroll
        for (int nf = 0; nf < 8; nf++)
#pragma unroll
            for (int j = 0; j < 4; j++) sc[nf][j] = 0.0f;

#pragma unroll
        for (int ks = 0; ks < 4; ks++) {
            uint32_t ah[4];
            ldsm4(ah, sbase + FL_QH + qoff[ks]);
#pragma unroll
            for (int p = 0; p < 4; p++) {
                uint32_t bh4[4];
                ldsm4(bh4, sbase + FL_KH(s) + koff[p][ks]);
#pragma unroll
                for (int qq = 0; qq < 2; qq++) {
                    uint32_t bhf[2] = { bh4[2 * qq], bh4[2 * qq + 1] };
                    mma_f16(sc[2 * p + qq], ah, bhf);
                }
            }
        }

        float rmax0 = -1e30f, rmax1 = -1e30f;
#pragma unroll
        for (int nf = 0; nf < 8; nf++) {
            float2 mk = *(const float2*)(sm2 + FL_MS(s) + (nf * 8 + 2 * t) * 4);
            sc[nf][0] = fmaf(sc[nf][0], 0.125f, mk.x);
            sc[nf][1] = fmaf(sc[nf][1], 0.125f, mk.y);
            sc[nf][2] = fmaf(sc[nf][2], 0.125f, mk.x);
            sc[nf][3] = fmaf(sc[nf][3], 0.125f, mk.y);
            rmax0 = fmaxf(rmax0, fmaxf(sc[nf][0], sc[nf][1]));
            rmax1 = fmaxf(rmax1, fmaxf(sc[nf][2], sc[nf][3]));
        }
        rmax0 = fmaxf(rmax0, __shfl_xor_sync(0xffffffffu, rmax0, 1));
        rmax0 = fmaxf(rmax0, __shfl_xor_sync(0xffffffffu, rmax0, 2));
        rmax1 = fmaxf(rmax1, __shfl_xor_sync(0xffffffffu, rmax1, 1));
        rmax1 = fmaxf(rmax1, __shfl_xor_sync(0xffffffffu, rmax1, 2));
        float mn0 = fmaxf(m0, rmax0), mn1 = fmaxf(m1, rmax1);
        float c0 = fast_exp(m0 - mn0), c1 = fast_exp(m1 - mn1);
        float sum0 = 0.0f, sum1 = 0.0f;
#pragma unroll
        for (int nf = 0; nf < 8; nf++) {
            sc[nf][0] = fast_exp(sc[nf][0] - mn0);
            sc[nf][1] = fast_exp(sc[nf][1] - mn0);
            sc[nf][2] = fast_exp(sc[nf][2] - mn1);
            sc[nf][3] = fast_exp(sc[nf][3] - mn1);
            sum0 += sc[nf][0] + sc[nf][1];
            sum1 += sc[nf][2] + sc[nf][3];
        }
        sum0 += __shfl_xor_sync(0xffffffffu, sum0, 1);
        sum0 += __shfl_xor_sync(0xffffffffu, sum0, 2);
        sum1 += __shfl_xor_sync(0xffffffffu, sum1, 1);
        sum1 += __shfl_xor_sync(0xffffffffu, sum1, 2);
        l0 = l0 * c0 + sum0;
        l1 = l1 * c1 + sum1;
        m0 = mn0; m1 = mn1;
#pragma unroll
        for (int nf = 0; nf < 8; nf++) {
            o[nf][0] *= c0; o[nf][1] *= c0;
            o[nf][2] *= c1; o[nf][3] *= c1;
        }

#pragma unroll
        for (int ks = 0; ks < 4; ks++) {
            uint32_t ph[4];
            ph[0] = pack_f16(sc[2 * ks][0],     sc[2 * ks][1]);
            ph[1] = pack_f16(sc[2 * ks][2],     sc[2 * ks][3]);
            ph[2] = pack_f16(sc[2 * ks + 1][0], sc[2 * ks + 1][1]);
            ph[3] = pack_f16(sc[2 * ks + 1][2], sc[2 * ks + 1][3]);
#pragma unroll
            for (int p = 0; p < 4; p++) {
                uint32_t bh4[4];
                ldsm4(bh4, sbase + FL_VH(s) + koff[p][ks]);
#pragma unroll
                for (int qq = 0; qq < 2; qq++) {
                    uint32_t bhf[2] = { bh4[2 * qq], bh4[2 * qq + 1] };
                    mma_f16(o[2 * p + qq], ph, bhf);
                }
            }
        }
        __syncthreads();
    }

    float i0 = 1.0f / l0, i1 = 1.0f / l1;
    int row0 = b * SEQ + qt * 128 + w * 16 + g;
    int colb = h * HDIM + 2 * t;
#pragma unroll
    for (int nf = 0; nf < 8; nf++) {
        uint32_t hw0 = pack_f16(o[nf][0] * i0, o[nf][1] * i0);
        uint32_t hw1 = pack_f16(o[nf][2] * i1, o[nf][3] * i1);
        *(uint32_t*)(Oh + row0 * D_MODEL + colb + nf * 8)       = hw0;
        *(uint32_t*)(Oh + (row0 + 8) * D_MODEL + colb + nf * 8) = hw1;
    }
}

// ---------------------------------------------------------------------------
// Launch
// ---------------------------------------------------------------------------
extern "C" void kernel_launch(void* const* d_in, const int* in_sizes, int n_in,
                              void* d_out, int out_size)
{
    const float* x    = (const float*)d_in[0];
    const float* wq   = (const float*)d_in[1];
    const float* bq   = (const float*)d_in[2];
    const float* wk   = (const float*)d_in[3];
    const float* bk   = (const float*)d_in[4];
    const float* wv   = (const float*)d_in[5];
    const float* bv   = (const float*)d_in[6];
    const float* wo   = (const float*)d_in[7];
    const float* bo   = (const float*)d_in[8];
    const float* mask = (const float*)d_in[9];
    float* out = (float*)d_out;

    float *q, *k, *v;
    float2* angtab;
    __half *qh, *kh, *vth, *xh, *ath;
    __half *wqh, *wqm, *wkh, *wkm, *wvh, *wvm, *woh, *wom;
    cudaGetSymbolAddress((void**)&q,      g_q);
    cudaGetSymbolAddress((void**)&k,      g_k);
    cudaGetSymbolAddress((void**)&v,      g_v);
    cudaGetSymbolAddress((void**)&angtab, g_angtab);
    cudaGetSymbolAddress((void**)&qh,  g_qh);
    cudaGetSymbolAddress((void**)&kh,  g_kh);
    cudaGetSymbolAddress((void**)&vth, g_vth);
    cudaGetSymbolAddress((void**)&xh,  g_xh);
    cudaGetSymbolAddress((void**)&ath, g_ath);
    cudaGetSymbolAddress((void**)&wqh, g_wqh);
    cudaGetSymbolAddress((void**)&wqm, g_wqm);
    cudaGetSymbolAddress((void**)&wkh, g_wkh);
    cudaGetSymbolAddress((void**)&wkm, g_wkm);
    cudaGetSymbolAddress((void**)&wvh, g_wvh);
    cudaGetSymbolAddress((void**)&wvm, g_wvm);
    cudaGetSymbolAddress((void**)&woh, g_woh);
    cudaGetSymbolAddress((void**)&wom, g_wom);

    cudaFuncSetAttribute(gemm_qkv_f16,
                         cudaFuncAttributeMaxDynamicSharedMemorySize, GEMM_SMEM3);
    cudaFuncSetAttribute(gemm_out_f16,
                         cudaFuncAttributeMaxDynamicSharedMemorySize, GEMM_SMEM3);
    cudaFuncSetAttribute(flash4_kernel,
                         cudaFuncAttributeMaxDynamicSharedMemorySize, FA4_SMEM);

    // Prepasses
    const int NX4 = ROWS * D_MODEL / 4;
    angtab_kernel<<<SEQ * 32 / 256, 256>>>(angtab);
    split_w4_kernel<<<(4 * W_UNITS / 2) / 256, 256>>>(
        wq, wk, wv, wo, wqh, wqm, wkh, wkm, wvh, wvm, woh, wom);
    split1_kernel<<<(NX4 / 2) / 256, 256>>>(x, xh, NX4);

    // QKV projections (fp16x2 mma.sync, 128-thread CTAs, 4/SM)
    dim3 g1(D_MODEL / 64, ROWS / 128, 3);
    gemm_qkv_f16<<<g1, 128, GEMM_SMEM3>>>(xh, wqh, wqm, bq, q,
                                          wkh, wkm, bk, k, wvh, wvm, bv, v);

    // RoPE (table) + fp16 hi split
    int rope_items = ROWS * N_HEADS * 8;
    rope_split_kernel<<<rope_items / 256, 256>>>(q, k, angtab, qh, kh);

    // V transpose (hi only)
    v_split_t_kernel<<<dim3(SEQ / 64, BATCH * N_HEADS), 256>>>(v, vth);

    // Flash attention (single-term fp16)
    flash4_kernel<<<dim3(SEQ / 128, BATCH * N_HEADS), 256, FA4_SMEM>>>(
        qh, kh, vth, mask, ath);

    // Output projection (fp16x2) -> d_out
    dim3 g3(D_MODEL / 64, ROWS / 128);
    gemm_out_f16<<<g3, 128, GEMM_SMEM3>>>(ath, woh, wom, bo, out);
}